// round 4
// baseline (speedup 1.0000x reference)
#include <cuda_runtime.h>
#include <cuda_bf16.h>
#include <cstdint>

// Problem constants
constexpr int Bc   = 2;
constexpr int Sc   = 2048;
constexpr int Dc   = 1024;
constexpr int Hc   = 16;
constexpr int HKVc = 4;
constexpr int DKc  = 64;         // D / H
constexpr int KVD  = HKVc * DKc; // 256

// Scratch (device globals: allocation-free)
__device__ float g_Qp[Bc * Sc * Dc];
__device__ float g_Kp[Bc * Sc * KVD];
__device__ float g_Vp[Bc * Sc * KVD];
__device__ float g_AO[Bc * Sc * Dc];

// ---------------------------------------------------------------------------
// tf32 helpers
// ---------------------------------------------------------------------------
__device__ __forceinline__ float to_tf32(float x) {
    float y;
    asm("cvt.rna.tf32.f32 %0, %1;" : "=f"(y) : "f"(x));
    return y;
}

__device__ __forceinline__ void mma_tf32(float* d, const float* a, const float* b) {
    asm volatile(
        "mma.sync.aligned.m16n8k8.row.col.f32.tf32.tf32.f32 "
        "{%0,%1,%2,%3}, {%4,%5,%6,%7}, {%8,%9}, {%0,%1,%2,%3};\n"
        : "+f"(d[0]), "+f"(d[1]), "+f"(d[2]), "+f"(d[3])
        : "r"(__float_as_uint(a[0])), "r"(__float_as_uint(a[1])),
          "r"(__float_as_uint(a[2])), "r"(__float_as_uint(a[3])),
          "r"(__float_as_uint(b[0])), "r"(__float_as_uint(b[1])));
}

// ---------------------------------------------------------------------------
// tf32 tensor-core GEMM + bias: C[M,N] = A[M,K] @ B[K,N] + bias[N]
// BM=BN=128, BK=32. 256 threads = 8 warps as 2(m) x 4(n); warp tile 64x32;
// per warp 4x4 mma tiles of m16n8k8 per k8-step.
// SMEM holds fragment-ordered tiles: A-fragment = one LDS.128 per tile,
// B-fragment = one LDS.64 per tile, both conflict-free.
// ---------------------------------------------------------------------------
__global__ __launch_bounds__(256) void gemm_tf32_bias(
    const float* __restrict__ A, const float* __restrict__ B,
    const float* __restrict__ bias, float* __restrict__ C,
    int M, int N, int K)
{
    // As: [kc(4)][mt(8)][lane(32)][reg(4)]  = 16 KB
    // Bs: [kc(4)][nt(16)][lane(32)][reg(2)] = 16 KB
    __shared__ float As[4 * 8 * 32 * 4];
    __shared__ float Bs[4 * 16 * 32 * 2];

    const int tid  = threadIdx.x;
    const int lane = tid & 31;
    const int warp = tid >> 5;
    const int wm   = warp >> 2;   // 0..1
    const int wn   = warp & 3;    // 0..3
    const int bm   = blockIdx.y * 128;
    const int bn   = blockIdx.x * 128;

    float c[4][4][4];
    #pragma unroll
    for (int mi = 0; mi < 4; mi++)
        #pragma unroll
        for (int ni = 0; ni < 4; ni++)
            #pragma unroll
            for (int r = 0; r < 4; r++) c[mi][ni][r] = 0.f;

    for (int k0 = 0; k0 < K; k0 += 32) {
        // ---- stage A tile: 128 rows x 32 k = 1024 float4, 4 per thread
        #pragma unroll
        for (int t = 0; t < 4; t++) {
            int f   = tid + t * 256;
            int row = f >> 3;           // 0..127
            int c0  = (f & 7) * 4;      // 0,4,...,28
            float4 v = *(const float4*)&A[(size_t)(bm + row) * K + k0 + c0];
            int mt  = row >> 4;
            int r   = row & 15;
            int kc  = c0 >> 3;
            int chi = (c0 >> 2) & 1;    // which k-half within tile
            int reg = (r >> 3) | (chi << 1);
            int base = ((kc * 8 + mt) * 32 + (r & 7) * 4) * 4 + reg;
            As[base +  0] = to_tf32(v.x);
            As[base +  4] = to_tf32(v.y);
            As[base +  8] = to_tf32(v.z);
            As[base + 12] = to_tf32(v.w);
        }
        // ---- stage B tile: 32 k x 128 n = 1024 float4, 4 per thread
        #pragma unroll
        for (int t = 0; t < 4; t++) {
            int f    = tid + t * 256;
            int krow = f >> 5;          // 0..31
            int n0   = (f & 31) * 4;    // 0..124
            float4 v = *(const float4*)&B[(size_t)(k0 + krow) * N + bn + n0];
            int kc  = krow >> 3;
            int kk  = krow & 7;
            int reg = kk >> 2;
            int nt  = n0 >> 3;
            int base = ((kc * 16 + nt) * 32 + (n0 & 7) * 4 + (kk & 3)) * 2 + reg;
            Bs[base +  0] = to_tf32(v.x);
            Bs[base +  8] = to_tf32(v.y);
            Bs[base + 16] = to_tf32(v.z);
            Bs[base + 24] = to_tf32(v.w);
        }
        __syncthreads();

        #pragma unroll
        for (int kc = 0; kc < 4; kc++) {
            float a[4][4], b[4][2];
            #pragma unroll
            for (int mi = 0; mi < 4; mi++)
                *(float4*)a[mi] = *(float4*)&As[((kc * 8 + wm * 4 + mi) * 32 + lane) * 4];
            #pragma unroll
            for (int ni = 0; ni < 4; ni++)
                *(float2*)b[ni] = *(float2*)&Bs[((kc * 16 + wn * 4 + ni) * 32 + lane) * 2];
            #pragma unroll
            for (int mi = 0; mi < 4; mi++)
                #pragma unroll
                for (int ni = 0; ni < 4; ni++)
                    mma_tf32(c[mi][ni], a[mi], b[ni]);
        }
        __syncthreads();
    }

    // ---- epilogue: c0,c1 at (row,col..col+1); c2,c3 at (row+8, same cols)
    const int g  = lane >> 2;
    const int t2 = lane & 3;
    #pragma unroll
    for (int mi = 0; mi < 4; mi++) {
        int row = bm + wm * 64 + mi * 16 + g;
        #pragma unroll
        for (int ni = 0; ni < 4; ni++) {
            int col = bn + wn * 32 + ni * 8 + t2 * 2;
            float b0 = bias[col], b1 = bias[col + 1];
            float2 lo = make_float2(c[mi][ni][0] + b0, c[mi][ni][1] + b1);
            float2 hi = make_float2(c[mi][ni][2] + b0, c[mi][ni][3] + b1);
            *(float2*)&C[(size_t)row * N + col]       = lo;
            *(float2*)&C[(size_t)(row + 8) * N + col] = hi;
        }
    }
}

// ---------------------------------------------------------------------------
// Flash attention v2 (fp32, causal, GQA), register-tiled (unchanged).
// ---------------------------------------------------------------------------
constexpr int BQ = 64;
constexpr int BK = 64;

__global__ __launch_bounds__(256, 1) void attn_v2(
    const float* __restrict__ Qp, const float* __restrict__ Kp,
    const float* __restrict__ Vp, float* __restrict__ AO)
{
    __shared__ float Qs[DKc][BQ];
    __shared__ float Ks[DKc][BK];
    __shared__ float Vs[BK][DKc];
    __shared__ float Ps[BK][BQ];

    const int qtile = blockIdx.x;
    const int h     = blockIdx.y;
    const int b     = blockIdx.z;
    const int hkv   = h >> 2;
    const int tid   = threadIdx.x;
    const int tx    = tid & 15;
    const int ty    = tid >> 4;
    const float scale = 0.125f;

    #pragma unroll
    for (int t = 0; t < 4; t++) {
        int f   = tid + t * 256;
        int row = f >> 4;
        int c4  = (f & 15) << 2;
        float4 v = *(const float4*)&Qp[((size_t)(b * Sc + qtile * BQ + row)) * Dc + h * DKc + c4];
        Qs[c4 + 0][row] = v.x;
        Qs[c4 + 1][row] = v.y;
        Qs[c4 + 2][row] = v.z;
        Qs[c4 + 3][row] = v.w;
    }

    float o[4][4];
    float m[4], l[4];
    #pragma unroll
    for (int i = 0; i < 4; i++) {
        m[i] = -1e30f; l[i] = 0.f;
        #pragma unroll
        for (int d = 0; d < 4; d++) o[i][d] = 0.f;
    }

    const int ntiles = qtile + 1;
    for (int t0 = 0; t0 < ntiles; t0++) {
        const int k0 = t0 * BK;
        __syncthreads();

        #pragma unroll
        for (int t = 0; t < 4; t++) {
            int f   = tid + t * 256;
            int row = f >> 4;
            int c4  = (f & 15) << 2;
            size_t base = ((size_t)(b * Sc + k0 + row)) * KVD + hkv * DKc + c4;
            float4 kv = *(const float4*)&Kp[base];
            Ks[c4 + 0][row] = kv.x;
            Ks[c4 + 1][row] = kv.y;
            Ks[c4 + 2][row] = kv.z;
            Ks[c4 + 3][row] = kv.w;
            *(float4*)&Vs[row][c4] = *(const float4*)&Vp[base];
        }
        __syncthreads();

        float s[4][4];
        #pragma unroll
        for (int i = 0; i < 4; i++)
            #pragma unroll
            for (int j = 0; j < 4; j++) s[i][j] = 0.f;

        #pragma unroll 16
        for (int kk = 0; kk < DKc; kk++) {
            float a[4], bb[4];
            *(float4*)&a[0]  = *(float4*)&Qs[kk][ty * 4];
            *(float4*)&bb[0] = *(float4*)&Ks[kk][tx * 4];
            #pragma unroll
            for (int i = 0; i < 4; i++)
                #pragma unroll
                for (int j = 0; j < 4; j++)
                    s[i][j] = fmaf(a[i], bb[j], s[i][j]);
        }

        if (t0 == qtile) {
            #pragma unroll
            for (int i = 0; i < 4; i++) {
                int row = qtile * BQ + ty * 4 + i;
                #pragma unroll
                for (int j = 0; j < 4; j++) {
                    int col = k0 + tx * 4 + j;
                    s[i][j] = (col > row) ? -1e30f : s[i][j] * scale;
                }
            }
        } else {
            #pragma unroll
            for (int i = 0; i < 4; i++)
                #pragma unroll
                for (int j = 0; j < 4; j++) s[i][j] *= scale;
        }

        #pragma unroll
        for (int i = 0; i < 4; i++) {
            float mt = fmaxf(fmaxf(s[i][0], s[i][1]), fmaxf(s[i][2], s[i][3]));
            #pragma unroll
            for (int off = 1; off < 16; off <<= 1)
                mt = fmaxf(mt, __shfl_xor_sync(0xffffffffu, mt, off));
            float mn   = fmaxf(m[i], mt);
            float corr = __expf(m[i] - mn);
            float ps = 0.f;
            #pragma unroll
            for (int j = 0; j < 4; j++) {
                float p = __expf(s[i][j] - mn);
                s[i][j] = p;
                ps += p;
            }
            #pragma unroll
            for (int off = 1; off < 16; off <<= 1)
                ps += __shfl_xor_sync(0xffffffffu, ps, off);
            l[i] = l[i] * corr + ps;
            m[i] = mn;
            #pragma unroll
            for (int d = 0; d < 4; d++) o[i][d] *= corr;
        }

        #pragma unroll
        for (int i = 0; i < 4; i++)
            #pragma unroll
            for (int j = 0; j < 4; j++)
                Ps[tx * 4 + j][ty * 4 + i] = s[i][j];
        __syncthreads();

        #pragma unroll 16
        for (int j = 0; j < BK; j++) {
            float a[4], bb[4];
            *(float4*)&a[0]  = *(float4*)&Ps[j][ty * 4];
            *(float4*)&bb[0] = *(float4*)&Vs[j][tx * 4];
            #pragma unroll
            for (int i = 0; i < 4; i++)
                #pragma unroll
                for (int d = 0; d < 4; d++)
                    o[i][d] = fmaf(a[i], bb[d], o[i][d]);
        }
    }

    #pragma unroll
    for (int i = 0; i < 4; i++) {
        float inv = 1.f / l[i];
        float4 v;
        v.x = o[i][0] * inv;
        v.y = o[i][1] * inv;
        v.z = o[i][2] * inv;
        v.w = o[i][3] * inv;
        *(float4*)&AO[((size_t)(b * Sc + qtile * BQ + ty * 4 + i)) * Dc + h * DKc + tx * 4] = v;
    }
}

// ---------------------------------------------------------------------------
// Launch
// ---------------------------------------------------------------------------
extern "C" void kernel_launch(void* const* d_in, const int* in_sizes, int n_in,
                              void* d_out, int out_size)
{
    const float* q  = (const float*)d_in[0];
    const float* k  = (const float*)d_in[1];
    const float* v  = (const float*)d_in[2];
    // d_in[3] = mask (causal, static — unused)
    const float* Wq = (const float*)d_in[4];
    const float* bq = (const float*)d_in[5];
    const float* Wk = (const float*)d_in[6];
    const float* bk = (const float*)d_in[7];
    const float* Wv = (const float*)d_in[8];
    const float* bv = (const float*)d_in[9];
    const float* Wo = (const float*)d_in[10];
    const float* bo = (const float*)d_in[11];
    float* out = (float*)d_out;

    float *Qp, *Kp, *Vp, *AO;
    cudaGetSymbolAddress((void**)&Qp, g_Qp);
    cudaGetSymbolAddress((void**)&Kp, g_Kp);
    cudaGetSymbolAddress((void**)&Vp, g_Vp);
    cudaGetSymbolAddress((void**)&AO, g_AO);

    const int M = Bc * Sc;   // 4096

    // Q projection: [4096,1024] @ [1024,1024]
    {
        dim3 grid(Dc / 128, M / 128);
        gemm_tf32_bias<<<grid, 256>>>(q, Wq, bq, Qp, M, Dc, Dc);
    }
    // K projection: [4096,1024] @ [1024,256]
    {
        dim3 grid(KVD / 128, M / 128);
        gemm_tf32_bias<<<grid, 256>>>(k, Wk, bk, Kp, M, KVD, Dc);
    }
    // V projection
    {
        dim3 grid(KVD / 128, M / 128);
        gemm_tf32_bias<<<grid, 256>>>(v, Wv, bv, Vp, M, KVD, Dc);
    }
    // Attention
    {
        dim3 grid(Sc / BQ, Hc, Bc);
        attn_v2<<<grid, 256>>>(Qp, Kp, Vp, AO);
    }
    // Output projection -> d_out
    {
        dim3 grid(Dc / 128, M / 128);
        gemm_tf32_bias<<<grid, 256>>>(AO, Wo, bo, out, M, Dc, Dc);
    }
}

// round 5
// speedup vs baseline: 1.5260x; 1.5260x over previous
#include <cuda_runtime.h>
#include <cuda_bf16.h>
#include <cstdint>

// Problem constants
constexpr int Bc   = 2;
constexpr int Sc   = 2048;
constexpr int Dc   = 1024;
constexpr int Hc   = 16;
constexpr int HKVc = 4;
constexpr int DKc  = 64;         // D / H
constexpr int KVD  = HKVc * DKc; // 256

// Scratch (device globals: allocation-free)
__device__ float g_Qp[Bc * Sc * Dc];
__device__ float g_Kp[Bc * Sc * KVD];
__device__ float g_Vp[Bc * Sc * KVD];
__device__ float g_AO[Bc * Sc * Dc];

// Fragment-major tf32 copies
__device__ float g_qf[Bc * Sc * Dc];
__device__ float g_kf[Bc * Sc * Dc];
__device__ float g_vf[Bc * Sc * Dc];
__device__ float g_aof[Bc * Sc * Dc];
__device__ float g_Wqf[Dc * Dc];
__device__ float g_Wkf[Dc * KVD];
__device__ float g_Wvf[Dc * KVD];
__device__ float g_Wof[Dc * Dc];

// ---------------------------------------------------------------------------
// helpers
// ---------------------------------------------------------------------------
__device__ __forceinline__ float to_tf32(float x) {
    float y;
    asm("cvt.rna.tf32.f32 %0, %1;" : "=f"(y) : "f"(x));
    return y;
}

__device__ __forceinline__ void mma_tf32(float* d, const float* a, const float* b) {
    asm volatile(
        "mma.sync.aligned.m16n8k8.row.col.f32.tf32.tf32.f32 "
        "{%0,%1,%2,%3}, {%4,%5,%6,%7}, {%8,%9}, {%0,%1,%2,%3};\n"
        : "+f"(d[0]), "+f"(d[1]), "+f"(d[2]), "+f"(d[3])
        : "r"(__float_as_uint(a[0])), "r"(__float_as_uint(a[1])),
          "r"(__float_as_uint(a[2])), "r"(__float_as_uint(a[3])),
          "r"(__float_as_uint(b[0])), "r"(__float_as_uint(b[1])));
}

__device__ __forceinline__ void cp_async16(uint32_t smem_addr, const void* gptr) {
    asm volatile("cp.async.cg.shared.global [%0], [%1], 16;" :: "r"(smem_addr), "l"(gptr));
}
__device__ __forceinline__ void cp_commit() { asm volatile("cp.async.commit_group;"); }
__device__ __forceinline__ void cp_wait0()  { asm volatile("cp.async.wait_group 0;"); }

// ---------------------------------------------------------------------------
// Fragmentize A: A[M][K] row-major -> fragment-major tf32
// out[((mt*KC + kc)*32 + lane)*4 + reg]
//   reg0=(g,t) reg1=(g+8,t) reg2=(g,t+4) reg3=(g+8,t+4);  g=lane>>2,t=lane&3
// ---------------------------------------------------------------------------
__global__ void fragmentize_A(const float* __restrict__ A, float* __restrict__ out,
                              int M, int K)
{
    int id = blockIdx.x * blockDim.x + threadIdx.x;     // one per (block,lane)
    int KC = K >> 3;
    int lane = id & 31;
    int blk  = id >> 5;
    int mt = blk / KC, kc = blk - mt * KC;
    if (mt >= M / 16) return;
    int m = mt * 16 + (lane >> 2);
    int k = kc * 8 + (lane & 3);
    const float* base = A + (size_t)m * K + k;
    float4 o;
    o.x = to_tf32(base[0]);
    o.y = to_tf32(base[(size_t)8 * K]);
    o.z = to_tf32(base[4]);
    o.w = to_tf32(base[(size_t)8 * K + 4]);
    *(float4*)&out[(size_t)id * 4] = o;
}

// ---------------------------------------------------------------------------
// Fragmentize B: B[K][N] row-major -> fragment-major tf32 (row.col mma B)
// out[((nt*KC + kc)*32 + lane)*2 + reg]; reg0=(k,n) reg1=(k+4,n); n=nt*8+(lane>>2)
// ---------------------------------------------------------------------------
__global__ void fragmentize_B(const float* __restrict__ B, float* __restrict__ out,
                              int K, int N)
{
    int id = blockIdx.x * blockDim.x + threadIdx.x;
    int KC = K >> 3;
    int lane = id & 31;
    int blk  = id >> 5;
    int nt = blk / KC, kc = blk - nt * KC;
    if (nt >= N / 8) return;
    int n = nt * 8 + (lane >> 2);
    int k = kc * 8 + (lane & 3);
    float2 o;
    o.x = to_tf32(B[(size_t)k * N + n]);
    o.y = to_tf32(B[(size_t)(k + 4) * N + n]);
    *(float2*)&out[(size_t)id * 2] = o;
}

// ---------------------------------------------------------------------------
// tf32 tensor-core GEMM from fragment-major operands.
// C[M,N] = A @ B + bias.  BM=BN=128, BK=32, 256 thr = 8 warps (2m x 4n),
// warp tile 64x32 = 4x4 mma(m16n8k8). Double-buffered cp.async staging.
// Dynamic smem: 64 KB (2*16KB A + 2*16KB B).
// ---------------------------------------------------------------------------
__global__ __launch_bounds__(256) void gemm_frag_tf32(
    const float* __restrict__ Af, const float* __restrict__ Bf,
    const float* __restrict__ bias, float* __restrict__ C,
    int M, int N, int K)
{
    extern __shared__ float sm[];
    // As: sm[0 .. 8191]   (2 bufs x 4096 floats: 32 blocks x 128)
    // Bs: sm[8192..16383] (2 bufs x 4096 floats: 64 blocks x 64)
    const int tid  = threadIdx.x;
    const int lane = tid & 31;
    const int warp = tid >> 5;
    const int wm   = warp >> 2;
    const int wn   = warp & 3;
    const int bm   = blockIdx.y * 128;
    const int bn   = blockIdx.x * 128;
    const int KC   = K >> 3;
    const uint32_t sbase = (uint32_t)__cvta_generic_to_shared(sm);

    float c[4][4][4];
    #pragma unroll
    for (int mi = 0; mi < 4; mi++)
        #pragma unroll
        for (int ni = 0; ni < 4; ni++)
            #pragma unroll
            for (int r = 0; r < 4; r++) c[mi][ni][r] = 0.f;

    auto stage = [&](int buf, int k0) {
        // A: 32 blocks x 128 floats = 1024 float4
        #pragma unroll
        for (int t = 0; t < 4; t++) {
            int idx = tid + t * 256;
            int b = idx >> 5, f4 = idx & 31;
            int mt = (bm >> 4) + (b >> 2);
            int kc = (k0 >> 3) + (b & 3);
            const float* g = Af + ((size_t)(mt * KC + kc)) * 128 + f4 * 4;
            cp_async16(sbase + (buf * 4096 + b * 128 + f4 * 4) * 4, g);
        }
        // B: 64 blocks x 64 floats = 1024 float4
        #pragma unroll
        for (int t = 0; t < 4; t++) {
            int idx = tid + t * 256;
            int b = idx >> 4, f4 = idx & 15;
            int nt = (bn >> 3) + (b >> 2);
            int kc = (k0 >> 3) + (b & 3);
            const float* g = Bf + ((size_t)(nt * KC + kc)) * 64 + f4 * 4;
            cp_async16(sbase + (8192 + buf * 4096 + b * 64 + f4 * 4) * 4, g);
        }
        cp_commit();
    };

    stage(0, 0);
    const int nit = K >> 5;
    int buf = 0;
    for (int it = 0; it < nit; it++) {
        cp_wait0();
        __syncthreads();
        if (it + 1 < nit) stage(buf ^ 1, (it + 1) << 5);

        #pragma unroll
        for (int kc = 0; kc < 4; kc++) {
            float a[4][4], b[4][2];
            #pragma unroll
            for (int mi = 0; mi < 4; mi++)
                *(float4*)a[mi] =
                    *(float4*)&sm[buf * 4096 + (((wm * 4 + mi) * 4 + kc) * 32 + lane) * 4];
            #pragma unroll
            for (int ni = 0; ni < 4; ni++)
                *(float2*)b[ni] =
                    *(float2*)&sm[8192 + buf * 4096 + (((wn * 4 + ni) * 4 + kc) * 32 + lane) * 2];
            #pragma unroll
            for (int mi = 0; mi < 4; mi++)
                #pragma unroll
                for (int ni = 0; ni < 4; ni++)
                    mma_tf32(c[mi][ni], a[mi], b[ni]);
        }
        buf ^= 1;
    }

    // epilogue: c0,c1 at (row, col..col+1); c2,c3 at (row+8, same cols)
    const int g  = lane >> 2;
    const int t2 = lane & 3;
    #pragma unroll
    for (int mi = 0; mi < 4; mi++) {
        int row = bm + wm * 64 + mi * 16 + g;
        #pragma unroll
        for (int ni = 0; ni < 4; ni++) {
            int col = bn + wn * 32 + ni * 8 + t2 * 2;
            float b0 = bias[col], b1 = bias[col + 1];
            float2 lo = make_float2(c[mi][ni][0] + b0, c[mi][ni][1] + b1);
            float2 hi = make_float2(c[mi][ni][2] + b0, c[mi][ni][3] + b1);
            *(float2*)&C[(size_t)row * N + col]       = lo;
            *(float2*)&C[(size_t)(row + 8) * N + col] = hi;
        }
    }
}

// ---------------------------------------------------------------------------
// Flash attention v2 (fp32, causal, GQA), register-tiled (unchanged, proven).
// ---------------------------------------------------------------------------
constexpr int BQ = 64;
constexpr int BK = 64;

__global__ __launch_bounds__(256, 1) void attn_v2(
    const float* __restrict__ Qp, const float* __restrict__ Kp,
    const float* __restrict__ Vp, float* __restrict__ AO)
{
    __shared__ float Qs[DKc][BQ];
    __shared__ float Ks[DKc][BK];
    __shared__ float Vs[BK][DKc];
    __shared__ float Ps[BK][BQ];

    const int qtile = blockIdx.x;
    const int h     = blockIdx.y;
    const int b     = blockIdx.z;
    const int hkv   = h >> 2;
    const int tid   = threadIdx.x;
    const int tx    = tid & 15;
    const int ty    = tid >> 4;
    const float scale = 0.125f;

    #pragma unroll
    for (int t = 0; t < 4; t++) {
        int f   = tid + t * 256;
        int row = f >> 4;
        int c4  = (f & 15) << 2;
        float4 v = *(const float4*)&Qp[((size_t)(b * Sc + qtile * BQ + row)) * Dc + h * DKc + c4];
        Qs[c4 + 0][row] = v.x;
        Qs[c4 + 1][row] = v.y;
        Qs[c4 + 2][row] = v.z;
        Qs[c4 + 3][row] = v.w;
    }

    float o[4][4];
    float m[4], l[4];
    #pragma unroll
    for (int i = 0; i < 4; i++) {
        m[i] = -1e30f; l[i] = 0.f;
        #pragma unroll
        for (int d = 0; d < 4; d++) o[i][d] = 0.f;
    }

    const int ntiles = qtile + 1;
    for (int t0 = 0; t0 < ntiles; t0++) {
        const int k0 = t0 * BK;
        __syncthreads();

        #pragma unroll
        for (int t = 0; t < 4; t++) {
            int f   = tid + t * 256;
            int row = f >> 4;
            int c4  = (f & 15) << 2;
            size_t base = ((size_t)(b * Sc + k0 + row)) * KVD + hkv * DKc + c4;
            float4 kv = *(const float4*)&Kp[base];
            Ks[c4 + 0][row] = kv.x;
            Ks[c4 + 1][row] = kv.y;
            Ks[c4 + 2][row] = kv.z;
            Ks[c4 + 3][row] = kv.w;
            *(float4*)&Vs[row][c4] = *(const float4*)&Vp[base];
        }
        __syncthreads();

        float s[4][4];
        #pragma unroll
        for (int i = 0; i < 4; i++)
            #pragma unroll
            for (int j = 0; j < 4; j++) s[i][j] = 0.f;

        #pragma unroll 16
        for (int kk = 0; kk < DKc; kk++) {
            float a[4], bb[4];
            *(float4*)&a[0]  = *(float4*)&Qs[kk][ty * 4];
            *(float4*)&bb[0] = *(float4*)&Ks[kk][tx * 4];
            #pragma unroll
            for (int i = 0; i < 4; i++)
                #pragma unroll
                for (int j = 0; j < 4; j++)
                    s[i][j] = fmaf(a[i], bb[j], s[i][j]);
        }

        if (t0 == qtile) {
            #pragma unroll
            for (int i = 0; i < 4; i++) {
                int row = qtile * BQ + ty * 4 + i;
                #pragma unroll
                for (int j = 0; j < 4; j++) {
                    int col = k0 + tx * 4 + j;
                    s[i][j] = (col > row) ? -1e30f : s[i][j] * scale;
                }
            }
        } else {
            #pragma unroll
            for (int i = 0; i < 4; i++)
                #pragma unroll
                for (int j = 0; j < 4; j++) s[i][j] *= scale;
        }

        #pragma unroll
        for (int i = 0; i < 4; i++) {
            float mt = fmaxf(fmaxf(s[i][0], s[i][1]), fmaxf(s[i][2], s[i][3]));
            #pragma unroll
            for (int off = 1; off < 16; off <<= 1)
                mt = fmaxf(mt, __shfl_xor_sync(0xffffffffu, mt, off));
            float mn   = fmaxf(m[i], mt);
            float corr = __expf(m[i] - mn);
            float ps = 0.f;
            #pragma unroll
            for (int j = 0; j < 4; j++) {
                float p = __expf(s[i][j] - mn);
                s[i][j] = p;
                ps += p;
            }
            #pragma unroll
            for (int off = 1; off < 16; off <<= 1)
                ps += __shfl_xor_sync(0xffffffffu, ps, off);
            l[i] = l[i] * corr + ps;
            m[i] = mn;
            #pragma unroll
            for (int d = 0; d < 4; d++) o[i][d] *= corr;
        }

        #pragma unroll
        for (int i = 0; i < 4; i++)
            #pragma unroll
            for (int j = 0; j < 4; j++)
                Ps[tx * 4 + j][ty * 4 + i] = s[i][j];
        __syncthreads();

        #pragma unroll 16
        for (int j = 0; j < BK; j++) {
            float a[4], bb[4];
            *(float4*)&a[0]  = *(float4*)&Ps[j][ty * 4];
            *(float4*)&bb[0] = *(float4*)&Vs[j][tx * 4];
            #pragma unroll
            for (int i = 0; i < 4; i++)
                #pragma unroll
                for (int d = 0; d < 4; d++)
                    o[i][d] = fmaf(a[i], bb[d], o[i][d]);
        }
    }

    #pragma unroll
    for (int i = 0; i < 4; i++) {
        float inv = 1.f / l[i];
        float4 v;
        v.x = o[i][0] * inv;
        v.y = o[i][1] * inv;
        v.z = o[i][2] * inv;
        v.w = o[i][3] * inv;
        *(float4*)&AO[((size_t)(b * Sc + qtile * BQ + ty * 4 + i)) * Dc + h * DKc + tx * 4] = v;
    }
}

// ---------------------------------------------------------------------------
// Launch
// ---------------------------------------------------------------------------
extern "C" void kernel_launch(void* const* d_in, const int* in_sizes, int n_in,
                              void* d_out, int out_size)
{
    const float* q  = (const float*)d_in[0];
    const float* k  = (const float*)d_in[1];
    const float* v  = (const float*)d_in[2];
    // d_in[3] = mask (causal, static — unused)
    const float* Wq = (const float*)d_in[4];
    const float* bq = (const float*)d_in[5];
    const float* Wk = (const float*)d_in[6];
    const float* bk = (const float*)d_in[7];
    const float* Wv = (const float*)d_in[8];
    const float* bv = (const float*)d_in[9];
    const float* Wo = (const float*)d_in[10];
    const float* bo = (const float*)d_in[11];
    float* out = (float*)d_out;

    float *Qp, *Kp, *Vp, *AO;
    float *qf, *kf, *vf, *aof, *Wqf, *Wkf, *Wvf, *Wof;
    cudaGetSymbolAddress((void**)&Qp, g_Qp);
    cudaGetSymbolAddress((void**)&Kp, g_Kp);
    cudaGetSymbolAddress((void**)&Vp, g_Vp);
    cudaGetSymbolAddress((void**)&AO, g_AO);
    cudaGetSymbolAddress((void**)&qf, g_qf);
    cudaGetSymbolAddress((void**)&kf, g_kf);
    cudaGetSymbolAddress((void**)&vf, g_vf);
    cudaGetSymbolAddress((void**)&aof, g_aof);
    cudaGetSymbolAddress((void**)&Wqf, g_Wqf);
    cudaGetSymbolAddress((void**)&Wkf, g_Wkf);
    cudaGetSymbolAddress((void**)&Wvf, g_Wvf);
    cudaGetSymbolAddress((void**)&Wof, g_Wof);

    static bool attr_set = false;
    if (!attr_set) {
        cudaFuncSetAttribute(gemm_frag_tf32,
                             cudaFuncAttributeMaxDynamicSharedMemorySize, 65536);
        attr_set = true;
    }

    const int M = Bc * Sc;   // 4096
    const int SMEM = 65536;

    // --- fragmentize inputs + weights
    fragmentize_A<<<(M * Dc / 4) / 256, 256>>>(q, qf, M, Dc);
    fragmentize_A<<<(M * Dc / 4) / 256, 256>>>(k, kf, M, Dc);
    fragmentize_A<<<(M * Dc / 4) / 256, 256>>>(v, vf, M, Dc);
    fragmentize_B<<<(Dc * Dc / 2) / 256, 256>>>(Wq, Wqf, Dc, Dc);
    fragmentize_B<<<(Dc * KVD / 2) / 256, 256>>>(Wk, Wkf, Dc, KVD);
    fragmentize_B<<<(Dc * KVD / 2) / 256, 256>>>(Wv, Wvf, Dc, KVD);
    fragmentize_B<<<(Dc * Dc / 2) / 256, 256>>>(Wo, Wof, Dc, Dc);

    // --- projections
    {
        dim3 grid(Dc / 128, M / 128);
        gemm_frag_tf32<<<grid, 256, SMEM>>>(qf, Wqf, bq, Qp, M, Dc, Dc);
    }
    {
        dim3 grid(KVD / 128, M / 128);
        gemm_frag_tf32<<<grid, 256, SMEM>>>(kf, Wkf, bk, Kp, M, KVD, Dc);
        gemm_frag_tf32<<<grid, 256, SMEM>>>(vf, Wvf, bv, Vp, M, KVD, Dc);
    }

    // --- attention
    {
        dim3 grid(Sc / BQ, Hc, Bc);
        attn_v2<<<grid, 256>>>(Qp, Kp, Vp, AO);
    }

    // --- output projection
    fragmentize_A<<<(M * Dc / 4) / 256, 256>>>(AO, aof, M, Dc);
    {
        dim3 grid(Dc / 128, M / 128);
        gemm_frag_tf32<<<grid, 256, SMEM>>>(aof, Wof, bo, out, M, Dc, Dc);
    }
}

// round 6
// speedup vs baseline: 3.9129x; 2.5642x over previous
#include <cuda_runtime.h>
#include <cuda_bf16.h>
#include <cstdint>

// Problem constants
constexpr int Bc   = 2;
constexpr int Sc   = 2048;
constexpr int Dc   = 1024;
constexpr int Hc   = 16;
constexpr int HKVc = 4;
constexpr int DKc  = 64;         // D / H
constexpr int KVD  = HKVc * DKc; // 256

// Scratch (device globals: allocation-free)
__device__ float g_Qp[Bc * Sc * Dc];
__device__ float g_Kp[Bc * Sc * KVD];
__device__ float g_Vp[Bc * Sc * KVD];
__device__ float g_AO[Bc * Sc * Dc];

// Fragment-major tf32 copies (GEMM operands)
__device__ float g_qf[Bc * Sc * Dc];
__device__ float g_kf[Bc * Sc * Dc];
__device__ float g_vf[Bc * Sc * Dc];
__device__ float g_aof[Bc * Sc * Dc];
__device__ float g_Wqf[Dc * Dc];
__device__ float g_Wkf[Dc * KVD];
__device__ float g_Wvf[Dc * KVD];
__device__ float g_Wof[Dc * Dc];

// Fragment-major K/V for attention: [b][hkv][kt(32)][frag(64)][lane(32)][2]
__device__ float g_Kfr[Bc * HKVc * 32 * 4096];
__device__ float g_Vfr[Bc * HKVc * 32 * 4096];

// ---------------------------------------------------------------------------
// helpers
// ---------------------------------------------------------------------------
__device__ __forceinline__ float to_tf32(float x) {
    float y;
    asm("cvt.rna.tf32.f32 %0, %1;" : "=f"(y) : "f"(x));
    return y;
}

__device__ __forceinline__ void mma_tf32(float* d, const float* a, const float* b) {
    asm volatile(
        "mma.sync.aligned.m16n8k8.row.col.f32.tf32.tf32.f32 "
        "{%0,%1,%2,%3}, {%4,%5,%6,%7}, {%8,%9}, {%0,%1,%2,%3};\n"
        : "+f"(d[0]), "+f"(d[1]), "+f"(d[2]), "+f"(d[3])
        : "r"(__float_as_uint(a[0])), "r"(__float_as_uint(a[1])),
          "r"(__float_as_uint(a[2])), "r"(__float_as_uint(a[3])),
          "r"(__float_as_uint(b[0])), "r"(__float_as_uint(b[1])));
}

__device__ __forceinline__ void cp_async16(uint32_t smem_addr, const void* gptr) {
    asm volatile("cp.async.cg.shared.global [%0], [%1], 16;" :: "r"(smem_addr), "l"(gptr));
}
__device__ __forceinline__ void cp_commit() { asm volatile("cp.async.commit_group;"); }
__device__ __forceinline__ void cp_wait0()  { asm volatile("cp.async.wait_group 0;"); }

// ---------------------------------------------------------------------------
// Fragmentize A (GEMM A operand): A[M][K] row-major -> fragment-major tf32
// ---------------------------------------------------------------------------
__global__ void fragmentize_A(const float* __restrict__ A, float* __restrict__ out,
                              int M, int K)
{
    int id = blockIdx.x * blockDim.x + threadIdx.x;
    int KC = K >> 3;
    int lane = id & 31;
    int blk  = id >> 5;
    int mt = blk / KC, kc = blk - mt * KC;
    if (mt >= M / 16) return;
    int m = mt * 16 + (lane >> 2);
    int k = kc * 8 + (lane & 3);
    const float* base = A + (size_t)m * K + k;
    float4 o;
    o.x = to_tf32(base[0]);
    o.y = to_tf32(base[(size_t)8 * K]);
    o.z = to_tf32(base[4]);
    o.w = to_tf32(base[(size_t)8 * K + 4]);
    *(float4*)&out[(size_t)id * 4] = o;
}

// ---------------------------------------------------------------------------
// Fragmentize B (GEMM B operand): B[K][N] row-major -> fragment-major tf32
// ---------------------------------------------------------------------------
__global__ void fragmentize_B(const float* __restrict__ B, float* __restrict__ out,
                              int K, int N)
{
    int id = blockIdx.x * blockDim.x + threadIdx.x;
    int KC = K >> 3;
    int lane = id & 31;
    int blk  = id >> 5;
    int nt = blk / KC, kc = blk - nt * KC;
    if (nt >= N / 8) return;
    int n = nt * 8 + (lane >> 2);
    int k = kc * 8 + (lane & 3);
    float2 o;
    o.x = to_tf32(B[(size_t)k * N + n]);
    o.y = to_tf32(B[(size_t)(k + 4) * N + n]);
    *(float2*)&out[(size_t)id * 2] = o;
}

// ---------------------------------------------------------------------------
// Fragmentize K for attention S = Q K^T.
// B-operand: B(k=dk, n=key).  b0 = K[key][dk], b1 = K[key][dk+4].
// Layout: [b][hkv][kt][kc(dk-tile)*8+nt(key-tile)][lane][2]
// ---------------------------------------------------------------------------
__global__ void frag_K_attn(const float* __restrict__ Kp, float* __restrict__ Kf)
{
    int id = blockIdx.x * blockDim.x + threadIdx.x;   // 524288 total
    int l  = id & 31;
    int r  = id >> 5;
    int fc = r & 63;
    int kc = fc >> 3, nt = fc & 7;
    int tile = r >> 6;
    int kt = tile & 31;
    int bh = tile >> 5;
    int hkv = bh & 3, b = bh >> 2;
    int key = kt * 64 + nt * 8 + (l >> 2);
    int dk  = kc * 8 + (l & 3);
    const float* src = Kp + ((size_t)(b * Sc + key)) * KVD + hkv * DKc + dk;
    float2 o = make_float2(to_tf32(src[0]), to_tf32(src[4]));
    *(float2*)&Kf[(size_t)id * 2] = o;
}

// ---------------------------------------------------------------------------
// Fragmentize V for attention O = P V.
// B-operand: B(k=key, n=dk).  b0 = V[key][dk], b1 = V[key+4][dk].
// Layout: [b][hkv][kt][kk(key-tile)*8+nd(dk-tile)][lane][2]
// ---------------------------------------------------------------------------
__global__ void frag_V_attn(const float* __restrict__ Vp, float* __restrict__ Vf)
{
    int id = blockIdx.x * blockDim.x + threadIdx.x;
    int l  = id & 31;
    int r  = id >> 5;
    int fc = r & 63;
    int kk = fc >> 3, nd = fc & 7;
    int tile = r >> 6;
    int kt = tile & 31;
    int bh = tile >> 5;
    int hkv = bh & 3, b = bh >> 2;
    int key = kt * 64 + kk * 8 + (l & 3);
    int dk  = nd * 8 + (l >> 2);
    const float* src = Vp + ((size_t)(b * Sc + key)) * KVD + hkv * DKc + dk;
    float2 o = make_float2(to_tf32(src[0]), to_tf32(src[(size_t)4 * KVD]));
    *(float2*)&Vf[(size_t)id * 2] = o;
}

// ---------------------------------------------------------------------------
// tf32 tensor-core GEMM from fragment-major operands (proven, unchanged).
// ---------------------------------------------------------------------------
__global__ __launch_bounds__(256) void gemm_frag_tf32(
    const float* __restrict__ Af, const float* __restrict__ Bf,
    const float* __restrict__ bias, float* __restrict__ C,
    int M, int N, int K)
{
    extern __shared__ float sm[];
    const int tid  = threadIdx.x;
    const int lane = tid & 31;
    const int warp = tid >> 5;
    const int wm   = warp >> 2;
    const int wn   = warp & 3;
    const int bm   = blockIdx.y * 128;
    const int bn   = blockIdx.x * 128;
    const int KC   = K >> 3;
    const uint32_t sbase = (uint32_t)__cvta_generic_to_shared(sm);

    float c[4][4][4];
    #pragma unroll
    for (int mi = 0; mi < 4; mi++)
        #pragma unroll
        for (int ni = 0; ni < 4; ni++)
            #pragma unroll
            for (int r = 0; r < 4; r++) c[mi][ni][r] = 0.f;

    auto stage = [&](int buf, int k0) {
        #pragma unroll
        for (int t = 0; t < 4; t++) {
            int idx = tid + t * 256;
            int b = idx >> 5, f4 = idx & 31;
            int mt = (bm >> 4) + (b >> 2);
            int kc = (k0 >> 3) + (b & 3);
            const float* g = Af + ((size_t)(mt * KC + kc)) * 128 + f4 * 4;
            cp_async16(sbase + (buf * 4096 + b * 128 + f4 * 4) * 4, g);
        }
        #pragma unroll
        for (int t = 0; t < 4; t++) {
            int idx = tid + t * 256;
            int b = idx >> 4, f4 = idx & 15;
            int nt = (bn >> 3) + (b >> 2);
            int kc = (k0 >> 3) + (b & 3);
            const float* g = Bf + ((size_t)(nt * KC + kc)) * 64 + f4 * 4;
            cp_async16(sbase + (8192 + buf * 4096 + b * 64 + f4 * 4) * 4, g);
        }
        cp_commit();
    };

    stage(0, 0);
    const int nit = K >> 5;
    int buf = 0;
    for (int it = 0; it < nit; it++) {
        cp_wait0();
        __syncthreads();
        if (it + 1 < nit) stage(buf ^ 1, (it + 1) << 5);

        #pragma unroll
        for (int kc = 0; kc < 4; kc++) {
            float a[4][4], b[4][2];
            #pragma unroll
            for (int mi = 0; mi < 4; mi++)
                *(float4*)a[mi] =
                    *(float4*)&sm[buf * 4096 + (((wm * 4 + mi) * 4 + kc) * 32 + lane) * 4];
            #pragma unroll
            for (int ni = 0; ni < 4; ni++)
                *(float2*)b[ni] =
                    *(float2*)&sm[8192 + buf * 4096 + (((wn * 4 + ni) * 4 + kc) * 32 + lane) * 2];
            #pragma unroll
            for (int mi = 0; mi < 4; mi++)
                #pragma unroll
                for (int ni = 0; ni < 4; ni++)
                    mma_tf32(c[mi][ni], a[mi], b[ni]);
        }
        buf ^= 1;
    }

    const int g  = lane >> 2;
    const int t2 = lane & 3;
    #pragma unroll
    for (int mi = 0; mi < 4; mi++) {
        int row = bm + wm * 64 + mi * 16 + g;
        #pragma unroll
        for (int ni = 0; ni < 4; ni++) {
            int col = bn + wn * 32 + ni * 8 + t2 * 2;
            float b0 = bias[col], b1 = bias[col + 1];
            float2 lo = make_float2(c[mi][ni][0] + b0, c[mi][ni][1] + b1);
            float2 hi = make_float2(c[mi][ni][2] + b0, c[mi][ni][3] + b1);
            *(float2*)&C[(size_t)row * N + col]       = lo;
            *(float2*)&C[(size_t)(row + 8) * N + col] = hi;
        }
    }
}

// ---------------------------------------------------------------------------
// Tensor-core flash attention (tf32 mma, causal, GQA).
// grid (S/64, H, B), 128 threads = 4 warps; warp w owns q-rows w*16..w*16+15.
// Per key tile: S = Q K^T (64 mma/warp), online softmax, O += P V (64 mma/warp).
// K/V fragment tiles double-buffered via cp.async. P staged through warp-
// private padded smem (pad 68 -> conflict-free A-fragment reads).
// ---------------------------------------------------------------------------
__global__ __launch_bounds__(128) void attn_mma(
    const float* __restrict__ Qp, const float* __restrict__ Kf,
    const float* __restrict__ Vf, float* __restrict__ AO)
{
    extern __shared__ float sm[];
    // kbuf: sm[0..8191] (2x4096), vbuf: sm[8192..16383], ps: sm[16384 + w*1088]
    const int qt  = blockIdx.x;
    const int h   = blockIdx.y;
    const int b   = blockIdx.z;
    const int hkv = h >> 2;
    const int tid = threadIdx.x;
    const int lane = tid & 31;
    const int w    = tid >> 5;
    const int g    = lane >> 2;
    const int t    = lane & 3;
    const uint32_t sb = (uint32_t)__cvta_generic_to_shared(sm);

    // ---- Q fragments (once per block)
    float qa[8][4];
    {
        const float* qb = Qp + ((size_t)(b * Sc + qt * 64 + w * 16)) * Dc + h * DKc;
        #pragma unroll
        for (int kc = 0; kc < 8; kc++) {
            qa[kc][0] = to_tf32(qb[(size_t)g * Dc + kc * 8 + t]);
            qa[kc][1] = to_tf32(qb[(size_t)(g + 8) * Dc + kc * 8 + t]);
            qa[kc][2] = to_tf32(qb[(size_t)g * Dc + kc * 8 + t + 4]);
            qa[kc][3] = to_tf32(qb[(size_t)(g + 8) * Dc + kc * 8 + t + 4]);
        }
    }

    float o[8][4];
    #pragma unroll
    for (int nt = 0; nt < 8; nt++)
        #pragma unroll
        for (int r = 0; r < 4; r++) o[nt][r] = 0.f;
    float m0 = -1e30f, m1 = -1e30f, l0 = 0.f, l1 = 0.f;

    const float* Kt = Kf + ((size_t)((b * HKVc + hkv) * 32)) * 4096;
    const float* Vt = Vf + ((size_t)((b * HKVc + hkv) * 32)) * 4096;

    auto stage = [&](int buf, int kt) {
        const float* ks = Kt + (size_t)kt * 4096;
        const float* vs = Vt + (size_t)kt * 4096;
        #pragma unroll
        for (int i = 0; i < 8; i++) {
            int pos = i * 128 + tid;    // float4 index 0..1023
            cp_async16(sb + (buf * 4096 + pos * 4) * 4, ks + pos * 4);
            cp_async16(sb + (8192 + buf * 4096 + pos * 4) * 4, vs + pos * 4);
        }
        cp_commit();
    };

    stage(0, 0);
    const int ntiles = qt + 1;
    int buf = 0;
    float* pw = sm + 16384 + w * 1088;

    for (int kt = 0; kt < ntiles; kt++) {
        cp_wait0();
        __syncthreads();
        if (kt + 1 < ntiles) stage(buf ^ 1, kt + 1);

        // ---- S = Q K^T
        float s[8][4];
        #pragma unroll
        for (int nt = 0; nt < 8; nt++)
            #pragma unroll
            for (int r = 0; r < 4; r++) s[nt][r] = 0.f;

        #pragma unroll
        for (int kc = 0; kc < 8; kc++) {
            #pragma unroll
            for (int nt = 0; nt < 8; nt++) {
                float bf[2];
                *(float2*)bf = *(float2*)&sm[buf * 4096 + ((kc * 8 + nt) * 32 + lane) * 2];
                mma_tf32(s[nt], qa[kc], bf);
            }
        }

        // ---- scale + causal mask
        if (kt == qt) {
            int r0 = w * 16 + g, r1 = r0 + 8;
            #pragma unroll
            for (int nt = 0; nt < 8; nt++) {
                int c0 = nt * 8 + 2 * t, c1 = c0 + 1;
                s[nt][0] = (c0 > r0) ? -1e30f : s[nt][0] * 0.125f;
                s[nt][1] = (c1 > r0) ? -1e30f : s[nt][1] * 0.125f;
                s[nt][2] = (c0 > r1) ? -1e30f : s[nt][2] * 0.125f;
                s[nt][3] = (c1 > r1) ? -1e30f : s[nt][3] * 0.125f;
            }
        } else {
            #pragma unroll
            for (int nt = 0; nt < 8; nt++)
                #pragma unroll
                for (int r = 0; r < 4; r++) s[nt][r] *= 0.125f;
        }

        // ---- online softmax (rows g and g+8; 4 lanes per row share t2)
        float mt0 = -1e30f, mt1 = -1e30f;
        #pragma unroll
        for (int nt = 0; nt < 8; nt++) {
            mt0 = fmaxf(mt0, fmaxf(s[nt][0], s[nt][1]));
            mt1 = fmaxf(mt1, fmaxf(s[nt][2], s[nt][3]));
        }
        mt0 = fmaxf(mt0, __shfl_xor_sync(0xffffffffu, mt0, 1));
        mt0 = fmaxf(mt0, __shfl_xor_sync(0xffffffffu, mt0, 2));
        mt1 = fmaxf(mt1, __shfl_xor_sync(0xffffffffu, mt1, 1));
        mt1 = fmaxf(mt1, __shfl_xor_sync(0xffffffffu, mt1, 2));
        float mn0 = fmaxf(m0, mt0), mn1 = fmaxf(m1, mt1);
        float cr0 = __expf(m0 - mn0), cr1 = __expf(m1 - mn1);
        float ps0 = 0.f, ps1 = 0.f;
        #pragma unroll
        for (int nt = 0; nt < 8; nt++) {
            float p0 = to_tf32(__expf(s[nt][0] - mn0));
            float p1 = to_tf32(__expf(s[nt][1] - mn0));
            float p2 = to_tf32(__expf(s[nt][2] - mn1));
            float p3 = to_tf32(__expf(s[nt][3] - mn1));
            s[nt][0] = p0; s[nt][1] = p1; s[nt][2] = p2; s[nt][3] = p3;
            ps0 += p0 + p1;
            ps1 += p2 + p3;
        }
        ps0 += __shfl_xor_sync(0xffffffffu, ps0, 1);
        ps0 += __shfl_xor_sync(0xffffffffu, ps0, 2);
        ps1 += __shfl_xor_sync(0xffffffffu, ps1, 1);
        ps1 += __shfl_xor_sync(0xffffffffu, ps1, 2);
        l0 = l0 * cr0 + ps0;
        l1 = l1 * cr1 + ps1;
        m0 = mn0; m1 = mn1;
        #pragma unroll
        for (int nt = 0; nt < 8; nt++) {
            o[nt][0] *= cr0; o[nt][1] *= cr0;
            o[nt][2] *= cr1; o[nt][3] *= cr1;
        }

        // ---- stage P (accumulator layout -> padded [16][68] tile)
        __syncwarp();
        #pragma unroll
        for (int nt = 0; nt < 8; nt++) {
            *(float2*)&pw[g * 68 + nt * 8 + 2 * t]       = make_float2(s[nt][0], s[nt][1]);
            *(float2*)&pw[(g + 8) * 68 + nt * 8 + 2 * t] = make_float2(s[nt][2], s[nt][3]);
        }
        __syncwarp();

        // ---- O += P V
        #pragma unroll
        for (int kc = 0; kc < 8; kc++) {
            float a[4];
            a[0] = pw[g * 68 + kc * 8 + t];
            a[1] = pw[(g + 8) * 68 + kc * 8 + t];
            a[2] = pw[g * 68 + kc * 8 + t + 4];
            a[3] = pw[(g + 8) * 68 + kc * 8 + t + 4];
            #pragma unroll
            for (int nt = 0; nt < 8; nt++) {
                float bf[2];
                *(float2*)bf = *(float2*)&sm[8192 + buf * 4096 + ((kc * 8 + nt) * 32 + lane) * 2];
                mma_tf32(o[nt], a, bf);
            }
        }
        buf ^= 1;
    }

    // ---- epilogue
    float inv0 = 1.f / l0, inv1 = 1.f / l1;
    float* ob = AO + ((size_t)(b * Sc + qt * 64 + w * 16)) * Dc + h * DKc;
    #pragma unroll
    for (int nt = 0; nt < 8; nt++) {
        *(float2*)&ob[(size_t)g * Dc + nt * 8 + 2 * t] =
            make_float2(o[nt][0] * inv0, o[nt][1] * inv0);
        *(float2*)&ob[(size_t)(g + 8) * Dc + nt * 8 + 2 * t] =
            make_float2(o[nt][2] * inv1, o[nt][3] * inv1);
    }
}

// ---------------------------------------------------------------------------
// Launch
// ---------------------------------------------------------------------------
extern "C" void kernel_launch(void* const* d_in, const int* in_sizes, int n_in,
                              void* d_out, int out_size)
{
    const float* q  = (const float*)d_in[0];
    const float* k  = (const float*)d_in[1];
    const float* v  = (const float*)d_in[2];
    // d_in[3] = mask (causal, static — unused)
    const float* Wq = (const float*)d_in[4];
    const float* bq = (const float*)d_in[5];
    const float* Wk = (const float*)d_in[6];
    const float* bk = (const float*)d_in[7];
    const float* Wv = (const float*)d_in[8];
    const float* bv = (const float*)d_in[9];
    const float* Wo = (const float*)d_in[10];
    const float* bo = (const float*)d_in[11];
    float* out = (float*)d_out;

    float *Qp, *Kp, *Vp, *AO;
    float *qf, *kf, *vf, *aof, *Wqf, *Wkf, *Wvf, *Wof, *Kfr, *Vfr;
    cudaGetSymbolAddress((void**)&Qp, g_Qp);
    cudaGetSymbolAddress((void**)&Kp, g_Kp);
    cudaGetSymbolAddress((void**)&Vp, g_Vp);
    cudaGetSymbolAddress((void**)&AO, g_AO);
    cudaGetSymbolAddress((void**)&qf, g_qf);
    cudaGetSymbolAddress((void**)&kf, g_kf);
    cudaGetSymbolAddress((void**)&vf, g_vf);
    cudaGetSymbolAddress((void**)&aof, g_aof);
    cudaGetSymbolAddress((void**)&Wqf, g_Wqf);
    cudaGetSymbolAddress((void**)&Wkf, g_Wkf);
    cudaGetSymbolAddress((void**)&Wvf, g_Wvf);
    cudaGetSymbolAddress((void**)&Wof, g_Wof);
    cudaGetSymbolAddress((void**)&Kfr, g_Kfr);
    cudaGetSymbolAddress((void**)&Vfr, g_Vfr);

    static bool attr_set = false;
    if (!attr_set) {
        cudaFuncSetAttribute(gemm_frag_tf32,
                             cudaFuncAttributeMaxDynamicSharedMemorySize, 65536);
        cudaFuncSetAttribute(attn_mma,
                             cudaFuncAttributeMaxDynamicSharedMemorySize, 82944);
        attr_set = true;
    }

    const int M = Bc * Sc;   // 4096
    const int SMEM = 65536;

    // --- fragmentize inputs + weights (GEMM operands)
    fragmentize_A<<<(M * Dc / 4) / 256, 256>>>(q, qf, M, Dc);
    fragmentize_A<<<(M * Dc / 4) / 256, 256>>>(k, kf, M, Dc);
    fragmentize_A<<<(M * Dc / 4) / 256, 256>>>(v, vf, M, Dc);
    fragmentize_B<<<(Dc * Dc / 2) / 256, 256>>>(Wq, Wqf, Dc, Dc);
    fragmentize_B<<<(Dc * KVD / 2) / 256, 256>>>(Wk, Wkf, Dc, KVD);
    fragmentize_B<<<(Dc * KVD / 2) / 256, 256>>>(Wv, Wvf, Dc, KVD);
    fragmentize_B<<<(Dc * Dc / 2) / 256, 256>>>(Wo, Wof, Dc, Dc);

    // --- projections
    {
        dim3 grid(Dc / 128, M / 128);
        gemm_frag_tf32<<<grid, 256, SMEM>>>(qf, Wqf, bq, Qp, M, Dc, Dc);
    }
    {
        dim3 grid(KVD / 128, M / 128);
        gemm_frag_tf32<<<grid, 256, SMEM>>>(kf, Wkf, bk, Kp, M, KVD, Dc);
        gemm_frag_tf32<<<grid, 256, SMEM>>>(vf, Wvf, bv, Vp, M, KVD, Dc);
    }

    // --- fragmentize K/V for attention
    frag_K_attn<<<2048, 256>>>(Kp, Kfr);
    frag_V_attn<<<2048, 256>>>(Vp, Vfr);

    // --- attention (tensor cores)
    {
        dim3 grid(Sc / 64, Hc, Bc);
        attn_mma<<<grid, 128, 82944>>>(Qp, Kfr, Vfr, AO);
    }

    // --- output projection
    fragmentize_A<<<(M * Dc / 4) / 256, 256>>>(AO, aof, M, Dc);
    {
        dim3 grid(Dc / 128, M / 128);
        gemm_frag_tf32<<<grid, 256, SMEM>>>(aof, Wof, bo, out, M, Dc, Dc);
    }
}

// round 7
// speedup vs baseline: 3.9859x; 1.0187x over previous
#include <cuda_runtime.h>
#include <cuda_bf16.h>
#include <cstdint>

// Problem constants
constexpr int Bc   = 2;
constexpr int Sc   = 2048;
constexpr int Dc   = 1024;
constexpr int Hc   = 16;
constexpr int HKVc = 4;
constexpr int DKc  = 64;         // D / H
constexpr int KVD  = HKVc * DKc; // 256

// Scratch (device globals: allocation-free)
__device__ float g_Qp[Bc * Sc * Dc];
__device__ float g_Kp[Bc * Sc * KVD];
__device__ float g_Vp[Bc * Sc * KVD];

// Fragment-major tf32 copies (GEMM operands)
__device__ float g_qf[Bc * Sc * Dc];
__device__ float g_kf[Bc * Sc * Dc];
__device__ float g_vf[Bc * Sc * Dc];
__device__ float g_aof[Bc * Sc * Dc];   // attention output, fragment-major (written by attn)
__device__ float g_Wqf[Dc * Dc];
__device__ float g_Wkf[Dc * KVD];
__device__ float g_Wvf[Dc * KVD];
__device__ float g_Wof[Dc * Dc];

// Fragment-major K/V for attention: [b][hkv][kt(32)][frag(64)][lane(32)][2]
__device__ float g_Kfr[Bc * HKVc * 32 * 4096];
__device__ float g_Vfr[Bc * HKVc * 32 * 4096];

// ---------------------------------------------------------------------------
// helpers
// ---------------------------------------------------------------------------
__device__ __forceinline__ float to_tf32(float x) {
    float y;
    asm("cvt.rna.tf32.f32 %0, %1;" : "=f"(y) : "f"(x));
    return y;
}

__device__ __forceinline__ void mma_tf32(float* d, const float* a, const float* b) {
    asm volatile(
        "mma.sync.aligned.m16n8k8.row.col.f32.tf32.tf32.f32 "
        "{%0,%1,%2,%3}, {%4,%5,%6,%7}, {%8,%9}, {%0,%1,%2,%3};\n"
        : "+f"(d[0]), "+f"(d[1]), "+f"(d[2]), "+f"(d[3])
        : "r"(__float_as_uint(a[0])), "r"(__float_as_uint(a[1])),
          "r"(__float_as_uint(a[2])), "r"(__float_as_uint(a[3])),
          "r"(__float_as_uint(b[0])), "r"(__float_as_uint(b[1])));
}

__device__ __forceinline__ void cp_async16(uint32_t smem_addr, const void* gptr) {
    asm volatile("cp.async.cg.shared.global [%0], [%1], 16;" :: "r"(smem_addr), "l"(gptr));
}
__device__ __forceinline__ void cp_commit() { asm volatile("cp.async.commit_group;"); }
__device__ __forceinline__ void cp_wait0()  { asm volatile("cp.async.wait_group 0;"); }

// ---------------------------------------------------------------------------
// Fragmentize A (GEMM A operand): A[M][K] row-major -> fragment-major tf32
// ---------------------------------------------------------------------------
__global__ void fragmentize_A(const float* __restrict__ A, float* __restrict__ out,
                              int M, int K)
{
    int id = blockIdx.x * blockDim.x + threadIdx.x;
    int KC = K >> 3;
    int lane = id & 31;
    int blk  = id >> 5;
    int mt = blk / KC, kc = blk - mt * KC;
    if (mt >= M / 16) return;
    int m = mt * 16 + (lane >> 2);
    int k = kc * 8 + (lane & 3);
    const float* base = A + (size_t)m * K + k;
    float4 o;
    o.x = to_tf32(base[0]);
    o.y = to_tf32(base[(size_t)8 * K]);
    o.z = to_tf32(base[4]);
    o.w = to_tf32(base[(size_t)8 * K + 4]);
    *(float4*)&out[(size_t)id * 4] = o;
}

// ---------------------------------------------------------------------------
// Fragmentize B (GEMM B operand): B[K][N] row-major -> fragment-major tf32
// ---------------------------------------------------------------------------
__global__ void fragmentize_B(const float* __restrict__ B, float* __restrict__ out,
                              int K, int N)
{
    int id = blockIdx.x * blockDim.x + threadIdx.x;
    int KC = K >> 3;
    int lane = id & 31;
    int blk  = id >> 5;
    int nt = blk / KC, kc = blk - nt * KC;
    if (nt >= N / 8) return;
    int n = nt * 8 + (lane >> 2);
    int k = kc * 8 + (lane & 3);
    float2 o;
    o.x = to_tf32(B[(size_t)k * N + n]);
    o.y = to_tf32(B[(size_t)(k + 4) * N + n]);
    *(float2*)&out[(size_t)id * 2] = o;
}

// ---------------------------------------------------------------------------
// Fragmentize K for attention S = Q K^T.  B(k=dk, n=key).
// ---------------------------------------------------------------------------
__global__ void frag_K_attn(const float* __restrict__ Kp, float* __restrict__ Kf)
{
    int id = blockIdx.x * blockDim.x + threadIdx.x;
    int l  = id & 31;
    int r  = id >> 5;
    int fc = r & 63;
    int kc = fc >> 3, nt = fc & 7;
    int tile = r >> 6;
    int kt = tile & 31;
    int bh = tile >> 5;
    int hkv = bh & 3, b = bh >> 2;
    int key = kt * 64 + nt * 8 + (l >> 2);
    int dk  = kc * 8 + (l & 3);
    const float* src = Kp + ((size_t)(b * Sc + key)) * KVD + hkv * DKc + dk;
    float2 o = make_float2(to_tf32(src[0]), to_tf32(src[4]));
    *(float2*)&Kf[(size_t)id * 2] = o;
}

// ---------------------------------------------------------------------------
// Fragmentize V for attention O = P V.  B(k=key, n=dk).
// ---------------------------------------------------------------------------
__global__ void frag_V_attn(const float* __restrict__ Vp, float* __restrict__ Vf)
{
    int id = blockIdx.x * blockDim.x + threadIdx.x;
    int l  = id & 31;
    int r  = id >> 5;
    int fc = r & 63;
    int kk = fc >> 3, nd = fc & 7;
    int tile = r >> 6;
    int kt = tile & 31;
    int bh = tile >> 5;
    int hkv = bh & 3, b = bh >> 2;
    int key = kt * 64 + kk * 8 + (l & 3);
    int dk  = nd * 8 + (l >> 2);
    const float* src = Vp + ((size_t)(b * Sc + key)) * KVD + hkv * DKc + dk;
    float2 o = make_float2(to_tf32(src[0]), to_tf32(src[(size_t)4 * KVD]));
    *(float2*)&Vf[(size_t)id * 2] = o;
}

// ---------------------------------------------------------------------------
// tf32 tensor-core GEMM from fragment-major operands (proven, unchanged).
// ---------------------------------------------------------------------------
__global__ __launch_bounds__(256) void gemm_frag_tf32(
    const float* __restrict__ Af, const float* __restrict__ Bf,
    const float* __restrict__ bias, float* __restrict__ C,
    int M, int N, int K)
{
    extern __shared__ float sm[];
    const int tid  = threadIdx.x;
    const int lane = tid & 31;
    const int warp = tid >> 5;
    const int wm   = warp >> 2;
    const int wn   = warp & 3;
    const int bm   = blockIdx.y * 128;
    const int bn   = blockIdx.x * 128;
    const int KC   = K >> 3;
    const uint32_t sbase = (uint32_t)__cvta_generic_to_shared(sm);

    float c[4][4][4];
    #pragma unroll
    for (int mi = 0; mi < 4; mi++)
        #pragma unroll
        for (int ni = 0; ni < 4; ni++)
            #pragma unroll
            for (int r = 0; r < 4; r++) c[mi][ni][r] = 0.f;

    auto stage = [&](int buf, int k0) {
        #pragma unroll
        for (int t = 0; t < 4; t++) {
            int idx = tid + t * 256;
            int b = idx >> 5, f4 = idx & 31;
            int mt = (bm >> 4) + (b >> 2);
            int kc = (k0 >> 3) + (b & 3);
            const float* g = Af + ((size_t)(mt * KC + kc)) * 128 + f4 * 4;
            cp_async16(sbase + (buf * 4096 + b * 128 + f4 * 4) * 4, g);
        }
        #pragma unroll
        for (int t = 0; t < 4; t++) {
            int idx = tid + t * 256;
            int b = idx >> 4, f4 = idx & 15;
            int nt = (bn >> 3) + (b >> 2);
            int kc = (k0 >> 3) + (b & 3);
            const float* g = Bf + ((size_t)(nt * KC + kc)) * 64 + f4 * 4;
            cp_async16(sbase + (8192 + buf * 4096 + b * 64 + f4 * 4) * 4, g);
        }
        cp_commit();
    };

    stage(0, 0);
    const int nit = K >> 5;
    int buf = 0;
    for (int it = 0; it < nit; it++) {
        cp_wait0();
        __syncthreads();
        if (it + 1 < nit) stage(buf ^ 1, (it + 1) << 5);

        #pragma unroll
        for (int kc = 0; kc < 4; kc++) {
            float a[4][4], b[4][2];
            #pragma unroll
            for (int mi = 0; mi < 4; mi++)
                *(float4*)a[mi] =
                    *(float4*)&sm[buf * 4096 + (((wm * 4 + mi) * 4 + kc) * 32 + lane) * 4];
            #pragma unroll
            for (int ni = 0; ni < 4; ni++)
                *(float2*)b[ni] =
                    *(float2*)&sm[8192 + buf * 4096 + (((wn * 4 + ni) * 4 + kc) * 32 + lane) * 2];
            #pragma unroll
            for (int mi = 0; mi < 4; mi++)
                #pragma unroll
                for (int ni = 0; ni < 4; ni++)
                    mma_tf32(c[mi][ni], a[mi], b[ni]);
        }
        buf ^= 1;
    }

    const int g  = lane >> 2;
    const int t2 = lane & 3;
    #pragma unroll
    for (int mi = 0; mi < 4; mi++) {
        int row = bm + wm * 64 + mi * 16 + g;
        #pragma unroll
        for (int ni = 0; ni < 4; ni++) {
            int col = bn + wn * 32 + ni * 8 + t2 * 2;
            float b0 = bias[col], b1 = bias[col + 1];
            float2 lo = make_float2(c[mi][ni][0] + b0, c[mi][ni][1] + b1);
            float2 hi = make_float2(c[mi][ni][2] + b0, c[mi][ni][3] + b1);
            *(float2*)&C[(size_t)row * N + col]       = lo;
            *(float2*)&C[(size_t)(row + 8) * N + col] = hi;
        }
    }
}

// ---------------------------------------------------------------------------
// Tensor-core flash attention v2 (tf32 mma, causal, GQA).
// grid (S/128, H, B) with qt REVERSED for load balance; 256 threads = 8 warps.
// Warp w owns q-rows qbase + w*16 .. +15 (one mt tile). Shared K/V tiles
// (64 keys) double-buffered via cp.async, amortized over 8 warps.
// Epilogue writes O directly in fragment-major tf32 layout for the O-proj GEMM.
// ---------------------------------------------------------------------------
__global__ __launch_bounds__(256) void attn_mma2(
    const float* __restrict__ Qp, const float* __restrict__ Kf,
    const float* __restrict__ Vf, float* __restrict__ AOf)
{
    extern __shared__ float sm[];
    // kbuf: sm[0..8191] (2x4096), vbuf: sm[8192..16383], pw: sm[16384 + w*1088]
    const int qt  = (gridDim.x - 1) - blockIdx.x;   // heavy blocks first
    const int h   = blockIdx.y;
    const int b   = blockIdx.z;
    const int hkv = h >> 2;
    const int tid = threadIdx.x;
    const int lane = tid & 31;
    const int w    = tid >> 5;
    const int g    = lane >> 2;
    const int t    = lane & 3;
    const int qbase = qt * 128;
    const int rmin  = qbase + w * 16;               // warp's first q row
    const uint32_t sb = (uint32_t)__cvta_generic_to_shared(sm);

    // ---- Q fragments
    float qa[8][4];
    {
        const float* qb = Qp + ((size_t)(b * Sc + rmin)) * Dc + h * DKc;
        #pragma unroll
        for (int kc = 0; kc < 8; kc++) {
            qa[kc][0] = to_tf32(qb[(size_t)g * Dc + kc * 8 + t]);
            qa[kc][1] = to_tf32(qb[(size_t)(g + 8) * Dc + kc * 8 + t]);
            qa[kc][2] = to_tf32(qb[(size_t)g * Dc + kc * 8 + t + 4]);
            qa[kc][3] = to_tf32(qb[(size_t)(g + 8) * Dc + kc * 8 + t + 4]);
        }
    }

    float o[8][4];
    #pragma unroll
    for (int nt = 0; nt < 8; nt++)
        #pragma unroll
        for (int r = 0; r < 4; r++) o[nt][r] = 0.f;
    float m0 = -1e30f, m1 = -1e30f, l0 = 0.f, l1 = 0.f;

    const float* Kt = Kf + ((size_t)((b * HKVc + hkv) * 32)) * 4096;
    const float* Vt = Vf + ((size_t)((b * HKVc + hkv) * 32)) * 4096;

    auto stage = [&](int buf, int kt) {
        const float* ks = Kt + (size_t)kt * 4096;
        const float* vs = Vt + (size_t)kt * 4096;
        #pragma unroll
        for (int i = 0; i < 4; i++) {
            int pos = i * 256 + tid;    // float4 index 0..1023
            cp_async16(sb + (buf * 4096 + pos * 4) * 4, ks + pos * 4);
            cp_async16(sb + (8192 + buf * 4096 + pos * 4) * 4, vs + pos * 4);
        }
        cp_commit();
    };

    stage(0, 0);
    const int ntiles = 2 * qt + 2;      // key tiles covering rows 0..qbase+127
    int buf = 0;
    float* pw = sm + 16384 + w * 1088;

    for (int kt = 0; kt < ntiles; kt++) {
        cp_wait0();
        __syncthreads();
        if (kt + 1 < ntiles) stage(buf ^ 1, kt + 1);

        // ---- S = Q K^T
        float s[8][4];
        #pragma unroll
        for (int nt = 0; nt < 8; nt++)
            #pragma unroll
            for (int r = 0; r < 4; r++) s[nt][r] = 0.f;

        #pragma unroll
        for (int kc = 0; kc < 8; kc++) {
            #pragma unroll
            for (int nt = 0; nt < 8; nt++) {
                float bf[2];
                *(float2*)bf = *(float2*)&sm[buf * 4096 + ((kc * 8 + nt) * 32 + lane) * 2];
                mma_tf32(s[nt], qa[kc], bf);
            }
        }

        // ---- scale + causal mask (mask whenever tile reaches past warp's rows)
        if (kt * 64 + 63 > rmin) {
            int r0 = rmin + g, r1 = r0 + 8;
            #pragma unroll
            for (int nt = 0; nt < 8; nt++) {
                int c0 = kt * 64 + nt * 8 + 2 * t, c1 = c0 + 1;
                s[nt][0] = (c0 > r0) ? -1e30f : s[nt][0] * 0.125f;
                s[nt][1] = (c1 > r0) ? -1e30f : s[nt][1] * 0.125f;
                s[nt][2] = (c0 > r1) ? -1e30f : s[nt][2] * 0.125f;
                s[nt][3] = (c1 > r1) ? -1e30f : s[nt][3] * 0.125f;
            }
        } else {
            #pragma unroll
            for (int nt = 0; nt < 8; nt++)
                #pragma unroll
                for (int r = 0; r < 4; r++) s[nt][r] *= 0.125f;
        }

        // ---- online softmax (rows g and g+8)
        float mt0 = -1e30f, mt1 = -1e30f;
        #pragma unroll
        for (int nt = 0; nt < 8; nt++) {
            mt0 = fmaxf(mt0, fmaxf(s[nt][0], s[nt][1]));
            mt1 = fmaxf(mt1, fmaxf(s[nt][2], s[nt][3]));
        }
        mt0 = fmaxf(mt0, __shfl_xor_sync(0xffffffffu, mt0, 1));
        mt0 = fmaxf(mt0, __shfl_xor_sync(0xffffffffu, mt0, 2));
        mt1 = fmaxf(mt1, __shfl_xor_sync(0xffffffffu, mt1, 1));
        mt1 = fmaxf(mt1, __shfl_xor_sync(0xffffffffu, mt1, 2));
        float mn0 = fmaxf(m0, mt0), mn1 = fmaxf(m1, mt1);
        float cr0 = __expf(m0 - mn0), cr1 = __expf(m1 - mn1);
        float ps0 = 0.f, ps1 = 0.f;
        #pragma unroll
        for (int nt = 0; nt < 8; nt++) {
            float p0 = to_tf32(__expf(s[nt][0] - mn0));
            float p1 = to_tf32(__expf(s[nt][1] - mn0));
            float p2 = to_tf32(__expf(s[nt][2] - mn1));
            float p3 = to_tf32(__expf(s[nt][3] - mn1));
            s[nt][0] = p0; s[nt][1] = p1; s[nt][2] = p2; s[nt][3] = p3;
            ps0 += p0 + p1;
            ps1 += p2 + p3;
        }
        ps0 += __shfl_xor_sync(0xffffffffu, ps0, 1);
        ps0 += __shfl_xor_sync(0xffffffffu, ps0, 2);
        ps1 += __shfl_xor_sync(0xffffffffu, ps1, 1);
        ps1 += __shfl_xor_sync(0xffffffffu, ps1, 2);
        l0 = l0 * cr0 + ps0;
        l1 = l1 * cr1 + ps1;
        m0 = mn0; m1 = mn1;
        #pragma unroll
        for (int nt = 0; nt < 8; nt++) {
            o[nt][0] *= cr0; o[nt][1] *= cr0;
            o[nt][2] *= cr1; o[nt][3] *= cr1;
        }

        // ---- stage P (accumulator layout -> padded [16][68] tile)
        __syncwarp();
        #pragma unroll
        for (int nt = 0; nt < 8; nt++) {
            *(float2*)&pw[g * 68 + nt * 8 + 2 * t]       = make_float2(s[nt][0], s[nt][1]);
            *(float2*)&pw[(g + 8) * 68 + nt * 8 + 2 * t] = make_float2(s[nt][2], s[nt][3]);
        }
        __syncwarp();

        // ---- O += P V
        #pragma unroll
        for (int kc = 0; kc < 8; kc++) {
            float a[4];
            a[0] = pw[g * 68 + kc * 8 + t];
            a[1] = pw[(g + 8) * 68 + kc * 8 + t];
            a[2] = pw[g * 68 + kc * 8 + t + 4];
            a[3] = pw[(g + 8) * 68 + kc * 8 + t + 4];
            #pragma unroll
            for (int nt = 0; nt < 8; nt++) {
                float bf[2];
                *(float2*)bf = *(float2*)&sm[8192 + buf * 4096 + ((kc * 8 + nt) * 32 + lane) * 2];
                mma_tf32(o[nt], a, bf);
            }
        }
        buf ^= 1;
    }

    // ---- epilogue: normalize, stage through pw, emit fragment-major tf32
    float inv0 = 1.f / l0, inv1 = 1.f / l1;
    __syncwarp();
    #pragma unroll
    for (int nt = 0; nt < 8; nt++) {
        *(float2*)&pw[g * 68 + nt * 8 + 2 * t] =
            make_float2(o[nt][0] * inv0, o[nt][1] * inv0);
        *(float2*)&pw[(g + 8) * 68 + nt * 8 + 2 * t] =
            make_float2(o[nt][2] * inv1, o[nt][3] * inv1);
    }
    __syncwarp();

    const int KC = Dc >> 3;                       // 128
    const int mt = ((b * Sc + qbase) >> 4) + w;   // warp's global m-tile
    #pragma unroll
    for (int c = 0; c < 8; c++) {
        int kc = h * 8 + c;
        float4 v;
        v.x = to_tf32(pw[g * 68 + c * 8 + t]);
        v.y = to_tf32(pw[(g + 8) * 68 + c * 8 + t]);
        v.z = to_tf32(pw[g * 68 + c * 8 + t + 4]);
        v.w = to_tf32(pw[(g + 8) * 68 + c * 8 + t + 4]);
        *(float4*)&AOf[((size_t)(mt * KC + kc) * 32 + lane) * 4] = v;
    }
}

// ---------------------------------------------------------------------------
// Launch
// ---------------------------------------------------------------------------
extern "C" void kernel_launch(void* const* d_in, const int* in_sizes, int n_in,
                              void* d_out, int out_size)
{
    const float* q  = (const float*)d_in[0];
    const float* k  = (const float*)d_in[1];
    const float* v  = (const float*)d_in[2];
    // d_in[3] = mask (causal, static — unused)
    const float* Wq = (const float*)d_in[4];
    const float* bq = (const float*)d_in[5];
    const float* Wk = (const float*)d_in[6];
    const float* bk = (const float*)d_in[7];
    const float* Wv = (const float*)d_in[8];
    const float* bv = (const float*)d_in[9];
    const float* Wo = (const float*)d_in[10];
    const float* bo = (const float*)d_in[11];
    float* out = (float*)d_out;

    float *Qp, *Kp, *Vp;
    float *qf, *kf, *vf, *aof, *Wqf, *Wkf, *Wvf, *Wof, *Kfr, *Vfr;
    cudaGetSymbolAddress((void**)&Qp, g_Qp);
    cudaGetSymbolAddress((void**)&Kp, g_Kp);
    cudaGetSymbolAddress((void**)&Vp, g_Vp);
    cudaGetSymbolAddress((void**)&qf, g_qf);
    cudaGetSymbolAddress((void**)&kf, g_kf);
    cudaGetSymbolAddress((void**)&vf, g_vf);
    cudaGetSymbolAddress((void**)&aof, g_aof);
    cudaGetSymbolAddress((void**)&Wqf, g_Wqf);
    cudaGetSymbolAddress((void**)&Wkf, g_Wkf);
    cudaGetSymbolAddress((void**)&Wvf, g_Wvf);
    cudaGetSymbolAddress((void**)&Wof, g_Wof);
    cudaGetSymbolAddress((void**)&Kfr, g_Kfr);
    cudaGetSymbolAddress((void**)&Vfr, g_Vfr);

    static bool attr_set = false;
    if (!attr_set) {
        cudaFuncSetAttribute(gemm_frag_tf32,
                             cudaFuncAttributeMaxDynamicSharedMemorySize, 65536);
        cudaFuncSetAttribute(attn_mma2,
                             cudaFuncAttributeMaxDynamicSharedMemorySize, 100352);
        attr_set = true;
    }

    const int M = Bc * Sc;   // 4096
    const int SMEM = 65536;

    // --- fragmentize inputs + weights (GEMM operands)
    fragmentize_A<<<(M * Dc / 4) / 256, 256>>>(q, qf, M, Dc);
    fragmentize_A<<<(M * Dc / 4) / 256, 256>>>(k, kf, M, Dc);
    fragmentize_A<<<(M * Dc / 4) / 256, 256>>>(v, vf, M, Dc);
    fragmentize_B<<<(Dc * Dc / 2) / 256, 256>>>(Wq, Wqf, Dc, Dc);
    fragmentize_B<<<(Dc * KVD / 2) / 256, 256>>>(Wk, Wkf, Dc, KVD);
    fragmentize_B<<<(Dc * KVD / 2) / 256, 256>>>(Wv, Wvf, Dc, KVD);
    fragmentize_B<<<(Dc * Dc / 2) / 256, 256>>>(Wo, Wof, Dc, Dc);

    // --- projections
    {
        dim3 grid(Dc / 128, M / 128);
        gemm_frag_tf32<<<grid, 256, SMEM>>>(qf, Wqf, bq, Qp, M, Dc, Dc);
    }
    {
        dim3 grid(KVD / 128, M / 128);
        gemm_frag_tf32<<<grid, 256, SMEM>>>(kf, Wkf, bk, Kp, M, KVD, Dc);
        gemm_frag_tf32<<<grid, 256, SMEM>>>(vf, Wvf, bv, Vp, M, KVD, Dc);
    }

    // --- fragmentize K/V for attention
    frag_K_attn<<<2048, 256>>>(Kp, Kfr);
    frag_V_attn<<<2048, 256>>>(Vp, Vfr);

    // --- attention (tensor cores), writes fragment-major AO directly
    {
        dim3 grid(Sc / 128, Hc, Bc);
        attn_mma2<<<grid, 256, 100352>>>(Qp, Kfr, Vfr, aof);
    }

    // --- output projection (consumes fragment-major AO)
    {
        dim3 grid(Dc / 128, M / 128);
        gemm_frag_tf32<<<grid, 256, SMEM>>>(aof, Wof, bo, out, M, Dc, Dc);
    }
}

// round 9
// speedup vs baseline: 6.3437x; 1.5915x over previous
#include <cuda_runtime.h>
#include <cuda_fp16.h>
#include <cstdint>

// Problem constants
constexpr int Bc   = 2;
constexpr int Sc   = 2048;
constexpr int Dc   = 1024;
constexpr int Hc   = 16;
constexpr int HKVc = 4;
constexpr int DKc  = 64;         // D / H
constexpr int KVD  = HKVc * DKc; // 256

// Scratch (device globals, allocation-free)
__device__ float g_Qp[Bc * Sc * Dc];          // projected Q (float)
__device__ float g_KVp[Bc * Sc * 512];        // projected K|V (cols 0..255 K, 256..511 V)

// fp16 fragment-major operand buffers
__device__ unsigned g_qfh [(Bc*Sc/16) * (Dc/16) * 32 * 4];
__device__ unsigned g_kfh [(Bc*Sc/16) * (Dc/16) * 32 * 4];
__device__ unsigned g_vfh [(Bc*Sc/16) * (Dc/16) * 32 * 4];
__device__ unsigned g_aofh[(Bc*Sc/16) * (Dc/16) * 32 * 4];   // attn output (fragment-major)
__device__ unsigned g_Wqfh[(Dc/8)  * (Dc/16) * 32 * 2];
__device__ unsigned g_Wkfh[(KVD/8) * (Dc/16) * 32 * 2];
__device__ unsigned g_Wvfh[(KVD/8) * (Dc/16) * 32 * 2];
__device__ unsigned g_Wofh[(Dc/8)  * (Dc/16) * 32 * 2];

// fp16 fragment-major K/V for attention: [b*HKV][kt(32)][fc(32)][lane(32)][2]
__device__ unsigned g_Kfrh[Bc * HKVc * 32 * 2048];
__device__ unsigned g_Vfrh[Bc * HKVc * 32 * 2048];

// ---------------------------------------------------------------------------
// helpers
// ---------------------------------------------------------------------------
__device__ __forceinline__ unsigned h2u(float a, float b) {
    __half2 h = __floats2half2_rn(a, b);
    return *(unsigned*)&h;
}

__device__ __forceinline__ void mma_f16(float* d, const unsigned* a, const unsigned* b) {
    asm volatile(
        "mma.sync.aligned.m16n8k16.row.col.f32.f16.f16.f32 "
        "{%0,%1,%2,%3}, {%4,%5,%6,%7}, {%8,%9}, {%0,%1,%2,%3};\n"
        : "+f"(d[0]), "+f"(d[1]), "+f"(d[2]), "+f"(d[3])
        : "r"(a[0]), "r"(a[1]), "r"(a[2]), "r"(a[3]), "r"(b[0]), "r"(b[1]));
}

__device__ __forceinline__ void cp_async16(uint32_t smem_addr, const void* gptr) {
    asm volatile("cp.async.cg.shared.global [%0], [%1], 16;" :: "r"(smem_addr), "l"(gptr));
}
__device__ __forceinline__ void cp_commit() { asm volatile("cp.async.commit_group;"); }
__device__ __forceinline__ void cp_wait0()  { asm volatile("cp.async.wait_group 0;"); }

// ---------------------------------------------------------------------------
// Fragmentize A (fp16): A[M][K] row-major -> [mt][kc16][lane][4 x b32]
// ---------------------------------------------------------------------------
__global__ void fragA_h(const float* __restrict__ A, unsigned* __restrict__ out,
                        int M, int K)
{
    int id = blockIdx.x * blockDim.x + threadIdx.x;
    int lane = id & 31, blk = id >> 5;
    int KC = K >> 4;
    int mt = blk / KC, kc = blk - mt * KC;
    if (mt >= M / 16) return;
    int g = lane >> 2, t = lane & 3;
    int m0 = mt * 16 + g, k0 = kc * 16 + 2 * t;
    const float* p = A + (size_t)m0 * K + k0;
    float2 x0 = *(const float2*)p;
    float2 x1 = *(const float2*)(p + (size_t)8 * K);
    float2 x2 = *(const float2*)(p + 8);
    float2 x3 = *(const float2*)(p + (size_t)8 * K + 8);
    uint4 o;
    o.x = h2u(x0.x, x0.y);
    o.y = h2u(x1.x, x1.y);
    o.z = h2u(x2.x, x2.y);
    o.w = h2u(x3.x, x3.y);
    *(uint4*)&out[(size_t)id * 4] = o;
}

// ---------------------------------------------------------------------------
// Fragmentize B (fp16): B[K][N] row-major -> [nt][kc16][lane][2 x b32]
// ---------------------------------------------------------------------------
__global__ void fragB_h(const float* __restrict__ B, unsigned* __restrict__ out,
                        int K, int N)
{
    int id = blockIdx.x * blockDim.x + threadIdx.x;
    int lane = id & 31, blk = id >> 5;
    int KC = K >> 4;
    int nt = blk / KC, kc = blk - nt * KC;
    if (nt >= N / 8) return;
    int g = lane >> 2, t = lane & 3;
    int n = nt * 8 + g, k0 = kc * 16 + 2 * t;
    uint2 o;
    o.x = h2u(B[(size_t)k0 * N + n],       B[(size_t)(k0 + 1) * N + n]);
    o.y = h2u(B[(size_t)(k0 + 8) * N + n], B[(size_t)(k0 + 9) * N + n]);
    *(uint2*)&out[(size_t)id * 2] = o;
}

// ---------------------------------------------------------------------------
// Fragmentize K for attention S = Q K^T (B-operand: k=dk, n=key).
// ---------------------------------------------------------------------------
__global__ void frag_K_attn_h(const float* __restrict__ KVp, unsigned* __restrict__ Kf)
{
    int id = blockIdx.x * blockDim.x + threadIdx.x;
    int lane = id & 31;
    int rest = id >> 5;
    int fc = rest & 31;
    int kc = fc >> 3, nt = fc & 7;
    int tile = rest >> 5;
    int kt = tile & 31;
    int bh = tile >> 5;
    int hkv = bh & 3, b = bh >> 2;
    int g = lane >> 2, t = lane & 3;
    int key = kt * 64 + nt * 8 + g;
    int dk0 = kc * 16 + 2 * t;
    const float* src = KVp + ((size_t)(b * Sc + key)) * 512 + hkv * DKc;
    float2 lo = *(const float2*)&src[dk0];
    float2 hi = *(const float2*)&src[dk0 + 8];
    uint2 o;
    o.x = h2u(lo.x, lo.y);
    o.y = h2u(hi.x, hi.y);
    *(uint2*)&Kf[(size_t)id * 2] = o;
}

// ---------------------------------------------------------------------------
// Fragmentize V for attention O = P V (B-operand: k=key, n=dk).
// ---------------------------------------------------------------------------
__global__ void frag_V_attn_h(const float* __restrict__ KVp, unsigned* __restrict__ Vf)
{
    int id = blockIdx.x * blockDim.x + threadIdx.x;
    int lane = id & 31;
    int rest = id >> 5;
    int fc = rest & 31;
    int kc = fc >> 3, nd = fc & 7;
    int tile = rest >> 5;
    int kt = tile & 31;
    int bh = tile >> 5;
    int hkv = bh & 3, b = bh >> 2;
    int g = lane >> 2, t = lane & 3;
    int key0 = kt * 64 + kc * 16 + 2 * t;
    int col  = 256 + hkv * DKc + nd * 8 + g;
    const float* src = KVp + ((size_t)(b * Sc + key0)) * 512 + col;
    uint2 o;
    o.x = h2u(src[0],              src[512]);
    o.y = h2u(src[(size_t)8*512],  src[(size_t)9*512]);
    *(uint2*)&Vf[(size_t)id * 2] = o;
}

// ---------------------------------------------------------------------------
// fp16 tensor-core GEMM. C[M, Ntot] (+colOff) = A @ B + bias, N = GEMM width.
// BM=BN=128, BK=32, 256 thr, warp tile 64x32, m16n8k16. cp.async double-buffer.
// ---------------------------------------------------------------------------
__global__ __launch_bounds__(256) void gemm_f16(
    const unsigned* __restrict__ Af, const unsigned* __restrict__ Bf,
    const float* __restrict__ bias, float* __restrict__ C,
    int M, int N, int K, int Ntot, int colOff)
{
    extern __shared__ unsigned smu[];
    const int tid  = threadIdx.x;
    const int lane = tid & 31;
    const int warp = tid >> 5;
    const int wm   = warp >> 2;
    const int wn   = warp & 3;
    const int bm   = blockIdx.y * 128;
    const int bn   = blockIdx.x * 128;
    const int KC   = K >> 4;
    const uint32_t sb = (uint32_t)__cvta_generic_to_shared(smu);

    float c[4][4][4];
    #pragma unroll
    for (int mi = 0; mi < 4; mi++)
        #pragma unroll
        for (int ni = 0; ni < 4; ni++)
            #pragma unroll
            for (int r = 0; r < 4; r++) c[mi][ni][r] = 0.f;

    auto stage = [&](int buf, int k0) {
        #pragma unroll
        for (int t2 = 0; t2 < 2; t2++) {
            int idx = tid + t2 * 256;
            int blkA = idx >> 5, ln = idx & 31;
            int mt = (bm >> 4) + (blkA >> 1);
            int kc = (k0 >> 4) + (blkA & 1);
            cp_async16(sb + (buf * 2048 + blkA * 128 + ln * 4) * 4,
                       Af + ((size_t)(mt * KC + kc) * 32 + ln) * 4);
        }
        #pragma unroll
        for (int t2 = 0; t2 < 2; t2++) {
            int idx = tid + t2 * 256;
            int blkB = idx >> 4, lp = idx & 15;
            int nt = (bn >> 3) + (blkB >> 1);
            int kc = (k0 >> 4) + (blkB & 1);
            cp_async16(sb + (4096 + buf * 2048 + blkB * 64 + lp * 4) * 4,
                       Bf + ((size_t)(nt * KC + kc) * 32 + lp * 2) * 2);
        }
        cp_commit();
    };

    stage(0, 0);
    const int nit = K >> 5;
    int buf = 0;
    for (int it = 0; it < nit; it++) {
        cp_wait0();
        __syncthreads();
        if (it + 1 < nit) stage(buf ^ 1, (it + 1) << 5);

        #pragma unroll
        for (int kc = 0; kc < 2; kc++) {
            unsigned a[4][4], b[4][2];
            #pragma unroll
            for (int mi = 0; mi < 4; mi++)
                *(uint4*)a[mi] = *(uint4*)&smu[buf * 2048 + (((wm * 4 + mi) * 2 + kc) * 32 + lane) * 4];
            #pragma unroll
            for (int ni = 0; ni < 4; ni++)
                *(uint2*)b[ni] = *(uint2*)&smu[4096 + buf * 2048 + (((wn * 4 + ni) * 2 + kc) * 32 + lane) * 2];
            #pragma unroll
            for (int mi = 0; mi < 4; mi++)
                #pragma unroll
                for (int ni = 0; ni < 4; ni++)
                    mma_f16(c[mi][ni], a[mi], b[ni]);
        }
        buf ^= 1;
    }

    const int g  = lane >> 2;
    const int t2 = lane & 3;
    #pragma unroll
    for (int mi = 0; mi < 4; mi++) {
        int row = bm + wm * 64 + mi * 16 + g;
        #pragma unroll
        for (int ni = 0; ni < 4; ni++) {
            int col = bn + wn * 32 + ni * 8 + t2 * 2;
            float b0 = bias[col], b1 = bias[col + 1];
            float2 lo = make_float2(c[mi][ni][0] + b0, c[mi][ni][1] + b1);
            float2 hi = make_float2(c[mi][ni][2] + b0, c[mi][ni][3] + b1);
            *(float2*)&C[(size_t)row * Ntot + colOff + col]       = lo;
            *(float2*)&C[(size_t)(row + 8) * Ntot + colOff + col] = hi;
        }
    }
}

// ---------------------------------------------------------------------------
// fp16 tensor-core flash attention (causal, GQA).
// grid (S/128, H, B), qt reversed; 256 threads = 8 warps, warp = 16-row tile.
// P via pure register repack; epilogue emits fragment-major fp16 O directly.
// ---------------------------------------------------------------------------
__global__ __launch_bounds__(256) void attn_f16(
    const float* __restrict__ Qp, const unsigned* __restrict__ Kf,
    const unsigned* __restrict__ Vf, unsigned* __restrict__ AOf)
{
    extern __shared__ unsigned smu[];
    const int qt  = (gridDim.x - 1) - blockIdx.x;
    const int h   = blockIdx.y;
    const int b   = blockIdx.z;
    const int hkv = h >> 2;
    const int tid = threadIdx.x;
    const int lane = tid & 31;
    const int w    = tid >> 5;
    const int g    = lane >> 2;
    const int t    = lane & 3;
    const int qbase = qt * 128;
    const int rmin  = qbase + w * 16;
    const uint32_t sb = (uint32_t)__cvta_generic_to_shared(smu);

    unsigned qa[4][4];
    {
        const float* qb = Qp + ((size_t)(b * Sc + rmin)) * Dc + h * DKc;
        #pragma unroll
        for (int kc = 0; kc < 4; kc++) {
            float2 v0 = *(const float2*)&qb[(size_t)g * Dc + kc * 16 + 2 * t];
            float2 v1 = *(const float2*)&qb[(size_t)(g + 8) * Dc + kc * 16 + 2 * t];
            float2 v2 = *(const float2*)&qb[(size_t)g * Dc + kc * 16 + 2 * t + 8];
            float2 v3 = *(const float2*)&qb[(size_t)(g + 8) * Dc + kc * 16 + 2 * t + 8];
            qa[kc][0] = h2u(v0.x, v0.y);
            qa[kc][1] = h2u(v1.x, v1.y);
            qa[kc][2] = h2u(v2.x, v2.y);
            qa[kc][3] = h2u(v3.x, v3.y);
        }
    }

    float o[8][4];
    #pragma unroll
    for (int nd = 0; nd < 8; nd++)
        #pragma unroll
        for (int r = 0; r < 4; r++) o[nd][r] = 0.f;
    float m0 = -1e30f, m1 = -1e30f, l0 = 0.f, l1 = 0.f;

    const int bh = b * HKVc + hkv;
    const unsigned* Kt = Kf + (size_t)bh * 32 * 2048;
    const unsigned* Vt = Vf + (size_t)bh * 32 * 2048;

    auto stage = [&](int buf, int kt) {
        const unsigned* ks = Kt + (size_t)kt * 2048;
        const unsigned* vs = Vt + (size_t)kt * 2048;
        #pragma unroll
        for (int t2 = 0; t2 < 2; t2++) {
            int pos = tid + t2 * 256;
            cp_async16(sb + (buf * 2048 + pos * 4) * 4, ks + pos * 4);
            cp_async16(sb + (4096 + buf * 2048 + pos * 4) * 4, vs + pos * 4);
        }
        cp_commit();
    };

    stage(0, 0);
    const int ntiles = 2 * qt + 2;
    int buf = 0;

    for (int kt = 0; kt < ntiles; kt++) {
        cp_wait0();
        __syncthreads();
        if (kt + 1 < ntiles) stage(buf ^ 1, kt + 1);

        float s[8][4];
        #pragma unroll
        for (int nt = 0; nt < 8; nt++)
            #pragma unroll
            for (int r = 0; r < 4; r++) s[nt][r] = 0.f;

        #pragma unroll
        for (int kc = 0; kc < 4; kc++) {
            #pragma unroll
            for (int nt = 0; nt < 8; nt++) {
                unsigned bf[2];
                *(uint2*)bf = *(uint2*)&smu[buf * 2048 + ((kc * 8 + nt) * 32 + lane) * 2];
                mma_f16(s[nt], qa[kc], bf);
            }
        }

        if (kt * 64 + 63 > rmin) {
            int r0 = rmin + g, r1 = r0 + 8;
            #pragma unroll
            for (int nt = 0; nt < 8; nt++) {
                int c0 = kt * 64 + nt * 8 + 2 * t, c1 = c0 + 1;
                s[nt][0] = (c0 > r0) ? -1e30f : s[nt][0] * 0.125f;
                s[nt][1] = (c1 > r0) ? -1e30f : s[nt][1] * 0.125f;
                s[nt][2] = (c0 > r1) ? -1e30f : s[nt][2] * 0.125f;
                s[nt][3] = (c1 > r1) ? -1e30f : s[nt][3] * 0.125f;
            }
        } else {
            #pragma unroll
            for (int nt = 0; nt < 8; nt++)
                #pragma unroll
                for (int r = 0; r < 4; r++) s[nt][r] *= 0.125f;
        }

        float mt0 = -1e30f, mt1 = -1e30f;
        #pragma unroll
        for (int nt = 0; nt < 8; nt++) {
            mt0 = fmaxf(mt0, fmaxf(s[nt][0], s[nt][1]));
            mt1 = fmaxf(mt1, fmaxf(s[nt][2], s[nt][3]));
        }
        mt0 = fmaxf(mt0, __shfl_xor_sync(0xffffffffu, mt0, 1));
        mt0 = fmaxf(mt0, __shfl_xor_sync(0xffffffffu, mt0, 2));
        mt1 = fmaxf(mt1, __shfl_xor_sync(0xffffffffu, mt1, 1));
        mt1 = fmaxf(mt1, __shfl_xor_sync(0xffffffffu, mt1, 2));
        float mn0 = fmaxf(m0, mt0), mn1 = fmaxf(m1, mt1);
        float cr0 = __expf(m0 - mn0), cr1 = __expf(m1 - mn1);
        float ps0 = 0.f, ps1 = 0.f;
        #pragma unroll
        for (int nt = 0; nt < 8; nt++) {
            float p0 = __half2float(__float2half_rn(__expf(s[nt][0] - mn0)));
            float p1 = __half2float(__float2half_rn(__expf(s[nt][1] - mn0)));
            float p2 = __half2float(__float2half_rn(__expf(s[nt][2] - mn1)));
            float p3 = __half2float(__float2half_rn(__expf(s[nt][3] - mn1)));
            s[nt][0] = p0; s[nt][1] = p1; s[nt][2] = p2; s[nt][3] = p3;
            ps0 += p0 + p1;
            ps1 += p2 + p3;
        }
        ps0 += __shfl_xor_sync(0xffffffffu, ps0, 1);
        ps0 += __shfl_xor_sync(0xffffffffu, ps0, 2);
        ps1 += __shfl_xor_sync(0xffffffffu, ps1, 1);
        ps1 += __shfl_xor_sync(0xffffffffu, ps1, 2);
        l0 = l0 * cr0 + ps0;
        l1 = l1 * cr1 + ps1;
        m0 = mn0; m1 = mn1;
        #pragma unroll
        for (int nd = 0; nd < 8; nd++) {
            o[nd][0] *= cr0; o[nd][1] *= cr0;
            o[nd][2] *= cr1; o[nd][3] *= cr1;
        }

        unsigned pa[4][4];
        #pragma unroll
        for (int kc = 0; kc < 4; kc++) {
            pa[kc][0] = h2u(s[2*kc][0],   s[2*kc][1]);
            pa[kc][1] = h2u(s[2*kc][2],   s[2*kc][3]);
            pa[kc][2] = h2u(s[2*kc+1][0], s[2*kc+1][1]);
            pa[kc][3] = h2u(s[2*kc+1][2], s[2*kc+1][3]);
        }

        #pragma unroll
        for (int kc = 0; kc < 4; kc++) {
            #pragma unroll
            for (int nd = 0; nd < 8; nd++) {
                unsigned bf[2];
                *(uint2*)bf = *(uint2*)&smu[4096 + buf * 2048 + ((kc * 8 + nd) * 32 + lane) * 2];
                mma_f16(o[nd], pa[kc], bf);
            }
        }
        buf ^= 1;
    }

    float inv0 = 1.f / l0, inv1 = 1.f / l1;
    const int KC16 = Dc >> 4;
    const int mt = ((b * Sc + qbase) >> 4) + w;
    #pragma unroll
    for (int c = 0; c < 4; c++) {
        uint4 wv;
        wv.x = h2u(o[2*c][0] * inv0,   o[2*c][1] * inv0);
        wv.y = h2u(o[2*c][2] * inv1,   o[2*c][3] * inv1);
        wv.z = h2u(o[2*c+1][0] * inv0, o[2*c+1][1] * inv0);
        wv.w = h2u(o[2*c+1][2] * inv1, o[2*c+1][3] * inv1);
        *(uint4*)&AOf[((size_t)(mt * KC16 + h * 4 + c) * 32 + lane) * 4] = wv;
    }
}

// ---------------------------------------------------------------------------
// Launch
// ---------------------------------------------------------------------------
extern "C" void kernel_launch(void* const* d_in, const int* in_sizes, int n_in,
                              void* d_out, int out_size)
{
    const float* q  = (const float*)d_in[0];
    const float* k  = (const float*)d_in[1];
    const float* v  = (const float*)d_in[2];
    const float* Wq = (const float*)d_in[4];
    const float* bq = (const float*)d_in[5];
    const float* Wk = (const float*)d_in[6];
    const float* bk = (const float*)d_in[7];
    const float* Wv = (const float*)d_in[8];
    const float* bv = (const float*)d_in[9];
    const float* Wo = (const float*)d_in[10];
    const float* bo = (const float*)d_in[11];
    float* out = (float*)d_out;

    float *Qp, *KVp;
    unsigned *qfh, *kfh, *vfh, *aofh, *Wqfh, *Wkfh, *Wvfh, *Wofh, *Kfrh, *Vfrh;
    cudaGetSymbolAddress((void**)&Qp,   g_Qp);
    cudaGetSymbolAddress((void**)&KVp,  g_KVp);
    cudaGetSymbolAddress((void**)&qfh,  g_qfh);
    cudaGetSymbolAddress((void**)&kfh,  g_kfh);
    cudaGetSymbolAddress((void**)&vfh,  g_vfh);
    cudaGetSymbolAddress((void**)&aofh, g_aofh);
    cudaGetSymbolAddress((void**)&Wqfh, g_Wqfh);
    cudaGetSymbolAddress((void**)&Wkfh, g_Wkfh);
    cudaGetSymbolAddress((void**)&Wvfh, g_Wvfh);
    cudaGetSymbolAddress((void**)&Wofh, g_Wofh);
    cudaGetSymbolAddress((void**)&Kfrh, g_Kfrh);
    cudaGetSymbolAddress((void**)&Vfrh, g_Vfrh);

    const int M = Bc * Sc;
    const int SMEM = 32768;

    fragA_h<<<(M/16)*(Dc/16)*32/256, 256>>>(q, qfh, M, Dc);
    fragA_h<<<(M/16)*(Dc/16)*32/256, 256>>>(k, kfh, M, Dc);
    fragA_h<<<(M/16)*(Dc/16)*32/256, 256>>>(v, vfh, M, Dc);
    fragB_h<<<(Dc/8)*(Dc/16)*32/256, 256>>>(Wq, Wqfh, Dc, Dc);
    fragB_h<<<(KVD/8)*(Dc/16)*32/256, 256>>>(Wk, Wkfh, Dc, KVD);
    fragB_h<<<(KVD/8)*(Dc/16)*32/256, 256>>>(Wv, Wvfh, Dc, KVD);
    fragB_h<<<(Dc/8)*(Dc/16)*32/256, 256>>>(Wo, Wofh, Dc, Dc);

    {   // Q projection
        dim3 grid(Dc / 128, M / 128);
        gemm_f16<<<grid, 256, SMEM>>>(qfh, Wqfh, bq, Qp, M, Dc, Dc, Dc, 0);
    }
    {   // K and V projections into fused KVp [M][512]
        dim3 grid(KVD / 128, M / 128);
        gemm_f16<<<grid, 256, SMEM>>>(kfh, Wkfh, bk, KVp, M, KVD, Dc, 512, 0);
        gemm_f16<<<grid, 256, SMEM>>>(vfh, Wvfh, bv, KVp, M, KVD, Dc, 512, 256);
    }

    frag_K_attn_h<<<Bc*HKVc*32*32*32/256, 256>>>(KVp, Kfrh);
    frag_V_attn_h<<<Bc*HKVc*32*32*32/256, 256>>>(KVp, Vfrh);

    {   // attention
        dim3 grid(Sc / 128, Hc, Bc);
        attn_f16<<<grid, 256, SMEM>>>(Qp, Kfrh, Vfrh, aofh);
    }

    {   // output projection
        dim3 grid(Dc / 128, M / 128);
        gemm_f16<<<grid, 256, SMEM>>>(aofh, Wofh, bo, out, M, Dc, Dc, Dc, 0);
    }
}

// round 13
// speedup vs baseline: 7.8709x; 1.2407x over previous
#include <cuda_runtime.h>
#include <cuda_fp16.h>
#include <cstdint>

// Problem constants
constexpr int Bc   = 2;
constexpr int Sc   = 2048;
constexpr int Dc   = 1024;
constexpr int Hc   = 16;
constexpr int HKVc = 4;
constexpr int DKc  = 64;         // D / H
constexpr int KVD  = HKVc * DKc; // 256

// Scratch (device globals, allocation-free)
__device__ float    g_Vp[Bc * Sc * KVD];                     // projected V (float, [M,256])
__device__ unsigned g_qfh [(Bc*Sc/16) * (Dc/16) * 32 * 4];   // input A-fragments
__device__ unsigned g_kfh [(Bc*Sc/16) * (Dc/16) * 32 * 4];
__device__ unsigned g_vfh [(Bc*Sc/16) * (Dc/16) * 32 * 4];
__device__ unsigned g_qafh[(Bc*Sc/16) * (Dc/16) * 32 * 4];   // projected Q, A-fragments (fp16)
__device__ unsigned g_aofh[(Bc*Sc/16) * (Dc/16) * 32 * 4];   // attn out, A-fragments (fp16)
__device__ unsigned g_Wqfh[(Dc/8)  * (Dc/16) * 32 * 2];
__device__ unsigned g_Wkfh[(KVD/8) * (Dc/16) * 32 * 2];
__device__ unsigned g_Wvfh[(KVD/8) * (Dc/16) * 32 * 2];
__device__ unsigned g_Wofh[(Dc/8)  * (Dc/16) * 32 * 2];
// attention K/V B-fragments: [b*HKV][kt(32)][fc(32)][lane(32)][2]
__device__ unsigned g_Kfrh[Bc * HKVc * 32 * 2048];
__device__ unsigned g_Vfrh[Bc * HKVc * 32 * 2048];

// ---------------------------------------------------------------------------
// helpers
// ---------------------------------------------------------------------------
__device__ __forceinline__ unsigned h2u(float a, float b) {
    __half2 h = __floats2half2_rn(a, b);
    return *(unsigned*)&h;
}

__device__ __forceinline__ void mma_f16(float* d, const unsigned* a, const unsigned* b) {
    asm volatile(
        "mma.sync.aligned.m16n8k16.row.col.f32.f16.f16.f32 "
        "{%0,%1,%2,%3}, {%4,%5,%6,%7}, {%8,%9}, {%0,%1,%2,%3};\n"
        : "+f"(d[0]), "+f"(d[1]), "+f"(d[2]), "+f"(d[3])
        : "r"(a[0]), "r"(a[1]), "r"(a[2]), "r"(a[3]), "r"(b[0]), "r"(b[1]));
}

__device__ __forceinline__ void cp_async16(uint32_t smem_addr, const void* gptr) {
    asm volatile("cp.async.cg.shared.global [%0], [%1], 16;" :: "r"(smem_addr), "l"(gptr));
}
__device__ __forceinline__ void cp_commit() { asm volatile("cp.async.commit_group;"); }
__device__ __forceinline__ void cp_wait0()  { asm volatile("cp.async.wait_group 0;"); }

// ---------------------------------------------------------------------------
// Fused fragmentize of q,k,v (A-operands) via smem tile transpose.
// grid.x = (M/64)*(K/64); grid.y selects tensor. Coalesced in and out.
// NOTE: pad = 68 (multiple of 4) so float4 smem stores stay 16B-aligned.
// ---------------------------------------------------------------------------
__global__ __launch_bounds__(256) void fragA3(
    const float* __restrict__ q, const float* __restrict__ k,
    const float* __restrict__ v, unsigned* __restrict__ qf,
    unsigned* __restrict__ kf, unsigned* __restrict__ vf)
{
    __shared__ float tile[64][68];
    const float* A; unsigned* out;
    if (blockIdx.y == 0)      { A = q; out = qf; }
    else if (blockIdx.y == 1) { A = k; out = kf; }
    else                      { A = v; out = vf; }

    const int K = Dc, KT = K / 64, KC = K / 16;
    const int bt = blockIdx.x;
    const int bm64 = (bt / KT) * 64, bk64 = (bt % KT) * 64;
    const int tid = threadIdx.x;

    #pragma unroll
    for (int i = 0; i < 4; i++) {
        int f = tid + i * 256;
        int row = f >> 4, col4 = (f & 15) * 4;
        *(float4*)&tile[row][col4] = *(const float4*)&A[(size_t)(bm64 + row) * K + bk64 + col4];
    }
    __syncthreads();

    #pragma unroll
    for (int i = 0; i < 2; i++) {
        int s = tid + i * 256;
        int blk = s >> 5, lane = s & 31;
        int mtl = blk >> 2, kcl = blk & 3;
        int g = lane >> 2, t = lane & 3;
        int r0 = mtl * 16 + g, c0 = kcl * 16 + 2 * t;
        uint4 o;
        o.x = h2u(tile[r0][c0],         tile[r0][c0 + 1]);
        o.y = h2u(tile[r0 + 8][c0],     tile[r0 + 8][c0 + 1]);
        o.z = h2u(tile[r0][c0 + 8],     tile[r0][c0 + 9]);
        o.w = h2u(tile[r0 + 8][c0 + 8], tile[r0 + 8][c0 + 9]);
        int mt = bm64 / 16 + mtl, kc = bk64 / 16 + kcl;
        *(uint4*)&out[((size_t)(mt * KC + kc) * 32 + lane) * 4] = o;
    }
}

// ---------------------------------------------------------------------------
// Fused fragmentize of all 4 weights (B-operands) via smem tile transpose.
// grid.x = 256 (Wq) + 64 (Wk) + 64 (Wv) + 256 (Wo) = 640 blocks.
// ---------------------------------------------------------------------------
__global__ __launch_bounds__(256) void fragB4(
    const float* __restrict__ Wq, const float* __restrict__ Wk,
    const float* __restrict__ Wv, const float* __restrict__ Wo,
    unsigned* __restrict__ Wqf, unsigned* __restrict__ Wkf,
    unsigned* __restrict__ Wvf, unsigned* __restrict__ Wof)
{
    __shared__ float tile[64][68];
    int bt = blockIdx.x;
    const float* B; unsigned* out; int N;
    if (bt < 256)      { B = Wq; out = Wqf; N = 1024; }
    else if (bt < 320) { B = Wk; out = Wkf; N = 256;  bt -= 256; }
    else if (bt < 384) { B = Wv; out = Wvf; N = 256;  bt -= 320; }
    else               { B = Wo; out = Wof; N = 1024; bt -= 384; }

    const int K = Dc, KC = K / 16, NT = N / 64;
    const int bk64 = (bt / NT) * 64, bn64 = (bt % NT) * 64;
    const int tid = threadIdx.x;

    #pragma unroll
    for (int i = 0; i < 4; i++) {
        int f = tid + i * 256;
        int row = f >> 4, col4 = (f & 15) * 4;   // row = k, col = n
        *(float4*)&tile[row][col4] = *(const float4*)&B[(size_t)(bk64 + row) * N + bn64 + col4];
    }
    __syncthreads();

    #pragma unroll
    for (int i = 0; i < 4; i++) {
        int s = tid + i * 256;
        int blk = s >> 5, lane = s & 31;
        int ntl = blk >> 2, kcl = blk & 3;
        int g = lane >> 2, t = lane & 3;
        int n = ntl * 8 + g, k0 = kcl * 16 + 2 * t;
        uint2 o;
        o.x = h2u(tile[k0][n],     tile[k0 + 1][n]);
        o.y = h2u(tile[k0 + 8][n], tile[k0 + 9][n]);
        int nt = bn64 / 8 + ntl, kc = bk64 / 16 + kcl;
        *(uint2*)&out[((size_t)(nt * KC + kc) * 32 + lane) * 2] = o;
    }
}

// ---------------------------------------------------------------------------
// Fragmentize V for attention via smem tile (reads float Vp [M,256]).
// grid.x = Bc*HKVc*32 = 256 (one block per (b,hkv,kt) 64x64 tile).
// ---------------------------------------------------------------------------
__global__ __launch_bounds__(256) void fragV_tile(
    const float* __restrict__ Vp, unsigned* __restrict__ Vf)
{
    __shared__ float tile[64][68];
    const int id = blockIdx.x;
    const int kt = id & 31, hkv = (id >> 5) & 3, b = id >> 7;
    const int tid = threadIdx.x;

    #pragma unroll
    for (int i = 0; i < 4; i++) {
        int f = tid + i * 256;
        int row = f >> 4, col4 = (f & 15) * 4;   // row = key, col = dk
        *(float4*)&tile[row][col4] =
            *(const float4*)&Vp[(size_t)(b * Sc + kt * 64 + row) * KVD + hkv * 64 + col4];
    }
    __syncthreads();

    #pragma unroll
    for (int i = 0; i < 4; i++) {
        int s = tid + i * 256;
        int blk = s >> 5, lane = s & 31;
        int kcl = blk >> 3, nd = blk & 7;
        int g = lane >> 2, t = lane & 3;
        int k0 = kcl * 16 + 2 * t, n = nd * 8 + g;
        uint2 o;
        o.x = h2u(tile[k0][n],     tile[k0 + 1][n]);
        o.y = h2u(tile[k0 + 8][n], tile[k0 + 9][n]);
        int fc = kcl * 8 + nd;
        *(uint2*)&Vf[(((size_t)((b * HKVc + hkv) * 32 + kt) * 32 + fc) * 32 + lane) * 2] = o;
    }
}

// ---------------------------------------------------------------------------
// Shared fp16 GEMM mainloop: BM=BN=128, BK=32, 256 thr, warp tile 64x32.
// Accumulates into c[4][4][4]. Dynamic smem 32 KB, cp.async double-buffered.
// ---------------------------------------------------------------------------
__device__ __forceinline__ void mainloop_f16(
    const unsigned* __restrict__ Af, const unsigned* __restrict__ Bf,
    int K, int bm, int bn, unsigned* smu, float c[4][4][4])
{
    const int tid  = threadIdx.x;
    const int lane = tid & 31;
    const int warp = tid >> 5;
    const int wm   = warp >> 2;
    const int wn   = warp & 3;
    const int KC   = K >> 4;
    const uint32_t sb = (uint32_t)__cvta_generic_to_shared(smu);

    #pragma unroll
    for (int mi = 0; mi < 4; mi++)
        #pragma unroll
        for (int ni = 0; ni < 4; ni++)
            #pragma unroll
            for (int r = 0; r < 4; r++) c[mi][ni][r] = 0.f;

    auto stage = [&](int buf, int k0) {
        #pragma unroll
        for (int t2 = 0; t2 < 2; t2++) {
            int idx = tid + t2 * 256;
            int blkA = idx >> 5, ln = idx & 31;
            int mt = (bm >> 4) + (blkA >> 1);
            int kc = (k0 >> 4) + (blkA & 1);
            cp_async16(sb + (buf * 2048 + blkA * 128 + ln * 4) * 4,
                       Af + ((size_t)(mt * KC + kc) * 32 + ln) * 4);
        }
        #pragma unroll
        for (int t2 = 0; t2 < 2; t2++) {
            int idx = tid + t2 * 256;
            int blkB = idx >> 4, lp = idx & 15;
            int nt = (bn >> 3) + (blkB >> 1);
            int kc = (k0 >> 4) + (blkB & 1);
            cp_async16(sb + (4096 + buf * 2048 + blkB * 64 + lp * 4) * 4,
                       Bf + ((size_t)(nt * KC + kc) * 32 + lp * 2) * 2);
        }
        cp_commit();
    };

    stage(0, 0);
    const int nit = K >> 5;
    int buf = 0;
    for (int it = 0; it < nit; it++) {
        cp_wait0();
        __syncthreads();
        if (it + 1 < nit) stage(buf ^ 1, (it + 1) << 5);

        #pragma unroll
        for (int kc = 0; kc < 2; kc++) {
            unsigned a[4][4], b[4][2];
            #pragma unroll
            for (int mi = 0; mi < 4; mi++)
                *(uint4*)a[mi] = *(uint4*)&smu[buf * 2048 + (((wm * 4 + mi) * 2 + kc) * 32 + lane) * 4];
            #pragma unroll
            for (int ni = 0; ni < 4; ni++)
                *(uint2*)b[ni] = *(uint2*)&smu[4096 + buf * 2048 + (((wn * 4 + ni) * 2 + kc) * 32 + lane) * 2];
            #pragma unroll
            for (int mi = 0; mi < 4; mi++)
                #pragma unroll
                for (int ni = 0; ni < 4; ni++)
                    mma_f16(c[mi][ni], a[mi], b[ni]);
        }
        buf ^= 1;
    }
    __syncthreads();
}

// ---------------------------------------------------------------------------
// Q projection: epilogue writes fragment-major fp16 A-operand directly.
// ---------------------------------------------------------------------------
__global__ __launch_bounds__(256) void gemm_q(
    const unsigned* __restrict__ Af, const unsigned* __restrict__ Bf,
    const float* __restrict__ bias, unsigned* __restrict__ Qaf)
{
    extern __shared__ unsigned smu[];
    const int bm = blockIdx.y * 128, bn = blockIdx.x * 128;
    float c[4][4][4];
    mainloop_f16(Af, Bf, Dc, bm, bn, smu, c);

    const int lane = threadIdx.x & 31, warp = threadIdx.x >> 5;
    const int wm = warp >> 2, wn = warp & 3;
    const int t = lane & 3;
    const int KC16 = Dc >> 4;    // 64
    #pragma unroll
    for (int mi = 0; mi < 4; mi++) {
        int mt = (bm + wm * 64 + mi * 16) >> 4;
        #pragma unroll
        for (int kc2 = 0; kc2 < 2; kc2++) {
            int colb = bn + wn * 32 + kc2 * 16;
            float b0 = bias[colb + 2*t], b1 = bias[colb + 2*t + 1];
            float b2 = bias[colb + 8 + 2*t], b3 = bias[colb + 9 + 2*t];
            uint4 o;
            o.x = h2u(c[mi][2*kc2][0] + b0,   c[mi][2*kc2][1] + b1);
            o.y = h2u(c[mi][2*kc2][2] + b0,   c[mi][2*kc2][3] + b1);
            o.z = h2u(c[mi][2*kc2+1][0] + b2, c[mi][2*kc2+1][1] + b3);
            o.w = h2u(c[mi][2*kc2+1][2] + b2, c[mi][2*kc2+1][3] + b3);
            int kcg = (colb >> 4);
            *(uint4*)&Qaf[((size_t)(mt * KC16 + kcg) * 32 + lane) * 4] = o;
        }
    }
}

// ---------------------------------------------------------------------------
// Fused K/V projection. grid (2, 32, 2): z=0 K -> Kfr B-fragments directly;
// z=1 V -> float Vp [M,256].
// ---------------------------------------------------------------------------
__global__ __launch_bounds__(256) void gemm_kv(
    const unsigned* __restrict__ Ak, const unsigned* __restrict__ Bk,
    const float* __restrict__ biask,
    const unsigned* __restrict__ Av, const unsigned* __restrict__ Bv,
    const float* __restrict__ biasv,
    unsigned* __restrict__ Kfr, float* __restrict__ Vp)
{
    extern __shared__ unsigned smu[];
    const int z  = blockIdx.z;
    const int bm = blockIdx.y * 128, bn = blockIdx.x * 128;
    const unsigned* Af = z ? Av : Ak;
    const unsigned* Bf = z ? Bv : Bk;
    const float* bias  = z ? biasv : biask;

    float c[4][4][4];
    mainloop_f16(Af, Bf, Dc, bm, bn, smu, c);

    const int lane = threadIdx.x & 31, warp = threadIdx.x >> 5;
    const int wm = warp >> 2, wn = warp & 3;
    const int g = lane >> 2, t = lane & 3;

    if (z == 1) {
        // ---- V: plain float epilogue into Vp [M, 256]
        #pragma unroll
        for (int mi = 0; mi < 4; mi++) {
            int row = bm + wm * 64 + mi * 16 + g;
            #pragma unroll
            for (int ni = 0; ni < 4; ni++) {
                int col = bn + wn * 32 + ni * 8 + t * 2;
                float b0 = bias[col], b1 = bias[col + 1];
                *(float2*)&Vp[(size_t)row * KVD + col] =
                    make_float2(c[mi][ni][0] + b0, c[mi][ni][1] + b1);
                *(float2*)&Vp[(size_t)(row + 8) * KVD + col] =
                    make_float2(c[mi][ni][2] + b0, c[mi][ni][3] + b1);
            }
        }
    } else {
        // ---- K: write attention B-fragments directly.
        #pragma unroll
        for (int mi = 0; mi < 4; mi++) {
            int r0 = bm + wm * 64 + mi * 16 + g;
            int b  = r0 >> 11;                 // row / Sc
            int s  = r0 & 2047;
            int kt = s >> 6;
            int nt0 = ((s & 63) >> 3);         // = 2*mi for row g (wm*64 ≡ 0 mod 64)
            #pragma unroll
            for (int kc2 = 0; kc2 < 2; kc2++) {
                int colb = bn + wn * 32 + kc2 * 16;
                int hkv = colb >> 6;
                int kc  = (colb & 63) >> 4;
                float b0 = bias[colb + 2*t], b1 = bias[colb + 2*t + 1];
                float b2 = bias[colb + 8 + 2*t], b3 = bias[colb + 9 + 2*t];
                size_t base = ((size_t)((b * HKVc + hkv) * 32 + kt) * 32);
                uint2 o1, o2;
                o1.x = h2u(c[mi][2*kc2][0] + b0,   c[mi][2*kc2][1] + b1);
                o1.y = h2u(c[mi][2*kc2+1][0] + b2, c[mi][2*kc2+1][1] + b3);
                o2.x = h2u(c[mi][2*kc2][2] + b0,   c[mi][2*kc2][3] + b1);
                o2.y = h2u(c[mi][2*kc2+1][2] + b2, c[mi][2*kc2+1][3] + b3);
                *(uint2*)&Kfr[((base + kc * 8 + nt0)     * 32 + lane) * 2] = o1;
                *(uint2*)&Kfr[((base + kc * 8 + nt0 + 1) * 32 + lane) * 2] = o2;
            }
        }
    }
}

// ---------------------------------------------------------------------------
// O projection: standard float epilogue to d_out.
// ---------------------------------------------------------------------------
__global__ __launch_bounds__(256) void gemm_o(
    const unsigned* __restrict__ Af, const unsigned* __restrict__ Bf,
    const float* __restrict__ bias, float* __restrict__ C)
{
    extern __shared__ unsigned smu[];
    const int bm = blockIdx.y * 128, bn = blockIdx.x * 128;
    float c[4][4][4];
    mainloop_f16(Af, Bf, Dc, bm, bn, smu, c);

    const int lane = threadIdx.x & 31, warp = threadIdx.x >> 5;
    const int wm = warp >> 2, wn = warp & 3;
    const int g = lane >> 2, t2 = lane & 3;
    #pragma unroll
    for (int mi = 0; mi < 4; mi++) {
        int row = bm + wm * 64 + mi * 16 + g;
        #pragma unroll
        for (int ni = 0; ni < 4; ni++) {
            int col = bn + wn * 32 + ni * 8 + t2 * 2;
            float b0 = bias[col], b1 = bias[col + 1];
            *(float2*)&C[(size_t)row * Dc + col] =
                make_float2(c[mi][ni][0] + b0, c[mi][ni][1] + b1);
            *(float2*)&C[(size_t)(row + 8) * Dc + col] =
                make_float2(c[mi][ni][2] + b0, c[mi][ni][3] + b1);
        }
    }
}

// ---------------------------------------------------------------------------
// fp16 tensor-core flash attention (causal, GQA). Q from fragment-major fp16.
// grid (S/128, H, B), qt reversed; 256 threads = 8 warps, warp = 16-row tile.
// ---------------------------------------------------------------------------
__global__ __launch_bounds__(256) void attn_f16(
    const unsigned* __restrict__ Qf, const unsigned* __restrict__ Kf,
    const unsigned* __restrict__ Vf, unsigned* __restrict__ AOf)
{
    extern __shared__ unsigned smu[];
    const int qt  = (gridDim.x - 1) - blockIdx.x;
    const int h   = blockIdx.y;
    const int b   = blockIdx.z;
    const int hkv = h >> 2;
    const int tid = threadIdx.x;
    const int lane = tid & 31;
    const int w    = tid >> 5;
    const int g    = lane >> 2;
    const int t    = lane & 3;
    const int qbase = qt * 128;
    const int rmin  = qbase + w * 16;
    const uint32_t sb = (uint32_t)__cvta_generic_to_shared(smu);

    // ---- Q fragments: coalesced uint4 loads from fragment-major buffer
    unsigned qa[4][4];
    {
        const int mt = (b * Sc + rmin) >> 4;
        #pragma unroll
        for (int kc = 0; kc < 4; kc++)
            *(uint4*)qa[kc] = *(const uint4*)&Qf[((size_t)(mt * 64 + h * 4 + kc) * 32 + lane) * 4];
    }

    float o[8][4];
    #pragma unroll
    for (int nd = 0; nd < 8; nd++)
        #pragma unroll
        for (int r = 0; r < 4; r++) o[nd][r] = 0.f;
    float m0 = -1e30f, m1 = -1e30f, l0 = 0.f, l1 = 0.f;

    const int bh = b * HKVc + hkv;
    const unsigned* Kt = Kf + (size_t)bh * 32 * 2048;
    const unsigned* Vt = Vf + (size_t)bh * 32 * 2048;

    auto stage = [&](int buf, int kt) {
        const unsigned* ks = Kt + (size_t)kt * 2048;
        const unsigned* vs = Vt + (size_t)kt * 2048;
        #pragma unroll
        for (int t2 = 0; t2 < 2; t2++) {
            int pos = tid + t2 * 256;
            cp_async16(sb + (buf * 2048 + pos * 4) * 4, ks + pos * 4);
            cp_async16(sb + (4096 + buf * 2048 + pos * 4) * 4, vs + pos * 4);
        }
        cp_commit();
    };

    stage(0, 0);
    const int ntiles = 2 * qt + 2;
    int buf = 0;

    for (int kt = 0; kt < ntiles; kt++) {
        cp_wait0();
        __syncthreads();
        if (kt + 1 < ntiles) stage(buf ^ 1, kt + 1);

        float s[8][4];
        #pragma unroll
        for (int nt = 0; nt < 8; nt++)
            #pragma unroll
            for (int r = 0; r < 4; r++) s[nt][r] = 0.f;

        #pragma unroll
        for (int kc = 0; kc < 4; kc++) {
            #pragma unroll
            for (int nt = 0; nt < 8; nt++) {
                unsigned bf[2];
                *(uint2*)bf = *(uint2*)&smu[buf * 2048 + ((kc * 8 + nt) * 32 + lane) * 2];
                mma_f16(s[nt], qa[kc], bf);
            }
        }

        if (kt * 64 + 63 > rmin) {
            int r0 = rmin + g, r1 = r0 + 8;
            #pragma unroll
            for (int nt = 0; nt < 8; nt++) {
                int c0 = kt * 64 + nt * 8 + 2 * t, c1 = c0 + 1;
                s[nt][0] = (c0 > r0) ? -1e30f : s[nt][0] * 0.125f;
                s[nt][1] = (c1 > r0) ? -1e30f : s[nt][1] * 0.125f;
                s[nt][2] = (c0 > r1) ? -1e30f : s[nt][2] * 0.125f;
                s[nt][3] = (c1 > r1) ? -1e30f : s[nt][3] * 0.125f;
            }
        } else {
            #pragma unroll
            for (int nt = 0; nt < 8; nt++)
                #pragma unroll
                for (int r = 0; r < 4; r++) s[nt][r] *= 0.125f;
        }

        float mt0 = -1e30f, mt1 = -1e30f;
        #pragma unroll
        for (int nt = 0; nt < 8; nt++) {
            mt0 = fmaxf(mt0, fmaxf(s[nt][0], s[nt][1]));
            mt1 = fmaxf(mt1, fmaxf(s[nt][2], s[nt][3]));
        }
        mt0 = fmaxf(mt0, __shfl_xor_sync(0xffffffffu, mt0, 1));
        mt0 = fmaxf(mt0, __shfl_xor_sync(0xffffffffu, mt0, 2));
        mt1 = fmaxf(mt1, __shfl_xor_sync(0xffffffffu, mt1, 1));
        mt1 = fmaxf(mt1, __shfl_xor_sync(0xffffffffu, mt1, 2));
        float mn0 = fmaxf(m0, mt0), mn1 = fmaxf(m1, mt1);
        float cr0 = __expf(m0 - mn0), cr1 = __expf(m1 - mn1);
        float ps0 = 0.f, ps1 = 0.f;
        #pragma unroll
        for (int nt = 0; nt < 8; nt++) {
            float p0 = __half2float(__float2half_rn(__expf(s[nt][0] - mn0)));
            float p1 = __half2float(__float2half_rn(__expf(s[nt][1] - mn0)));
            float p2 = __half2float(__float2half_rn(__expf(s[nt][2] - mn1)));
            float p3 = __half2float(__float2half_rn(__expf(s[nt][3] - mn1)));
            s[nt][0] = p0; s[nt][1] = p1; s[nt][2] = p2; s[nt][3] = p3;
            ps0 += p0 + p1;
            ps1 += p2 + p3;
        }
        ps0 += __shfl_xor_sync(0xffffffffu, ps0, 1);
        ps0 += __shfl_xor_sync(0xffffffffu, ps0, 2);
        ps1 += __shfl_xor_sync(0xffffffffu, ps1, 1);
        ps1 += __shfl_xor_sync(0xffffffffu, ps1, 2);
        l0 = l0 * cr0 + ps0;
        l1 = l1 * cr1 + ps1;
        m0 = mn0; m1 = mn1;
        #pragma unroll
        for (int nd = 0; nd < 8; nd++) {
            o[nd][0] *= cr0; o[nd][1] *= cr0;
            o[nd][2] *= cr1; o[nd][3] *= cr1;
        }

        unsigned pa[4][4];
        #pragma unroll
        for (int kc = 0; kc < 4; kc++) {
            pa[kc][0] = h2u(s[2*kc][0],   s[2*kc][1]);
            pa[kc][1] = h2u(s[2*kc][2],   s[2*kc][3]);
            pa[kc][2] = h2u(s[2*kc+1][0], s[2*kc+1][1]);
            pa[kc][3] = h2u(s[2*kc+1][2], s[2*kc+1][3]);
        }

        #pragma unroll
        for (int kc = 0; kc < 4; kc++) {
            #pragma unroll
            for (int nd = 0; nd < 8; nd++) {
                unsigned bf[2];
                *(uint2*)bf = *(uint2*)&smu[4096 + buf * 2048 + ((kc * 8 + nd) * 32 + lane) * 2];
                mma_f16(o[nd], pa[kc], bf);
            }
        }
        buf ^= 1;
    }

    float inv0 = 1.f / l0, inv1 = 1.f / l1;
    const int KC16 = Dc >> 4;
    const int mt = ((b * Sc + qbase) >> 4) + w;
    #pragma unroll
    for (int c = 0; c < 4; c++) {
        uint4 wv;
        wv.x = h2u(o[2*c][0] * inv0,   o[2*c][1] * inv0);
        wv.y = h2u(o[2*c][2] * inv1,   o[2*c][3] * inv1);
        wv.z = h2u(o[2*c+1][0] * inv0, o[2*c+1][1] * inv0);
        wv.w = h2u(o[2*c+1][2] * inv1, o[2*c+1][3] * inv1);
        *(uint4*)&AOf[((size_t)(mt * KC16 + h * 4 + c) * 32 + lane) * 4] = wv;
    }
}

// ---------------------------------------------------------------------------
// Launch
// ---------------------------------------------------------------------------
extern "C" void kernel_launch(void* const* d_in, const int* in_sizes, int n_in,
                              void* d_out, int out_size)
{
    const float* q  = (const float*)d_in[0];
    const float* k  = (const float*)d_in[1];
    const float* v  = (const float*)d_in[2];
    const float* Wq = (const float*)d_in[4];
    const float* bq = (const float*)d_in[5];
    const float* Wk = (const float*)d_in[6];
    const float* bk = (const float*)d_in[7];
    const float* Wv = (const float*)d_in[8];
    const float* bv = (const float*)d_in[9];
    const float* Wo = (const float*)d_in[10];
    const float* bo = (const float*)d_in[11];
    float* out = (float*)d_out;

    float *Vp;
    unsigned *qfh, *kfh, *vfh, *qafh, *aofh, *Wqfh, *Wkfh, *Wvfh, *Wofh, *Kfrh, *Vfrh;
    cudaGetSymbolAddress((void**)&Vp,   g_Vp);
    cudaGetSymbolAddress((void**)&qfh,  g_qfh);
    cudaGetSymbolAddress((void**)&kfh,  g_kfh);
    cudaGetSymbolAddress((void**)&vfh,  g_vfh);
    cudaGetSymbolAddress((void**)&qafh, g_qafh);
    cudaGetSymbolAddress((void**)&aofh, g_aofh);
    cudaGetSymbolAddress((void**)&Wqfh, g_Wqfh);
    cudaGetSymbolAddress((void**)&Wkfh, g_Wkfh);
    cudaGetSymbolAddress((void**)&Wvfh, g_Wvfh);
    cudaGetSymbolAddress((void**)&Wofh, g_Wofh);
    cudaGetSymbolAddress((void**)&Kfrh, g_Kfrh);
    cudaGetSymbolAddress((void**)&Vfrh, g_Vfrh);

    const int M = Bc * Sc;
    const int SMEM = 32768;

    // 1. fragmentize inputs (fused q,k,v)
    {
        dim3 grid((M / 64) * (Dc / 64), 3);
        fragA3<<<grid, 256>>>(q, k, v, qfh, kfh, vfh);
    }
    // 2. fragmentize weights (fused)
    fragB4<<<640, 256>>>(Wq, Wk, Wv, Wo, Wqfh, Wkfh, Wvfh, Wofh);

    // 3. Q projection -> fragment-major fp16
    {
        dim3 grid(Dc / 128, M / 128);
        gemm_q<<<grid, 256, SMEM>>>(qfh, Wqfh, bq, qafh);
    }
    // 4. fused K/V projection (K -> Kfr fragments, V -> float Vp)
    {
        dim3 grid(KVD / 128, M / 128, 2);
        gemm_kv<<<grid, 256, SMEM>>>(kfh, Wkfh, bk, vfh, Wvfh, bv, Kfrh, Vp);
    }
    // 5. fragmentize V for attention
    fragV_tile<<<Bc * HKVc * 32, 256>>>(Vp, Vfrh);

    // 6. attention
    {
        dim3 grid(Sc / 128, Hc, Bc);
        attn_f16<<<grid, 256, SMEM>>>(qafh, Kfrh, Vfrh, aofh);
    }
    // 7. output projection
    {
        dim3 grid(Dc / 128, M / 128);
        gemm_o<<<grid, 256, SMEM>>>(aofh, Wofh, bo, out);
    }
}

// round 14
// speedup vs baseline: 7.9533x; 1.0105x over previous
#include <cuda_runtime.h>
#include <cuda_fp16.h>
#include <cstdint>

// Problem constants
constexpr int Bc   = 2;
constexpr int Sc   = 2048;
constexpr int Dc   = 1024;
constexpr int Hc   = 16;
constexpr int HKVc = 4;
constexpr int DKc  = 64;         // D / H
constexpr int KVD  = HKVc * DKc; // 256

// Scratch (device globals, allocation-free)
__device__ float    g_Vp[Bc * Sc * KVD];                     // projected V (float, [M,256])
__device__ unsigned g_qfh [(Bc*Sc/16) * (Dc/16) * 32 * 4];   // input A-fragments
__device__ unsigned g_kfh [(Bc*Sc/16) * (Dc/16) * 32 * 4];
__device__ unsigned g_vfh [(Bc*Sc/16) * (Dc/16) * 32 * 4];
__device__ unsigned g_qafh[(Bc*Sc/16) * (Dc/16) * 32 * 4];   // projected Q, A-fragments (fp16)
__device__ unsigned g_aofh[(Bc*Sc/16) * (Dc/16) * 32 * 4];   // attn out, A-fragments (fp16)
__device__ unsigned g_Wqfh[(Dc/8)  * (Dc/16) * 32 * 2];
__device__ unsigned g_Wkfh[(KVD/8) * (Dc/16) * 32 * 2];
__device__ unsigned g_Wvfh[(KVD/8) * (Dc/16) * 32 * 2];
__device__ unsigned g_Wofh[(Dc/8)  * (Dc/16) * 32 * 2];
// attention K/V B-fragments: [b*HKV][kt(32)][fc(32)][lane(32)][2]
__device__ unsigned g_Kfrh[Bc * HKVc * 32 * 2048];
__device__ unsigned g_Vfrh[Bc * HKVc * 32 * 2048];

// ---------------------------------------------------------------------------
// helpers
// ---------------------------------------------------------------------------
__device__ __forceinline__ unsigned h2u(float a, float b) {
    __half2 h = __floats2half2_rn(a, b);
    return *(unsigned*)&h;
}

__device__ __forceinline__ void mma_f16(float* d, const unsigned* a, const unsigned* b) {
    asm volatile(
        "mma.sync.aligned.m16n8k16.row.col.f32.f16.f16.f32 "
        "{%0,%1,%2,%3}, {%4,%5,%6,%7}, {%8,%9}, {%0,%1,%2,%3};\n"
        : "+f"(d[0]), "+f"(d[1]), "+f"(d[2]), "+f"(d[3])
        : "r"(a[0]), "r"(a[1]), "r"(a[2]), "r"(a[3]), "r"(b[0]), "r"(b[1]));
}

__device__ __forceinline__ void cp_async16(uint32_t smem_addr, const void* gptr) {
    asm volatile("cp.async.cg.shared.global [%0], [%1], 16;" :: "r"(smem_addr), "l"(gptr));
}
__device__ __forceinline__ void cp_commit() { asm volatile("cp.async.commit_group;"); }
__device__ __forceinline__ void cp_wait0()  { asm volatile("cp.async.wait_group 0;"); }
__device__ __forceinline__ void cp_wait1()  { asm volatile("cp.async.wait_group 1;"); }

// ---------------------------------------------------------------------------
// Fused fragmentize of q,k,v (A-operands) via smem tile transpose.
// pad = 68 so float4 smem stores stay 16B-aligned.
// ---------------------------------------------------------------------------
__global__ __launch_bounds__(256) void fragA3(
    const float* __restrict__ q, const float* __restrict__ k,
    const float* __restrict__ v, unsigned* __restrict__ qf,
    unsigned* __restrict__ kf, unsigned* __restrict__ vf)
{
    __shared__ float tile[64][68];
    const float* A; unsigned* out;
    if (blockIdx.y == 0)      { A = q; out = qf; }
    else if (blockIdx.y == 1) { A = k; out = kf; }
    else                      { A = v; out = vf; }

    const int K = Dc, KT = K / 64, KC = K / 16;
    const int bt = blockIdx.x;
    const int bm64 = (bt / KT) * 64, bk64 = (bt % KT) * 64;
    const int tid = threadIdx.x;

    #pragma unroll
    for (int i = 0; i < 4; i++) {
        int f = tid + i * 256;
        int row = f >> 4, col4 = (f & 15) * 4;
        *(float4*)&tile[row][col4] = *(const float4*)&A[(size_t)(bm64 + row) * K + bk64 + col4];
    }
    __syncthreads();

    #pragma unroll
    for (int i = 0; i < 2; i++) {
        int s = tid + i * 256;
        int blk = s >> 5, lane = s & 31;
        int mtl = blk >> 2, kcl = blk & 3;
        int g = lane >> 2, t = lane & 3;
        int r0 = mtl * 16 + g, c0 = kcl * 16 + 2 * t;
        uint4 o;
        o.x = h2u(tile[r0][c0],         tile[r0][c0 + 1]);
        o.y = h2u(tile[r0 + 8][c0],     tile[r0 + 8][c0 + 1]);
        o.z = h2u(tile[r0][c0 + 8],     tile[r0][c0 + 9]);
        o.w = h2u(tile[r0 + 8][c0 + 8], tile[r0 + 8][c0 + 9]);
        int mt = bm64 / 16 + mtl, kc = bk64 / 16 + kcl;
        *(uint4*)&out[((size_t)(mt * KC + kc) * 32 + lane) * 4] = o;
    }
}

// ---------------------------------------------------------------------------
// Fused fragmentize of all 4 weights (B-operands).
// grid.x = 256 (Wq) + 64 (Wk) + 64 (Wv) + 256 (Wo) = 640 blocks.
// ---------------------------------------------------------------------------
__global__ __launch_bounds__(256) void fragB4(
    const float* __restrict__ Wq, const float* __restrict__ Wk,
    const float* __restrict__ Wv, const float* __restrict__ Wo,
    unsigned* __restrict__ Wqf, unsigned* __restrict__ Wkf,
    unsigned* __restrict__ Wvf, unsigned* __restrict__ Wof)
{
    __shared__ float tile[64][68];
    int bt = blockIdx.x;
    const float* B; unsigned* out; int N;
    if (bt < 256)      { B = Wq; out = Wqf; N = 1024; }
    else if (bt < 320) { B = Wk; out = Wkf; N = 256;  bt -= 256; }
    else if (bt < 384) { B = Wv; out = Wvf; N = 256;  bt -= 320; }
    else               { B = Wo; out = Wof; N = 1024; bt -= 384; }

    const int K = Dc, KC = K / 16, NT = N / 64;
    const int bk64 = (bt / NT) * 64, bn64 = (bt % NT) * 64;
    const int tid = threadIdx.x;

    #pragma unroll
    for (int i = 0; i < 4; i++) {
        int f = tid + i * 256;
        int row = f >> 4, col4 = (f & 15) * 4;   // row = k, col = n
        *(float4*)&tile[row][col4] = *(const float4*)&B[(size_t)(bk64 + row) * N + bn64 + col4];
    }
    __syncthreads();

    #pragma unroll
    for (int i = 0; i < 4; i++) {
        int s = tid + i * 256;
        int blk = s >> 5, lane = s & 31;
        int ntl = blk >> 2, kcl = blk & 3;
        int g = lane >> 2, t = lane & 3;
        int n = ntl * 8 + g, k0 = kcl * 16 + 2 * t;
        uint2 o;
        o.x = h2u(tile[k0][n],     tile[k0 + 1][n]);
        o.y = h2u(tile[k0 + 8][n], tile[k0 + 9][n]);
        int nt = bn64 / 8 + ntl, kc = bk64 / 16 + kcl;
        *(uint2*)&out[((size_t)(nt * KC + kc) * 32 + lane) * 2] = o;
    }
}

// ---------------------------------------------------------------------------
// Fragmentize V for attention (reads float Vp [M,256]).
// grid.x = Bc*HKVc*32 = 256.
// ---------------------------------------------------------------------------
__global__ __launch_bounds__(256) void fragV_tile(
    const float* __restrict__ Vp, unsigned* __restrict__ Vf)
{
    __shared__ float tile[64][68];
    const int id = blockIdx.x;
    const int kt = id & 31, hkv = (id >> 5) & 3, b = id >> 7;
    const int tid = threadIdx.x;

    #pragma unroll
    for (int i = 0; i < 4; i++) {
        int f = tid + i * 256;
        int row = f >> 4, col4 = (f & 15) * 4;   // row = key, col = dk
        *(float4*)&tile[row][col4] =
            *(const float4*)&Vp[(size_t)(b * Sc + kt * 64 + row) * KVD + hkv * 64 + col4];
    }
    __syncthreads();

    #pragma unroll
    for (int i = 0; i < 4; i++) {
        int s = tid + i * 256;
        int blk = s >> 5, lane = s & 31;
        int kcl = blk >> 3, nd = blk & 7;
        int g = lane >> 2, t = lane & 3;
        int k0 = kcl * 16 + 2 * t, n = nd * 8 + g;
        uint2 o;
        o.x = h2u(tile[k0][n],     tile[k0 + 1][n]);
        o.y = h2u(tile[k0 + 8][n], tile[k0 + 9][n]);
        int fc = kcl * 8 + nd;
        *(uint2*)&Vf[(((size_t)((b * HKVc + hkv) * 32 + kt) * 32 + fc) * 32 + lane) * 2] = o;
    }
}

// ---------------------------------------------------------------------------
// Shared fp16 GEMM mainloop, 3-STAGE cp.async pipeline.
// BM=BN=128, BK=32, 256 thr, warp tile 64x32, m16n8k16.
// A bufs: smu[buf*2048] (buf=0..2); B bufs: smu[6144 + buf*2048]. 48KB smem.
// ---------------------------------------------------------------------------
__device__ __forceinline__ void mainloop_f16(
    const unsigned* __restrict__ Af, const unsigned* __restrict__ Bf,
    int K, int bm, int bn, unsigned* smu, float c[4][4][4])
{
    const int tid  = threadIdx.x;
    const int lane = tid & 31;
    const int warp = tid >> 5;
    const int wm   = warp >> 2;
    const int wn   = warp & 3;
    const int KC   = K >> 4;
    const uint32_t sb = (uint32_t)__cvta_generic_to_shared(smu);

    #pragma unroll
    for (int mi = 0; mi < 4; mi++)
        #pragma unroll
        for (int ni = 0; ni < 4; ni++)
            #pragma unroll
            for (int r = 0; r < 4; r++) c[mi][ni][r] = 0.f;

    auto stage = [&](int buf, int k0) {
        #pragma unroll
        for (int t2 = 0; t2 < 2; t2++) {
            int idx = tid + t2 * 256;
            int blkA = idx >> 5, ln = idx & 31;
            int mt = (bm >> 4) + (blkA >> 1);
            int kc = (k0 >> 4) + (blkA & 1);
            cp_async16(sb + (buf * 2048 + blkA * 128 + ln * 4) * 4,
                       Af + ((size_t)(mt * KC + kc) * 32 + ln) * 4);
        }
        #pragma unroll
        for (int t2 = 0; t2 < 2; t2++) {
            int idx = tid + t2 * 256;
            int blkB = idx >> 4, lp = idx & 15;
            int nt = (bn >> 3) + (blkB >> 1);
            int kc = (k0 >> 4) + (blkB & 1);
            cp_async16(sb + (6144 + buf * 2048 + blkB * 64 + lp * 4) * 4,
                       Bf + ((size_t)(nt * KC + kc) * 32 + lp * 2) * 2);
        }
        cp_commit();
    };

    const int nit = K >> 5;        // 32
    stage(0, 0);
    stage(1, 32);
    int buf = 0;
    for (int it = 0; it < nit; it++) {
        if (it + 1 < nit) cp_wait1(); else cp_wait0();
        __syncthreads();
        if (it + 2 < nit) {
            int nb = buf + 2; if (nb >= 3) nb -= 3;
            stage(nb, (it + 2) << 5);
        }

        #pragma unroll
        for (int kc = 0; kc < 2; kc++) {
            unsigned a[4][4], b[4][2];
            #pragma unroll
            for (int mi = 0; mi < 4; mi++)
                *(uint4*)a[mi] = *(uint4*)&smu[buf * 2048 + (((wm * 4 + mi) * 2 + kc) * 32 + lane) * 4];
            #pragma unroll
            for (int ni = 0; ni < 4; ni++)
                *(uint2*)b[ni] = *(uint2*)&smu[6144 + buf * 2048 + (((wn * 4 + ni) * 2 + kc) * 32 + lane) * 2];
            #pragma unroll
            for (int mi = 0; mi < 4; mi++)
                #pragma unroll
                for (int ni = 0; ni < 4; ni++)
                    mma_f16(c[mi][ni], a[mi], b[ni]);
        }
        if (++buf == 3) buf = 0;
    }
    __syncthreads();
}

// ---------------------------------------------------------------------------
// FUSED Q/K/V projection, one launch, 384 blocks.
//   blocks [0,256):   Q-proj -> fragment-major fp16 A-operand (qafh)
//   blocks [256,320): K-proj -> attention B-fragments (Kfrh) directly
//   blocks [320,384): V-proj -> float Vp [M,256]
// ---------------------------------------------------------------------------
__global__ __launch_bounds__(256) void gemm_qkv(
    const unsigned* __restrict__ qf, const unsigned* __restrict__ kf,
    const unsigned* __restrict__ vf,
    const unsigned* __restrict__ Wqf, const unsigned* __restrict__ Wkf,
    const unsigned* __restrict__ Wvf,
    const float* __restrict__ bqv, const float* __restrict__ bkv,
    const float* __restrict__ bvv,
    unsigned* __restrict__ Qaf, unsigned* __restrict__ Kfr,
    float* __restrict__ Vp)
{
    extern __shared__ unsigned smu[];
    const int bt = blockIdx.x;
    const unsigned *Af, *Bf;
    const float* bias;
    int bm, bn, mode;
    if (bt < 256) {
        Af = qf; Bf = Wqf; bias = bqv; mode = 0;
        bm = (bt >> 3) * 128; bn = (bt & 7) * 128;
    } else if (bt < 320) {
        int u = bt - 256;
        Af = kf; Bf = Wkf; bias = bkv; mode = 1;
        bm = (u >> 1) * 128; bn = (u & 1) * 128;
    } else {
        int u = bt - 320;
        Af = vf; Bf = Wvf; bias = bvv; mode = 2;
        bm = (u >> 1) * 128; bn = (u & 1) * 128;
    }

    float c[4][4][4];
    mainloop_f16(Af, Bf, Dc, bm, bn, smu, c);

    const int lane = threadIdx.x & 31, warp = threadIdx.x >> 5;
    const int wm = warp >> 2, wn = warp & 3;
    const int g = lane >> 2, t = lane & 3;

    if (mode == 0) {
        // ---- Q: fragment-major fp16 A-operand
        const int KC16 = Dc >> 4;    // 64
        #pragma unroll
        for (int mi = 0; mi < 4; mi++) {
            int mt = (bm + wm * 64 + mi * 16) >> 4;
            #pragma unroll
            for (int kc2 = 0; kc2 < 2; kc2++) {
                int colb = bn + wn * 32 + kc2 * 16;
                float b0 = bias[colb + 2*t], b1 = bias[colb + 2*t + 1];
                float b2 = bias[colb + 8 + 2*t], b3 = bias[colb + 9 + 2*t];
                uint4 o;
                o.x = h2u(c[mi][2*kc2][0] + b0,   c[mi][2*kc2][1] + b1);
                o.y = h2u(c[mi][2*kc2][2] + b0,   c[mi][2*kc2][3] + b1);
                o.z = h2u(c[mi][2*kc2+1][0] + b2, c[mi][2*kc2+1][1] + b3);
                o.w = h2u(c[mi][2*kc2+1][2] + b2, c[mi][2*kc2+1][3] + b3);
                int kcg = (colb >> 4);
                *(uint4*)&Qaf[((size_t)(mt * KC16 + kcg) * 32 + lane) * 4] = o;
            }
        }
    } else if (mode == 1) {
        // ---- K: attention B-fragments directly
        #pragma unroll
        for (int mi = 0; mi < 4; mi++) {
            int r0 = bm + wm * 64 + mi * 16 + g;
            int b  = r0 >> 11;
            int s  = r0 & 2047;
            int kt = s >> 6;
            int nt0 = ((s & 63) >> 3);
            #pragma unroll
            for (int kc2 = 0; kc2 < 2; kc2++) {
                int colb = bn + wn * 32 + kc2 * 16;
                int hkv = colb >> 6;
                int kc  = (colb & 63) >> 4;
                float b0 = bias[colb + 2*t], b1 = bias[colb + 2*t + 1];
                float b2 = bias[colb + 8 + 2*t], b3 = bias[colb + 9 + 2*t];
                size_t base = ((size_t)((b * HKVc + hkv) * 32 + kt) * 32);
                uint2 o1, o2;
                o1.x = h2u(c[mi][2*kc2][0] + b0,   c[mi][2*kc2][1] + b1);
                o1.y = h2u(c[mi][2*kc2+1][0] + b2, c[mi][2*kc2+1][1] + b3);
                o2.x = h2u(c[mi][2*kc2][2] + b0,   c[mi][2*kc2][3] + b1);
                o2.y = h2u(c[mi][2*kc2+1][2] + b2, c[mi][2*kc2+1][3] + b3);
                *(uint2*)&Kfr[((base + kc * 8 + nt0)     * 32 + lane) * 2] = o1;
                *(uint2*)&Kfr[((base + kc * 8 + nt0 + 1) * 32 + lane) * 2] = o2;
            }
        }
    } else {
        // ---- V: plain float epilogue into Vp [M, 256]
        #pragma unroll
        for (int mi = 0; mi < 4; mi++) {
            int row = bm + wm * 64 + mi * 16 + g;
            #pragma unroll
            for (int ni = 0; ni < 4; ni++) {
                int col = bn + wn * 32 + ni * 8 + t * 2;
                float b0 = bias[col], b1 = bias[col + 1];
                *(float2*)&Vp[(size_t)row * KVD + col] =
                    make_float2(c[mi][ni][0] + b0, c[mi][ni][1] + b1);
                *(float2*)&Vp[(size_t)(row + 8) * KVD + col] =
                    make_float2(c[mi][ni][2] + b0, c[mi][ni][3] + b1);
            }
        }
    }
}

// ---------------------------------------------------------------------------
// O projection: standard float epilogue to d_out.
// ---------------------------------------------------------------------------
__global__ __launch_bounds__(256) void gemm_o(
    const unsigned* __restrict__ Af, const unsigned* __restrict__ Bf,
    const float* __restrict__ bias, float* __restrict__ C)
{
    extern __shared__ unsigned smu[];
    const int bm = blockIdx.y * 128, bn = blockIdx.x * 128;
    float c[4][4][4];
    mainloop_f16(Af, Bf, Dc, bm, bn, smu, c);

    const int lane = threadIdx.x & 31, warp = threadIdx.x >> 5;
    const int wm = warp >> 2, wn = warp & 3;
    const int g = lane >> 2, t2 = lane & 3;
    #pragma unroll
    for (int mi = 0; mi < 4; mi++) {
        int row = bm + wm * 64 + mi * 16 + g;
        #pragma unroll
        for (int ni = 0; ni < 4; ni++) {
            int col = bn + wn * 32 + ni * 8 + t2 * 2;
            float b0 = bias[col], b1 = bias[col + 1];
            *(float2*)&C[(size_t)row * Dc + col] =
                make_float2(c[mi][ni][0] + b0, c[mi][ni][1] + b1);
            *(float2*)&C[(size_t)(row + 8) * Dc + col] =
                make_float2(c[mi][ni][2] + b0, c[mi][ni][3] + b1);
        }
    }
}

// ---------------------------------------------------------------------------
// fp16 tensor-core flash attention (causal, GQA), 3-STAGE K/V pipeline.
// grid (S/128, H, B), qt reversed; 256 threads = 8 warps, warp = 16-row tile.
// K bufs: smu[buf*2048]; V bufs: smu[6144 + buf*2048]. 48KB smem.
// ---------------------------------------------------------------------------
__global__ __launch_bounds__(256) void attn_f16(
    const unsigned* __restrict__ Qf, const unsigned* __restrict__ Kf,
    const unsigned* __restrict__ Vf, unsigned* __restrict__ AOf)
{
    extern __shared__ unsigned smu[];
    const int qt  = (gridDim.x - 1) - blockIdx.x;
    const int h   = blockIdx.y;
    const int b   = blockIdx.z;
    const int hkv = h >> 2;
    const int tid = threadIdx.x;
    const int lane = tid & 31;
    const int w    = tid >> 5;
    const int g    = lane >> 2;
    const int t    = lane & 3;
    const int qbase = qt * 128;
    const int rmin  = qbase + w * 16;
    const uint32_t sb = (uint32_t)__cvta_generic_to_shared(smu);

    // ---- Q fragments: coalesced uint4 loads from fragment-major buffer
    unsigned qa[4][4];
    {
        const int mt = (b * Sc + rmin) >> 4;
        #pragma unroll
        for (int kc = 0; kc < 4; kc++)
            *(uint4*)qa[kc] = *(const uint4*)&Qf[((size_t)(mt * 64 + h * 4 + kc) * 32 + lane) * 4];
    }

    float o[8][4];
    #pragma unroll
    for (int nd = 0; nd < 8; nd++)
        #pragma unroll
        for (int r = 0; r < 4; r++) o[nd][r] = 0.f;
    float m0 = -1e30f, m1 = -1e30f, l0 = 0.f, l1 = 0.f;

    const int bh = b * HKVc + hkv;
    const unsigned* Kt = Kf + (size_t)bh * 32 * 2048;
    const unsigned* Vt = Vf + (size_t)bh * 32 * 2048;

    auto stage = [&](int buf, int kt) {
        const unsigned* ks = Kt + (size_t)kt * 2048;
        const unsigned* vs = Vt + (size_t)kt * 2048;
        #pragma unroll
        for (int t2 = 0; t2 < 2; t2++) {
            int pos = tid + t2 * 256;
            cp_async16(sb + (buf * 2048 + pos * 4) * 4, ks + pos * 4);
            cp_async16(sb + (6144 + buf * 2048 + pos * 4) * 4, vs + pos * 4);
        }
        cp_commit();
    };

    const int ntiles = 2 * qt + 2;   // always >= 2
    stage(0, 0);
    stage(1, 1);
    int buf = 0;

    for (int kt = 0; kt < ntiles; kt++) {
        if (kt + 1 < ntiles) cp_wait1(); else cp_wait0();
        __syncthreads();
        if (kt + 2 < ntiles) {
            int nb = buf + 2; if (nb >= 3) nb -= 3;
            stage(nb, kt + 2);
        }

        float s[8][4];
        #pragma unroll
        for (int nt = 0; nt < 8; nt++)
            #pragma unroll
            for (int r = 0; r < 4; r++) s[nt][r] = 0.f;

        #pragma unroll
        for (int kc = 0; kc < 4; kc++) {
            #pragma unroll
            for (int nt = 0; nt < 8; nt++) {
                unsigned bf[2];
                *(uint2*)bf = *(uint2*)&smu[buf * 2048 + ((kc * 8 + nt) * 32 + lane) * 2];
                mma_f16(s[nt], qa[kc], bf);
            }
        }

        if (kt * 64 + 63 > rmin) {
            int r0 = rmin + g, r1 = r0 + 8;
            #pragma unroll
            for (int nt = 0; nt < 8; nt++) {
                int c0 = kt * 64 + nt * 8 + 2 * t, c1 = c0 + 1;
                s[nt][0] = (c0 > r0) ? -1e30f : s[nt][0] * 0.125f;
                s[nt][1] = (c1 > r0) ? -1e30f : s[nt][1] * 0.125f;
                s[nt][2] = (c0 > r1) ? -1e30f : s[nt][2] * 0.125f;
                s[nt][3] = (c1 > r1) ? -1e30f : s[nt][3] * 0.125f;
            }
        } else {
            #pragma unroll
            for (int nt = 0; nt < 8; nt++)
                #pragma unroll
                for (int r = 0; r < 4; r++) s[nt][r] *= 0.125f;
        }

        float mt0 = -1e30f, mt1 = -1e30f;
        #pragma unroll
        for (int nt = 0; nt < 8; nt++) {
            mt0 = fmaxf(mt0, fmaxf(s[nt][0], s[nt][1]));
            mt1 = fmaxf(mt1, fmaxf(s[nt][2], s[nt][3]));
        }
        mt0 = fmaxf(mt0, __shfl_xor_sync(0xffffffffu, mt0, 1));
        mt0 = fmaxf(mt0, __shfl_xor_sync(0xffffffffu, mt0, 2));
        mt1 = fmaxf(mt1, __shfl_xor_sync(0xffffffffu, mt1, 1));
        mt1 = fmaxf(mt1, __shfl_xor_sync(0xffffffffu, mt1, 2));
        float mn0 = fmaxf(m0, mt0), mn1 = fmaxf(m1, mt1);
        float cr0 = __expf(m0 - mn0), cr1 = __expf(m1 - mn1);
        float ps0 = 0.f, ps1 = 0.f;
        #pragma unroll
        for (int nt = 0; nt < 8; nt++) {
            float p0 = __half2float(__float2half_rn(__expf(s[nt][0] - mn0)));
            float p1 = __half2float(__float2half_rn(__expf(s[nt][1] - mn0)));
            float p2 = __half2float(__float2half_rn(__expf(s[nt][2] - mn1)));
            float p3 = __half2float(__float2half_rn(__expf(s[nt][3] - mn1)));
            s[nt][0] = p0; s[nt][1] = p1; s[nt][2] = p2; s[nt][3] = p3;
            ps0 += p0 + p1;
            ps1 += p2 + p3;
        }
        ps0 += __shfl_xor_sync(0xffffffffu, ps0, 1);
        ps0 += __shfl_xor_sync(0xffffffffu, ps0, 2);
        ps1 += __shfl_xor_sync(0xffffffffu, ps1, 1);
        ps1 += __shfl_xor_sync(0xffffffffu, ps1, 2);
        l0 = l0 * cr0 + ps0;
        l1 = l1 * cr1 + ps1;
        m0 = mn0; m1 = mn1;
        #pragma unroll
        for (int nd = 0; nd < 8; nd++) {
            o[nd][0] *= cr0; o[nd][1] *= cr0;
            o[nd][2] *= cr1; o[nd][3] *= cr1;
        }

        unsigned pa[4][4];
        #pragma unroll
        for (int kc = 0; kc < 4; kc++) {
            pa[kc][0] = h2u(s[2*kc][0],   s[2*kc][1]);
            pa[kc][1] = h2u(s[2*kc][2],   s[2*kc][3]);
            pa[kc][2] = h2u(s[2*kc+1][0], s[2*kc+1][1]);
            pa[kc][3] = h2u(s[2*kc+1][2], s[2*kc+1][3]);
        }

        #pragma unroll
        for (int kc = 0; kc < 4; kc++) {
            #pragma unroll
            for (int nd = 0; nd < 8; nd++) {
                unsigned bf[2];
                *(uint2*)bf = *(uint2*)&smu[6144 + buf * 2048 + ((kc * 8 + nd) * 32 + lane) * 2];
                mma_f16(o[nd], pa[kc], bf);
            }
        }
        if (++buf == 3) buf = 0;
    }

    float inv0 = 1.f / l0, inv1 = 1.f / l1;
    const int KC16 = Dc >> 4;
    const int mt = ((b * Sc + qbase) >> 4) + w;
    #pragma unroll
    for (int c = 0; c < 4; c++) {
        uint4 wv;
        wv.x = h2u(o[2*c][0] * inv0,   o[2*c][1] * inv0);
        wv.y = h2u(o[2*c][2] * inv1,   o[2*c][3] * inv1);
        wv.z = h2u(o[2*c+1][0] * inv0, o[2*c+1][1] * inv0);
        wv.w = h2u(o[2*c+1][2] * inv1, o[2*c+1][3] * inv1);
        *(uint4*)&AOf[((size_t)(mt * KC16 + h * 4 + c) * 32 + lane) * 4] = wv;
    }
}

// ---------------------------------------------------------------------------
// Launch
// ---------------------------------------------------------------------------
extern "C" void kernel_launch(void* const* d_in, const int* in_sizes, int n_in,
                              void* d_out, int out_size)
{
    const float* q  = (const float*)d_in[0];
    const float* k  = (const float*)d_in[1];
    const float* v  = (const float*)d_in[2];
    const float* Wq = (const float*)d_in[4];
    const float* bq = (const float*)d_in[5];
    const float* Wk = (const float*)d_in[6];
    const float* bk = (const float*)d_in[7];
    const float* Wv = (const float*)d_in[8];
    const float* bv = (const float*)d_in[9];
    const float* Wo = (const float*)d_in[10];
    const float* bo = (const float*)d_in[11];
    float* out = (float*)d_out;

    float *Vp;
    unsigned *qfh, *kfh, *vfh, *qafh, *aofh, *Wqfh, *Wkfh, *Wvfh, *Wofh, *Kfrh, *Vfrh;
    cudaGetSymbolAddress((void**)&Vp,   g_Vp);
    cudaGetSymbolAddress((void**)&qfh,  g_qfh);
    cudaGetSymbolAddress((void**)&kfh,  g_kfh);
    cudaGetSymbolAddress((void**)&vfh,  g_vfh);
    cudaGetSymbolAddress((void**)&qafh, g_qafh);
    cudaGetSymbolAddress((void**)&aofh, g_aofh);
    cudaGetSymbolAddress((void**)&Wqfh, g_Wqfh);
    cudaGetSymbolAddress((void**)&Wkfh, g_Wkfh);
    cudaGetSymbolAddress((void**)&Wvfh, g_Wvfh);
    cudaGetSymbolAddress((void**)&Wofh, g_Wofh);
    cudaGetSymbolAddress((void**)&Kfrh, g_Kfrh);
    cudaGetSymbolAddress((void**)&Vfrh, g_Vfrh);

    const int M = Bc * Sc;
    const int SMEM = 49152;   // 3-stage: 3*(8KB A + 8KB B)

    // 1. fragmentize inputs (fused q,k,v)
    {
        dim3 grid((M / 64) * (Dc / 64), 3);
        fragA3<<<grid, 256>>>(q, k, v, qfh, kfh, vfh);
    }
    // 2. fragmentize weights (fused)
    fragB4<<<640, 256>>>(Wq, Wk, Wv, Wo, Wqfh, Wkfh, Wvfh, Wofh);

    // 3. FUSED Q/K/V projections (384 blocks)
    gemm_qkv<<<384, 256, SMEM>>>(qfh, kfh, vfh, Wqfh, Wkfh, Wvfh,
                                 bq, bk, bv, qafh, Kfrh, Vp);

    // 4. fragmentize V for attention
    fragV_tile<<<Bc * HKVc * 32, 256>>>(Vp, Vfrh);

    // 5. attention
    {
        dim3 grid(Sc / 128, Hc, Bc);
        attn_f16<<<grid, 256, SMEM>>>(qafh, Kfrh, Vfrh, aofh);
    }
    // 6. output projection
    {
        dim3 grid(Dc / 128, M / 128);
        gemm_o<<<grid, 256, SMEM>>>(aofh, Wofh, bo, out);
    }
}

// round 15
// speedup vs baseline: 8.9732x; 1.1282x over previous
#include <cuda_runtime.h>
#include <cuda_fp16.h>
#include <cstdint>

// Problem constants
constexpr int Bc   = 2;
constexpr int Sc   = 2048;
constexpr int Dc   = 1024;
constexpr int Hc   = 16;
constexpr int HKVc = 4;
constexpr int DKc  = 64;         // D / H
constexpr int KVD  = HKVc * DKc; // 256

// Scratch (device globals, allocation-free)
__device__ unsigned g_qfh [(Bc*Sc/16) * (Dc/16) * 32 * 4];   // input A-fragments
__device__ unsigned g_kfh [(Bc*Sc/16) * (Dc/16) * 32 * 4];
__device__ unsigned g_vfh [(Bc*Sc/16) * (Dc/16) * 32 * 4];
__device__ unsigned g_qafh[(Bc*Sc/16) * (Dc/16) * 32 * 4];   // projected Q, A-fragments
__device__ unsigned g_aofh[(Bc*Sc/16) * (Dc/16) * 32 * 4];   // attn out, A-fragments
__device__ unsigned g_Wqfh[(Dc/8)  * (Dc/16) * 32 * 2];
__device__ unsigned g_Wkfh[(KVD/8) * (Dc/16) * 32 * 2];
__device__ unsigned g_Wvfh[(KVD/8) * (Dc/16) * 32 * 2];
__device__ unsigned g_Wofh[(Dc/8)  * (Dc/16) * 32 * 2];
// attention K/V B-fragments: [b*HKV][kt(32)][fc(32)][lane(32)][2]
__device__ unsigned g_Kfrh[Bc * HKVc * 32 * 2048];
__device__ unsigned g_Vfrh[Bc * HKVc * 32 * 2048];

// ---------------------------------------------------------------------------
// helpers
// ---------------------------------------------------------------------------
__device__ __forceinline__ unsigned h2u(float a, float b) {
    __half2 h = __floats2half2_rn(a, b);
    return *(unsigned*)&h;
}
__device__ __forceinline__ unsigned hh2u(__half a, __half b) {
    __half2 h = __halves2half2(a, b);
    return *(unsigned*)&h;
}

__device__ __forceinline__ void mma_f16(float* d, const unsigned* a, const unsigned* b) {
    asm volatile(
        "mma.sync.aligned.m16n8k16.row.col.f32.f16.f16.f32 "
        "{%0,%1,%2,%3}, {%4,%5,%6,%7}, {%8,%9}, {%0,%1,%2,%3};\n"
        : "+f"(d[0]), "+f"(d[1]), "+f"(d[2]), "+f"(d[3])
        : "r"(a[0]), "r"(a[1]), "r"(a[2]), "r"(a[3]), "r"(b[0]), "r"(b[1]));
}

__device__ __forceinline__ void cp_async16(uint32_t smem_addr, const void* gptr) {
    asm volatile("cp.async.cg.shared.global [%0], [%1], 16;" :: "r"(smem_addr), "l"(gptr));
}
__device__ __forceinline__ void cp_commit() { asm volatile("cp.async.commit_group;"); }
__device__ __forceinline__ void cp_wait0()  { asm volatile("cp.async.wait_group 0;"); }
__device__ __forceinline__ void cp_wait1()  { asm volatile("cp.async.wait_group 1;"); }

// ---------------------------------------------------------------------------
// MERGED input fragmentize: blocks [0,3072) = q/k/v A-fragments (1024 each);
// blocks [3072,3712) = weight B-fragments (Wq 256 | Wk 64 | Wv 64 | Wo 256).
// pad = 68 so float4 smem stores stay 16B-aligned.
// ---------------------------------------------------------------------------
__global__ __launch_bounds__(256) void frag_inputs(
    const float* __restrict__ q, const float* __restrict__ k,
    const float* __restrict__ v,
    const float* __restrict__ Wq, const float* __restrict__ Wk,
    const float* __restrict__ Wv, const float* __restrict__ Wo,
    unsigned* __restrict__ qf, unsigned* __restrict__ kf,
    unsigned* __restrict__ vf,
    unsigned* __restrict__ Wqf, unsigned* __restrict__ Wkf,
    unsigned* __restrict__ Wvf, unsigned* __restrict__ Wof)
{
    __shared__ float tile[64][68];
    const int tid = threadIdx.x;
    int bt = blockIdx.x;

    if (bt < 3072) {
        // ---- A-fragments for q/k/v
        const float* A; unsigned* out;
        int sel = bt >> 10; bt &= 1023;
        if (sel == 0)      { A = q; out = qf; }
        else if (sel == 1) { A = k; out = kf; }
        else               { A = v; out = vf; }

        const int KT = Dc / 64, KC = Dc / 16;
        const int bm64 = (bt / KT) * 64, bk64 = (bt % KT) * 64;

        #pragma unroll
        for (int i = 0; i < 4; i++) {
            int f = tid + i * 256;
            int row = f >> 4, col4 = (f & 15) * 4;
            *(float4*)&tile[row][col4] = *(const float4*)&A[(size_t)(bm64 + row) * Dc + bk64 + col4];
        }
        __syncthreads();

        #pragma unroll
        for (int i = 0; i < 2; i++) {
            int s = tid + i * 256;
            int blk = s >> 5, lane = s & 31;
            int mtl = blk >> 2, kcl = blk & 3;
            int g = lane >> 2, t = lane & 3;
            int r0 = mtl * 16 + g, c0 = kcl * 16 + 2 * t;
            uint4 o;
            o.x = h2u(tile[r0][c0],         tile[r0][c0 + 1]);
            o.y = h2u(tile[r0 + 8][c0],     tile[r0 + 8][c0 + 1]);
            o.z = h2u(tile[r0][c0 + 8],     tile[r0][c0 + 9]);
            o.w = h2u(tile[r0 + 8][c0 + 8], tile[r0 + 8][c0 + 9]);
            int mt = bm64 / 16 + mtl, kc = bk64 / 16 + kcl;
            *(uint4*)&out[((size_t)(mt * KC + kc) * 32 + lane) * 4] = o;
        }
    } else {
        // ---- B-fragments for weights
        bt -= 3072;
        const float* B; unsigned* out; int N;
        if (bt < 256)      { B = Wq; out = Wqf; N = 1024; }
        else if (bt < 320) { B = Wk; out = Wkf; N = 256;  bt -= 256; }
        else if (bt < 384) { B = Wv; out = Wvf; N = 256;  bt -= 320; }
        else               { B = Wo; out = Wof; N = 1024; bt -= 384; }

        const int KC = Dc / 16, NT = N / 64;
        const int bk64 = (bt / NT) * 64, bn64 = (bt % NT) * 64;

        #pragma unroll
        for (int i = 0; i < 4; i++) {
            int f = tid + i * 256;
            int row = f >> 4, col4 = (f & 15) * 4;   // row = k, col = n
            *(float4*)&tile[row][col4] = *(const float4*)&B[(size_t)(bk64 + row) * N + bn64 + col4];
        }
        __syncthreads();

        #pragma unroll
        for (int i = 0; i < 4; i++) {
            int s = tid + i * 256;
            int blk = s >> 5, lane = s & 31;
            int ntl = blk >> 2, kcl = blk & 3;
            int g = lane >> 2, t = lane & 3;
            int n = ntl * 8 + g, k0 = kcl * 16 + 2 * t;
            uint2 o;
            o.x = h2u(tile[k0][n],     tile[k0 + 1][n]);
            o.y = h2u(tile[k0 + 8][n], tile[k0 + 9][n]);
            int nt = bn64 / 8 + ntl, kc = bk64 / 16 + kcl;
            *(uint2*)&out[((size_t)(nt * KC + kc) * 32 + lane) * 2] = o;
        }
    }
}

// ---------------------------------------------------------------------------
// Shared fp16 GEMM mainloop, 3-STAGE cp.async pipeline.
// BM=BN=128, BK=32, 256 thr, warp tile 64x32, m16n8k16. 48KB smem.
// ---------------------------------------------------------------------------
__device__ __forceinline__ void mainloop_f16(
    const unsigned* __restrict__ Af, const unsigned* __restrict__ Bf,
    int K, int bm, int bn, unsigned* smu, float c[4][4][4])
{
    const int tid  = threadIdx.x;
    const int lane = tid & 31;
    const int warp = tid >> 5;
    const int wm   = warp >> 2;
    const int wn   = warp & 3;
    const int KC   = K >> 4;
    const uint32_t sb = (uint32_t)__cvta_generic_to_shared(smu);

    #pragma unroll
    for (int mi = 0; mi < 4; mi++)
        #pragma unroll
        for (int ni = 0; ni < 4; ni++)
            #pragma unroll
            for (int r = 0; r < 4; r++) c[mi][ni][r] = 0.f;

    auto stage = [&](int buf, int k0) {
        #pragma unroll
        for (int t2 = 0; t2 < 2; t2++) {
            int idx = tid + t2 * 256;
            int blkA = idx >> 5, ln = idx & 31;
            int mt = (bm >> 4) + (blkA >> 1);
            int kc = (k0 >> 4) + (blkA & 1);
            cp_async16(sb + (buf * 2048 + blkA * 128 + ln * 4) * 4,
                       Af + ((size_t)(mt * KC + kc) * 32 + ln) * 4);
        }
        #pragma unroll
        for (int t2 = 0; t2 < 2; t2++) {
            int idx = tid + t2 * 256;
            int blkB = idx >> 4, lp = idx & 15;
            int nt = (bn >> 3) + (blkB >> 1);
            int kc = (k0 >> 4) + (blkB & 1);
            cp_async16(sb + (6144 + buf * 2048 + blkB * 64 + lp * 4) * 4,
                       Bf + ((size_t)(nt * KC + kc) * 32 + lp * 2) * 2);
        }
        cp_commit();
    };

    const int nit = K >> 5;
    stage(0, 0);
    stage(1, 32);
    int buf = 0;
    for (int it = 0; it < nit; it++) {
        if (it + 1 < nit) cp_wait1(); else cp_wait0();
        __syncthreads();
        if (it + 2 < nit) {
            int nb = buf + 2; if (nb >= 3) nb -= 3;
            stage(nb, (it + 2) << 5);
        }

        #pragma unroll
        for (int kc = 0; kc < 2; kc++) {
            unsigned a[4][4], b[4][2];
            #pragma unroll
            for (int mi = 0; mi < 4; mi++)
                *(uint4*)a[mi] = *(uint4*)&smu[buf * 2048 + (((wm * 4 + mi) * 2 + kc) * 32 + lane) * 4];
            #pragma unroll
            for (int ni = 0; ni < 4; ni++)
                *(uint2*)b[ni] = *(uint2*)&smu[6144 + buf * 2048 + (((wn * 4 + ni) * 2 + kc) * 32 + lane) * 2];
            #pragma unroll
            for (int mi = 0; mi < 4; mi++)
                #pragma unroll
                for (int ni = 0; ni < 4; ni++)
                    mma_f16(c[mi][ni], a[mi], b[ni]);
        }
        if (++buf == 3) buf = 0;
    }
    __syncthreads();
}

// ---------------------------------------------------------------------------
// FUSED Q/K/V projection, one launch, 384 blocks.
//   blocks [0,256):   Q-proj -> fragment-major fp16 A-operand (qafh)
//   blocks [256,320): K-proj -> attention B-fragments (Kfrh) directly
//   blocks [320,384): V-proj -> attention B-fragments (Vfrh) via smem stage
// ---------------------------------------------------------------------------
__global__ __launch_bounds__(256) void gemm_qkv(
    const unsigned* __restrict__ qf, const unsigned* __restrict__ kf,
    const unsigned* __restrict__ vf,
    const unsigned* __restrict__ Wqf, const unsigned* __restrict__ Wkf,
    const unsigned* __restrict__ Wvf,
    const float* __restrict__ bqv, const float* __restrict__ bkv,
    const float* __restrict__ bvv,
    unsigned* __restrict__ Qaf, unsigned* __restrict__ Kfr,
    unsigned* __restrict__ Vfr)
{
    extern __shared__ unsigned smu[];
    const int bt = blockIdx.x;
    const unsigned *Af, *Bf;
    const float* bias;
    int bm, bn, mode;
    if (bt < 256) {
        Af = qf; Bf = Wqf; bias = bqv; mode = 0;
        bm = (bt >> 3) * 128; bn = (bt & 7) * 128;
    } else if (bt < 320) {
        int u = bt - 256;
        Af = kf; Bf = Wkf; bias = bkv; mode = 1;
        bm = (u >> 1) * 128; bn = (u & 1) * 128;
    } else {
        int u = bt - 320;
        Af = vf; Bf = Wvf; bias = bvv; mode = 2;
        bm = (u >> 1) * 128; bn = (u & 1) * 128;
    }

    float c[4][4][4];
    mainloop_f16(Af, Bf, Dc, bm, bn, smu, c);

    const int tid  = threadIdx.x;
    const int lane = tid & 31, warp = tid >> 5;
    const int wm = warp >> 2, wn = warp & 3;
    const int g = lane >> 2, t = lane & 3;

    if (mode == 0) {
        // ---- Q: fragment-major fp16 A-operand
        const int KC16 = Dc >> 4;    // 64
        #pragma unroll
        for (int mi = 0; mi < 4; mi++) {
            int mt = (bm + wm * 64 + mi * 16) >> 4;
            #pragma unroll
            for (int kc2 = 0; kc2 < 2; kc2++) {
                int colb = bn + wn * 32 + kc2 * 16;
                float b0 = bias[colb + 2*t], b1 = bias[colb + 2*t + 1];
                float b2 = bias[colb + 8 + 2*t], b3 = bias[colb + 9 + 2*t];
                uint4 o;
                o.x = h2u(c[mi][2*kc2][0] + b0,   c[mi][2*kc2][1] + b1);
                o.y = h2u(c[mi][2*kc2][2] + b0,   c[mi][2*kc2][3] + b1);
                o.z = h2u(c[mi][2*kc2+1][0] + b2, c[mi][2*kc2+1][1] + b3);
                o.w = h2u(c[mi][2*kc2+1][2] + b2, c[mi][2*kc2+1][3] + b3);
                int kcg = (colb >> 4);
                *(uint4*)&Qaf[((size_t)(mt * KC16 + kcg) * 32 + lane) * 4] = o;
            }
        }
    } else if (mode == 1) {
        // ---- K: attention B-fragments directly
        #pragma unroll
        for (int mi = 0; mi < 4; mi++) {
            int r0 = bm + wm * 64 + mi * 16 + g;
            int b  = r0 >> 11;
            int s  = r0 & 2047;
            int kt = s >> 6;
            int nt0 = ((s & 63) >> 3);
            #pragma unroll
            for (int kc2 = 0; kc2 < 2; kc2++) {
                int colb = bn + wn * 32 + kc2 * 16;
                int hkv = colb >> 6;
                int kc  = (colb & 63) >> 4;
                float b0 = bias[colb + 2*t], b1 = bias[colb + 2*t + 1];
                float b2 = bias[colb + 8 + 2*t], b3 = bias[colb + 9 + 2*t];
                size_t base = ((size_t)((b * HKVc + hkv) * 32 + kt) * 32);
                uint2 o1, o2;
                o1.x = h2u(c[mi][2*kc2][0] + b0,   c[mi][2*kc2][1] + b1);
                o1.y = h2u(c[mi][2*kc2+1][0] + b2, c[mi][2*kc2+1][1] + b3);
                o2.x = h2u(c[mi][2*kc2][2] + b0,   c[mi][2*kc2][3] + b1);
                o2.y = h2u(c[mi][2*kc2+1][2] + b2, c[mi][2*kc2+1][3] + b3);
                *(uint2*)&Kfr[((base + kc * 8 + nt0)     * 32 + lane) * 2] = o1;
                *(uint2*)&Kfr[((base + kc * 8 + nt0 + 1) * 32 + lane) * 2] = o2;
            }
        }
    } else {
        // ---- V: stage fp16 tile [128 rows(key)][132 cols(dk) pad] in smem,
        //      then emit attention B-fragments directly.
        __half* smh = (__half*)smu;
        #pragma unroll
        for (int mi = 0; mi < 4; mi++) {
            int r0 = wm * 64 + mi * 16 + g;
            #pragma unroll
            for (int ni = 0; ni < 4; ni++) {
                int col = wn * 32 + ni * 8 + t * 2;    // even
                float b0 = bias[bn + col], b1 = bias[bn + col + 1];
                *(unsigned*)&smh[r0 * 132 + col]       = h2u(c[mi][ni][0] + b0, c[mi][ni][1] + b1);
                *(unsigned*)&smh[(r0 + 8) * 132 + col] = h2u(c[mi][ni][2] + b0, c[mi][ni][3] + b1);
            }
        }
        __syncthreads();

        const int bglob = bm >> 11;
        const int kt0   = (bm & 2047) >> 6;
        const int hkv0  = bn >> 6;
        #pragma unroll
        for (int i = 0; i < 16; i++) {
            int si = tid + i * 256;                // 0..4095 uint2 fragments
            int ln = si & 31, fc = (si >> 5) & 31, sub = si >> 10;
            int hl = sub & 1, ktl = sub >> 1;
            int kc = fc >> 3, nd = fc & 7;
            int g2 = ln >> 2, t2 = ln & 3;
            int k0 = ktl * 64 + kc * 16 + 2 * t2;
            int n  = hl * 64 + nd * 8 + g2;
            uint2 o;
            o.x = hh2u(smh[k0 * 132 + n],       smh[(k0 + 1) * 132 + n]);
            o.y = hh2u(smh[(k0 + 8) * 132 + n], smh[(k0 + 9) * 132 + n]);
            size_t dst = ((((size_t)(bglob * HKVc + hkv0 + hl) * 32 + kt0 + ktl) * 32 + fc) * 32 + ln) * 2;
            *(uint2*)&Vfr[dst] = o;
        }
    }
}

// ---------------------------------------------------------------------------
// O projection: standard float epilogue to d_out.
// ---------------------------------------------------------------------------
__global__ __launch_bounds__(256) void gemm_o(
    const unsigned* __restrict__ Af, const unsigned* __restrict__ Bf,
    const float* __restrict__ bias, float* __restrict__ C)
{
    extern __shared__ unsigned smu[];
    const int bm = blockIdx.y * 128, bn = blockIdx.x * 128;
    float c[4][4][4];
    mainloop_f16(Af, Bf, Dc, bm, bn, smu, c);

    const int lane = threadIdx.x & 31, warp = threadIdx.x >> 5;
    const int wm = warp >> 2, wn = warp & 3;
    const int g = lane >> 2, t2 = lane & 3;
    #pragma unroll
    for (int mi = 0; mi < 4; mi++) {
        int row = bm + wm * 64 + mi * 16 + g;
        #pragma unroll
        for (int ni = 0; ni < 4; ni++) {
            int col = bn + wn * 32 + ni * 8 + t2 * 2;
            float b0 = bias[col], b1 = bias[col + 1];
            *(float2*)&C[(size_t)row * Dc + col] =
                make_float2(c[mi][ni][0] + b0, c[mi][ni][1] + b1);
            *(float2*)&C[(size_t)(row + 8) * Dc + col] =
                make_float2(c[mi][ni][2] + b0, c[mi][ni][3] + b1);
        }
    }
}

// ---------------------------------------------------------------------------
// fp16 tensor-core flash attention (causal, GQA), 3-stage K/V pipeline.
// Softmax in base-2 domain with ex2.approx.f16x2 (result IS the P-fragment).
// ---------------------------------------------------------------------------
__global__ __launch_bounds__(256) void attn_f16(
    const unsigned* __restrict__ Qf, const unsigned* __restrict__ Kf,
    const unsigned* __restrict__ Vf, unsigned* __restrict__ AOf)
{
    extern __shared__ unsigned smu[];
    const int qt  = (gridDim.x - 1) - blockIdx.x;
    const int h   = blockIdx.y;
    const int b   = blockIdx.z;
    const int hkv = h >> 2;
    const int tid = threadIdx.x;
    const int lane = tid & 31;
    const int w    = tid >> 5;
    const int g    = lane >> 2;
    const int t    = lane & 3;
    const int qbase = qt * 128;
    const int rmin  = qbase + w * 16;
    const uint32_t sb = (uint32_t)__cvta_generic_to_shared(smu);
    const float SC = 0.18033688011112042f;   // 0.125 * log2(e)

    unsigned qa[4][4];
    {
        const int mt = (b * Sc + rmin) >> 4;
        #pragma unroll
        for (int kc = 0; kc < 4; kc++)
            *(uint4*)qa[kc] = *(const uint4*)&Qf[((size_t)(mt * 64 + h * 4 + kc) * 32 + lane) * 4];
    }

    float o[8][4];
    #pragma unroll
    for (int nd = 0; nd < 8; nd++)
        #pragma unroll
        for (int r = 0; r < 4; r++) o[nd][r] = 0.f;
    float m0 = -1e30f, m1 = -1e30f, l0 = 0.f, l1 = 0.f;

    const int bh = b * HKVc + hkv;
    const unsigned* Kt = Kf + (size_t)bh * 32 * 2048;
    const unsigned* Vt = Vf + (size_t)bh * 32 * 2048;

    auto stage = [&](int buf, int kt) {
        const unsigned* ks = Kt + (size_t)kt * 2048;
        const unsigned* vs = Vt + (size_t)kt * 2048;
        #pragma unroll
        for (int t2 = 0; t2 < 2; t2++) {
            int pos = tid + t2 * 256;
            cp_async16(sb + (buf * 2048 + pos * 4) * 4, ks + pos * 4);
            cp_async16(sb + (6144 + buf * 2048 + pos * 4) * 4, vs + pos * 4);
        }
        cp_commit();
    };

    const int ntiles = 2 * qt + 2;
    stage(0, 0);
    stage(1, 1);
    int buf = 0;

    for (int kt = 0; kt < ntiles; kt++) {
        if (kt + 1 < ntiles) cp_wait1(); else cp_wait0();
        __syncthreads();
        if (kt + 2 < ntiles) {
            int nb = buf + 2; if (nb >= 3) nb -= 3;
            stage(nb, kt + 2);
        }

        float s[8][4];
        #pragma unroll
        for (int nt = 0; nt < 8; nt++)
            #pragma unroll
            for (int r = 0; r < 4; r++) s[nt][r] = 0.f;

        #pragma unroll
        for (int kc = 0; kc < 4; kc++) {
            #pragma unroll
            for (int nt = 0; nt < 8; nt++) {
                unsigned bf[2];
                *(uint2*)bf = *(uint2*)&smu[buf * 2048 + ((kc * 8 + nt) * 32 + lane) * 2];
                mma_f16(s[nt], qa[kc], bf);
            }
        }

        // ---- scale into base-2 domain + causal mask
        if (kt * 64 + 63 > rmin) {
            int r0 = rmin + g, r1 = r0 + 8;
            #pragma unroll
            for (int nt = 0; nt < 8; nt++) {
                int c0 = kt * 64 + nt * 8 + 2 * t, c1 = c0 + 1;
                s[nt][0] = (c0 > r0) ? -1e30f : s[nt][0] * SC;
                s[nt][1] = (c1 > r0) ? -1e30f : s[nt][1] * SC;
                s[nt][2] = (c0 > r1) ? -1e30f : s[nt][2] * SC;
                s[nt][3] = (c1 > r1) ? -1e30f : s[nt][3] * SC;
            }
        } else {
            #pragma unroll
            for (int nt = 0; nt < 8; nt++)
                #pragma unroll
                for (int r = 0; r < 4; r++) s[nt][r] *= SC;
        }

        // ---- online softmax (base 2), packed f16 exponentials
        float mt0 = -1e30f, mt1 = -1e30f;
        #pragma unroll
        for (int nt = 0; nt < 8; nt++) {
            mt0 = fmaxf(mt0, fmaxf(s[nt][0], s[nt][1]));
            mt1 = fmaxf(mt1, fmaxf(s[nt][2], s[nt][3]));
        }
        mt0 = fmaxf(mt0, __shfl_xor_sync(0xffffffffu, mt0, 1));
        mt0 = fmaxf(mt0, __shfl_xor_sync(0xffffffffu, mt0, 2));
        mt1 = fmaxf(mt1, __shfl_xor_sync(0xffffffffu, mt1, 1));
        mt1 = fmaxf(mt1, __shfl_xor_sync(0xffffffffu, mt1, 2));
        float mn0 = fmaxf(m0, mt0), mn1 = fmaxf(m1, mt1);
        float cr0 = exp2f(m0 - mn0), cr1 = exp2f(m1 - mn1);

        unsigned pa[4][4];
        float ps0 = 0.f, ps1 = 0.f;
        #pragma unroll
        for (int nt = 0; nt < 8; nt++) {
            __half2 d0 = __floats2half2_rn(s[nt][0] - mn0, s[nt][1] - mn0);
            __half2 d1 = __floats2half2_rn(s[nt][2] - mn1, s[nt][3] - mn1);
            unsigned p0, p1;
            asm("ex2.approx.f16x2 %0, %1;" : "=r"(p0) : "r"(*(unsigned*)&d0));
            asm("ex2.approx.f16x2 %0, %1;" : "=r"(p1) : "r"(*(unsigned*)&d1));
            pa[nt >> 1][(nt & 1) ? 2 : 0] = p0;
            pa[nt >> 1][(nt & 1) ? 3 : 1] = p1;
            float2 f0 = __half22float2(*(__half2*)&p0);
            float2 f1 = __half22float2(*(__half2*)&p1);
            ps0 += f0.x + f0.y;
            ps1 += f1.x + f1.y;
        }
        ps0 += __shfl_xor_sync(0xffffffffu, ps0, 1);
        ps0 += __shfl_xor_sync(0xffffffffu, ps0, 2);
        ps1 += __shfl_xor_sync(0xffffffffu, ps1, 1);
        ps1 += __shfl_xor_sync(0xffffffffu, ps1, 2);
        l0 = l0 * cr0 + ps0;
        l1 = l1 * cr1 + ps1;
        m0 = mn0; m1 = mn1;
        #pragma unroll
        for (int nd = 0; nd < 8; nd++) {
            o[nd][0] *= cr0; o[nd][1] *= cr0;
            o[nd][2] *= cr1; o[nd][3] *= cr1;
        }

        // ---- O += P V
        #pragma unroll
        for (int kc = 0; kc < 4; kc++) {
            #pragma unroll
            for (int nd = 0; nd < 8; nd++) {
                unsigned bf[2];
                *(uint2*)bf = *(uint2*)&smu[6144 + buf * 2048 + ((kc * 8 + nd) * 32 + lane) * 2];
                mma_f16(o[nd], pa[kc], bf);
            }
        }
        if (++buf == 3) buf = 0;
    }

    float inv0 = 1.f / l0, inv1 = 1.f / l1;
    const int KC16 = Dc >> 4;
    const int mt = ((b * Sc + qbase) >> 4) + w;
    #pragma unroll
    for (int c = 0; c < 4; c++) {
        uint4 wv;
        wv.x = h2u(o[2*c][0] * inv0,   o[2*c][1] * inv0);
        wv.y = h2u(o[2*c][2] * inv1,   o[2*c][3] * inv1);
        wv.z = h2u(o[2*c+1][0] * inv0, o[2*c+1][1] * inv0);
        wv.w = h2u(o[2*c+1][2] * inv1, o[2*c+1][3] * inv1);
        *(uint4*)&AOf[((size_t)(mt * KC16 + h * 4 + c) * 32 + lane) * 4] = wv;
    }
}

// ---------------------------------------------------------------------------
// Launch
// ---------------------------------------------------------------------------
extern "C" void kernel_launch(void* const* d_in, const int* in_sizes, int n_in,
                              void* d_out, int out_size)
{
    const float* q  = (const float*)d_in[0];
    const float* k  = (const float*)d_in[1];
    const float* v  = (const float*)d_in[2];
    const float* Wq = (const float*)d_in[4];
    const float* bq = (const float*)d_in[5];
    const float* Wk = (const float*)d_in[6];
    const float* bk = (const float*)d_in[7];
    const float* Wv = (const float*)d_in[8];
    const float* bv = (const float*)d_in[9];
    const float* Wo = (const float*)d_in[10];
    const float* bo = (const float*)d_in[11];
    float* out = (float*)d_out;

    unsigned *qfh, *kfh, *vfh, *qafh, *aofh, *Wqfh, *Wkfh, *Wvfh, *Wofh, *Kfrh, *Vfrh;
    cudaGetSymbolAddress((void**)&qfh,  g_qfh);
    cudaGetSymbolAddress((void**)&kfh,  g_kfh);
    cudaGetSymbolAddress((void**)&vfh,  g_vfh);
    cudaGetSymbolAddress((void**)&qafh, g_qafh);
    cudaGetSymbolAddress((void**)&aofh, g_aofh);
    cudaGetSymbolAddress((void**)&Wqfh, g_Wqfh);
    cudaGetSymbolAddress((void**)&Wkfh, g_Wkfh);
    cudaGetSymbolAddress((void**)&Wvfh, g_Wvfh);
    cudaGetSymbolAddress((void**)&Wofh, g_Wofh);
    cudaGetSymbolAddress((void**)&Kfrh, g_Kfrh);
    cudaGetSymbolAddress((void**)&Vfrh, g_Vfrh);

    const int M = Bc * Sc;
    const int SMEM = 49152;

    // 1. fragmentize inputs + weights (one launch)
    frag_inputs<<<3712, 256>>>(q, k, v, Wq, Wk, Wv, Wo,
                               qfh, kfh, vfh, Wqfh, Wkfh, Wvfh, Wofh);

    // 2. FUSED Q/K/V projections (Q->A-frags, K->Kfr, V->Vfr)
    gemm_qkv<<<384, 256, SMEM>>>(qfh, kfh, vfh, Wqfh, Wkfh, Wvfh,
                                 bq, bk, bv, qafh, Kfrh, Vfrh);

    // 3. attention
    {
        dim3 grid(Sc / 128, Hc, Bc);
        attn_f16<<<grid, 256, SMEM>>>(qafh, Kfrh, Vfrh, aofh);
    }
    // 4. output projection
    {
        dim3 grid(Dc / 128, M / 128);
        gemm_o<<<grid, 256, SMEM>>>(aofh, Wofh, bo, out);
    }
}

// round 16
// speedup vs baseline: 9.3082x; 1.0373x over previous
#include <cuda_runtime.h>
#include <cuda_fp16.h>
#include <cstdint>

// Problem constants
constexpr int Bc   = 2;
constexpr int Sc   = 2048;
constexpr int Dc   = 1024;
constexpr int Hc   = 16;
constexpr int HKVc = 4;
constexpr int DKc  = 64;         // D / H
constexpr int KVD  = HKVc * DKc; // 256

// Scratch (device globals, allocation-free)
__device__ unsigned g_qfh [(Bc*Sc/16) * (Dc/16) * 32 * 4];   // input A-fragments
__device__ unsigned g_kfh [(Bc*Sc/16) * (Dc/16) * 32 * 4];
__device__ unsigned g_vfh [(Bc*Sc/16) * (Dc/16) * 32 * 4];
__device__ unsigned g_qafh[(Bc*Sc/16) * (Dc/16) * 32 * 4];   // projected Q (pre-scaled), A-fragments
__device__ unsigned g_aofh[(Bc*Sc/16) * (Dc/16) * 32 * 4];   // attn out, A-fragments
__device__ unsigned g_Wqfh[(Dc/8)  * (Dc/16) * 32 * 2];
__device__ unsigned g_Wkfh[(KVD/8) * (Dc/16) * 32 * 2];
__device__ unsigned g_Wvfh[(KVD/8) * (Dc/16) * 32 * 2];
__device__ unsigned g_Wofh[(Dc/8)  * (Dc/16) * 32 * 2];
// attention K/V B-fragments: [b*HKV][kt(32)][fc(32)][lane(32)][2]
__device__ unsigned g_Kfrh[Bc * HKVc * 32 * 2048];
__device__ unsigned g_Vfrh[Bc * HKVc * 32 * 2048];

// ---------------------------------------------------------------------------
// helpers
// ---------------------------------------------------------------------------
__device__ __forceinline__ unsigned h2u(float a, float b) {
    __half2 h = __floats2half2_rn(a, b);
    return *(unsigned*)&h;
}
__device__ __forceinline__ unsigned hh2u(__half a, __half b) {
    __half2 h = __halves2half2(a, b);
    return *(unsigned*)&h;
}

__device__ __forceinline__ void mma_f16(float* d, const unsigned* a, const unsigned* b) {
    asm volatile(
        "mma.sync.aligned.m16n8k16.row.col.f32.f16.f16.f32 "
        "{%0,%1,%2,%3}, {%4,%5,%6,%7}, {%8,%9}, {%0,%1,%2,%3};\n"
        : "+f"(d[0]), "+f"(d[1]), "+f"(d[2]), "+f"(d[3])
        : "r"(a[0]), "r"(a[1]), "r"(a[2]), "r"(a[3]), "r"(b[0]), "r"(b[1]));
}

__device__ __forceinline__ void cp_async16(uint32_t smem_addr, const void* gptr) {
    asm volatile("cp.async.cg.shared.global [%0], [%1], 16;" :: "r"(smem_addr), "l"(gptr));
}
__device__ __forceinline__ void cp_commit() { asm volatile("cp.async.commit_group;"); }
__device__ __forceinline__ void cp_wait0()  { asm volatile("cp.async.wait_group 0;"); }
__device__ __forceinline__ void cp_wait1()  { asm volatile("cp.async.wait_group 1;"); }

// ---------------------------------------------------------------------------
// MERGED input fragmentize: blocks [0,3072) = q/k/v A-fragments (1024 each);
// blocks [3072,3712) = weight B-fragments (Wq 256 | Wk 64 | Wv 64 | Wo 256).
// pad = 68 so float4 smem stores stay 16B-aligned.
// ---------------------------------------------------------------------------
__global__ __launch_bounds__(256) void frag_inputs(
    const float* __restrict__ q, const float* __restrict__ k,
    const float* __restrict__ v,
    const float* __restrict__ Wq, const float* __restrict__ Wk,
    const float* __restrict__ Wv, const float* __restrict__ Wo,
    unsigned* __restrict__ qf, unsigned* __restrict__ kf,
    unsigned* __restrict__ vf,
    unsigned* __restrict__ Wqf, unsigned* __restrict__ Wkf,
    unsigned* __restrict__ Wvf, unsigned* __restrict__ Wof)
{
    __shared__ float tile[64][68];
    const int tid = threadIdx.x;
    int bt = blockIdx.x;

    if (bt < 3072) {
        const float* A; unsigned* out;
        int sel = bt >> 10; bt &= 1023;
        if (sel == 0)      { A = q; out = qf; }
        else if (sel == 1) { A = k; out = kf; }
        else               { A = v; out = vf; }

        const int KT = Dc / 64, KC = Dc / 16;
        const int bm64 = (bt / KT) * 64, bk64 = (bt % KT) * 64;

        #pragma unroll
        for (int i = 0; i < 4; i++) {
            int f = tid + i * 256;
            int row = f >> 4, col4 = (f & 15) * 4;
            *(float4*)&tile[row][col4] = *(const float4*)&A[(size_t)(bm64 + row) * Dc + bk64 + col4];
        }
        __syncthreads();

        #pragma unroll
        for (int i = 0; i < 2; i++) {
            int s = tid + i * 256;
            int blk = s >> 5, lane = s & 31;
            int mtl = blk >> 2, kcl = blk & 3;
            int g = lane >> 2, t = lane & 3;
            int r0 = mtl * 16 + g, c0 = kcl * 16 + 2 * t;
            uint4 o;
            o.x = h2u(tile[r0][c0],         tile[r0][c0 + 1]);
            o.y = h2u(tile[r0 + 8][c0],     tile[r0 + 8][c0 + 1]);
            o.z = h2u(tile[r0][c0 + 8],     tile[r0][c0 + 9]);
            o.w = h2u(tile[r0 + 8][c0 + 8], tile[r0 + 8][c0 + 9]);
            int mt = bm64 / 16 + mtl, kc = bk64 / 16 + kcl;
            *(uint4*)&out[((size_t)(mt * KC + kc) * 32 + lane) * 4] = o;
        }
    } else {
        bt -= 3072;
        const float* B; unsigned* out; int N;
        if (bt < 256)      { B = Wq; out = Wqf; N = 1024; }
        else if (bt < 320) { B = Wk; out = Wkf; N = 256;  bt -= 256; }
        else if (bt < 384) { B = Wv; out = Wvf; N = 256;  bt -= 320; }
        else               { B = Wo; out = Wof; N = 1024; bt -= 384; }

        const int KC = Dc / 16, NT = N / 64;
        const int bk64 = (bt / NT) * 64, bn64 = (bt % NT) * 64;

        #pragma unroll
        for (int i = 0; i < 4; i++) {
            int f = tid + i * 256;
            int row = f >> 4, col4 = (f & 15) * 4;   // row = k, col = n
            *(float4*)&tile[row][col4] = *(const float4*)&B[(size_t)(bk64 + row) * N + bn64 + col4];
        }
        __syncthreads();

        #pragma unroll
        for (int i = 0; i < 4; i++) {
            int s = tid + i * 256;
            int blk = s >> 5, lane = s & 31;
            int ntl = blk >> 2, kcl = blk & 3;
            int g = lane >> 2, t = lane & 3;
            int n = ntl * 8 + g, k0 = kcl * 16 + 2 * t;
            uint2 o;
            o.x = h2u(tile[k0][n],     tile[k0 + 1][n]);
            o.y = h2u(tile[k0 + 8][n], tile[k0 + 9][n]);
            int nt = bn64 / 8 + ntl, kc = bk64 / 16 + kcl;
            *(uint2*)&out[((size_t)(nt * KC + kc) * 32 + lane) * 2] = o;
        }
    }
}

// ---------------------------------------------------------------------------
// Shared fp16 GEMM mainloop, 3-STAGE cp.async pipeline.
// BM=BN=128, BK=32, 256 thr, warp tile 64x32, m16n8k16. 48KB smem.
// ---------------------------------------------------------------------------
__device__ __forceinline__ void mainloop_f16(
    const unsigned* __restrict__ Af, const unsigned* __restrict__ Bf,
    int K, int bm, int bn, unsigned* smu, float c[4][4][4])
{
    const int tid  = threadIdx.x;
    const int lane = tid & 31;
    const int warp = tid >> 5;
    const int wm   = warp >> 2;
    const int wn   = warp & 3;
    const int KC   = K >> 4;
    const uint32_t sb = (uint32_t)__cvta_generic_to_shared(smu);

    #pragma unroll
    for (int mi = 0; mi < 4; mi++)
        #pragma unroll
        for (int ni = 0; ni < 4; ni++)
            #pragma unroll
            for (int r = 0; r < 4; r++) c[mi][ni][r] = 0.f;

    auto stage = [&](int buf, int k0) {
        #pragma unroll
        for (int t2 = 0; t2 < 2; t2++) {
            int idx = tid + t2 * 256;
            int blkA = idx >> 5, ln = idx & 31;
            int mt = (bm >> 4) + (blkA >> 1);
            int kc = (k0 >> 4) + (blkA & 1);
            cp_async16(sb + (buf * 2048 + blkA * 128 + ln * 4) * 4,
                       Af + ((size_t)(mt * KC + kc) * 32 + ln) * 4);
        }
        #pragma unroll
        for (int t2 = 0; t2 < 2; t2++) {
            int idx = tid + t2 * 256;
            int blkB = idx >> 4, lp = idx & 15;
            int nt = (bn >> 3) + (blkB >> 1);
            int kc = (k0 >> 4) + (blkB & 1);
            cp_async16(sb + (6144 + buf * 2048 + blkB * 64 + lp * 4) * 4,
                       Bf + ((size_t)(nt * KC + kc) * 32 + lp * 2) * 2);
        }
        cp_commit();
    };

    const int nit = K >> 5;
    stage(0, 0);
    stage(1, 32);
    int buf = 0;
    for (int it = 0; it < nit; it++) {
        if (it + 1 < nit) cp_wait1(); else cp_wait0();
        __syncthreads();
        if (it + 2 < nit) {
            int nb = buf + 2; if (nb >= 3) nb -= 3;
            stage(nb, (it + 2) << 5);
        }

        #pragma unroll
        for (int kc = 0; kc < 2; kc++) {
            unsigned a[4][4], b[4][2];
            #pragma unroll
            for (int mi = 0; mi < 4; mi++)
                *(uint4*)a[mi] = *(uint4*)&smu[buf * 2048 + (((wm * 4 + mi) * 2 + kc) * 32 + lane) * 4];
            #pragma unroll
            for (int ni = 0; ni < 4; ni++)
                *(uint2*)b[ni] = *(uint2*)&smu[6144 + buf * 2048 + (((wn * 4 + ni) * 2 + kc) * 32 + lane) * 2];
            #pragma unroll
            for (int mi = 0; mi < 4; mi++)
                #pragma unroll
                for (int ni = 0; ni < 4; ni++)
                    mma_f16(c[mi][ni], a[mi], b[ni]);
        }
        if (++buf == 3) buf = 0;
    }
    __syncthreads();
}

// ---------------------------------------------------------------------------
// FUSED Q/K/V projection, one launch, 384 blocks.
//   blocks [0,256):   Q-proj -> PRE-SCALED fragment-major fp16 A-operand
//   blocks [256,320): K-proj -> attention B-fragments (Kfrh) directly
//   blocks [320,384): V-proj -> attention B-fragments (Vfrh) via smem stage
// ---------------------------------------------------------------------------
__global__ __launch_bounds__(256) void gemm_qkv(
    const unsigned* __restrict__ qf, const unsigned* __restrict__ kf,
    const unsigned* __restrict__ vf,
    const unsigned* __restrict__ Wqf, const unsigned* __restrict__ Wkf,
    const unsigned* __restrict__ Wvf,
    const float* __restrict__ bqv, const float* __restrict__ bkv,
    const float* __restrict__ bvv,
    unsigned* __restrict__ Qaf, unsigned* __restrict__ Kfr,
    unsigned* __restrict__ Vfr)
{
    extern __shared__ unsigned smu[];
    const int bt = blockIdx.x;
    const unsigned *Af, *Bf;
    const float* bias;
    int bm, bn, mode;
    if (bt < 256) {
        Af = qf; Bf = Wqf; bias = bqv; mode = 0;
        bm = (bt >> 3) * 128; bn = (bt & 7) * 128;
    } else if (bt < 320) {
        int u = bt - 256;
        Af = kf; Bf = Wkf; bias = bkv; mode = 1;
        bm = (u >> 1) * 128; bn = (u & 1) * 128;
    } else {
        int u = bt - 320;
        Af = vf; Bf = Wvf; bias = bvv; mode = 2;
        bm = (u >> 1) * 128; bn = (u & 1) * 128;
    }

    float c[4][4][4];
    mainloop_f16(Af, Bf, Dc, bm, bn, smu, c);

    const int tid  = threadIdx.x;
    const int lane = tid & 31, warp = tid >> 5;
    const int wm = warp >> 2, wn = warp & 3;
    const int g = lane >> 2, t = lane & 3;

    if (mode == 0) {
        // ---- Q: fragment-major fp16 A-operand, PRE-SCALED by 0.125*log2(e)
        const float SC = 0.18033688011112042f;
        const int KC16 = Dc >> 4;    // 64
        #pragma unroll
        for (int mi = 0; mi < 4; mi++) {
            int mt = (bm + wm * 64 + mi * 16) >> 4;
            #pragma unroll
            for (int kc2 = 0; kc2 < 2; kc2++) {
                int colb = bn + wn * 32 + kc2 * 16;
                float b0 = bias[colb + 2*t], b1 = bias[colb + 2*t + 1];
                float b2 = bias[colb + 8 + 2*t], b3 = bias[colb + 9 + 2*t];
                uint4 o;
                o.x = h2u((c[mi][2*kc2][0] + b0) * SC,   (c[mi][2*kc2][1] + b1) * SC);
                o.y = h2u((c[mi][2*kc2][2] + b0) * SC,   (c[mi][2*kc2][3] + b1) * SC);
                o.z = h2u((c[mi][2*kc2+1][0] + b2) * SC, (c[mi][2*kc2+1][1] + b3) * SC);
                o.w = h2u((c[mi][2*kc2+1][2] + b2) * SC, (c[mi][2*kc2+1][3] + b3) * SC);
                int kcg = (colb >> 4);
                *(uint4*)&Qaf[((size_t)(mt * KC16 + kcg) * 32 + lane) * 4] = o;
            }
        }
    } else if (mode == 1) {
        // ---- K: attention B-fragments directly
        #pragma unroll
        for (int mi = 0; mi < 4; mi++) {
            int r0 = bm + wm * 64 + mi * 16 + g;
            int b  = r0 >> 11;
            int s  = r0 & 2047;
            int kt = s >> 6;
            int nt0 = ((s & 63) >> 3);
            #pragma unroll
            for (int kc2 = 0; kc2 < 2; kc2++) {
                int colb = bn + wn * 32 + kc2 * 16;
                int hkv = colb >> 6;
                int kc  = (colb & 63) >> 4;
                float b0 = bias[colb + 2*t], b1 = bias[colb + 2*t + 1];
                float b2 = bias[colb + 8 + 2*t], b3 = bias[colb + 9 + 2*t];
                size_t base = ((size_t)((b * HKVc + hkv) * 32 + kt) * 32);
                uint2 o1, o2;
                o1.x = h2u(c[mi][2*kc2][0] + b0,   c[mi][2*kc2][1] + b1);
                o1.y = h2u(c[mi][2*kc2+1][0] + b2, c[mi][2*kc2+1][1] + b3);
                o2.x = h2u(c[mi][2*kc2][2] + b0,   c[mi][2*kc2][3] + b1);
                o2.y = h2u(c[mi][2*kc2+1][2] + b2, c[mi][2*kc2+1][3] + b3);
                *(uint2*)&Kfr[((base + kc * 8 + nt0)     * 32 + lane) * 2] = o1;
                *(uint2*)&Kfr[((base + kc * 8 + nt0 + 1) * 32 + lane) * 2] = o2;
            }
        }
    } else {
        // ---- V: stage fp16 tile [128 key][132 dk pad], emit B-fragments
        __half* smh = (__half*)smu;
        #pragma unroll
        for (int mi = 0; mi < 4; mi++) {
            int r0 = wm * 64 + mi * 16 + g;
            #pragma unroll
            for (int ni = 0; ni < 4; ni++) {
                int col = wn * 32 + ni * 8 + t * 2;
                float b0 = bias[bn + col], b1 = bias[bn + col + 1];
                *(unsigned*)&smh[r0 * 132 + col]       = h2u(c[mi][ni][0] + b0, c[mi][ni][1] + b1);
                *(unsigned*)&smh[(r0 + 8) * 132 + col] = h2u(c[mi][ni][2] + b0, c[mi][ni][3] + b1);
            }
        }
        __syncthreads();

        const int bglob = bm >> 11;
        const int kt0   = (bm & 2047) >> 6;
        const int hkv0  = bn >> 6;
        #pragma unroll
        for (int i = 0; i < 16; i++) {
            int si = tid + i * 256;
            int ln = si & 31, fc = (si >> 5) & 31, sub = si >> 10;
            int hl = sub & 1, ktl = sub >> 1;
            int kc = fc >> 3, nd = fc & 7;
            int g2 = ln >> 2, t2 = ln & 3;
            int k0 = ktl * 64 + kc * 16 + 2 * t2;
            int n  = hl * 64 + nd * 8 + g2;
            uint2 o;
            o.x = hh2u(smh[k0 * 132 + n],       smh[(k0 + 1) * 132 + n]);
            o.y = hh2u(smh[(k0 + 8) * 132 + n], smh[(k0 + 9) * 132 + n]);
            size_t dst = ((((size_t)(bglob * HKVc + hkv0 + hl) * 32 + kt0 + ktl) * 32 + fc) * 32 + ln) * 2;
            *(uint2*)&Vfr[dst] = o;
        }
    }
}

// ---------------------------------------------------------------------------
// O projection: standard float epilogue to d_out.
// ---------------------------------------------------------------------------
__global__ __launch_bounds__(256) void gemm_o(
    const unsigned* __restrict__ Af, const unsigned* __restrict__ Bf,
    const float* __restrict__ bias, float* __restrict__ C)
{
    extern __shared__ unsigned smu[];
    const int bm = blockIdx.y * 128, bn = blockIdx.x * 128;
    float c[4][4][4];
    mainloop_f16(Af, Bf, Dc, bm, bn, smu, c);

    const int lane = threadIdx.x & 31, warp = threadIdx.x >> 5;
    const int wm = warp >> 2, wn = warp & 3;
    const int g = lane >> 2, t2 = lane & 3;
    #pragma unroll
    for (int mi = 0; mi < 4; mi++) {
        int row = bm + wm * 64 + mi * 16 + g;
        #pragma unroll
        for (int ni = 0; ni < 4; ni++) {
            int col = bn + wn * 32 + ni * 8 + t2 * 2;
            float b0 = bias[col], b1 = bias[col + 1];
            *(float2*)&C[(size_t)row * Dc + col] =
                make_float2(c[mi][ni][0] + b0, c[mi][ni][1] + b1);
            *(float2*)&C[(size_t)(row + 8) * Dc + col] =
                make_float2(c[mi][ni][2] + b0, c[mi][ni][3] + b1);
        }
    }
}

// ---------------------------------------------------------------------------
// fp16 tensor-core flash attention (causal, GQA), 3-stage K/V pipeline.
// Q pre-scaled (base-2 domain). Softmax via ex2.approx.f16x2.
// Row sums via mma with ones-B-fragment (no cvt/shfl reduction).
// ---------------------------------------------------------------------------
__global__ __launch_bounds__(256) void attn_f16(
    const unsigned* __restrict__ Qf, const unsigned* __restrict__ Kf,
    const unsigned* __restrict__ Vf, unsigned* __restrict__ AOf)
{
    extern __shared__ unsigned smu[];
    const int qt  = (gridDim.x - 1) - blockIdx.x;
    const int h   = blockIdx.y;
    const int b   = blockIdx.z;
    const int hkv = h >> 2;
    const int tid = threadIdx.x;
    const int lane = tid & 31;
    const int w    = tid >> 5;
    const int g    = lane >> 2;
    const int t    = lane & 3;
    const int qbase = qt * 128;
    const int rmin  = qbase + w * 16;
    const uint32_t sb = (uint32_t)__cvta_generic_to_shared(smu);

    unsigned qa[4][4];
    {
        const int mt = (b * Sc + rmin) >> 4;
        #pragma unroll
        for (int kc = 0; kc < 4; kc++)
            *(uint4*)qa[kc] = *(const uint4*)&Qf[((size_t)(mt * 64 + h * 4 + kc) * 32 + lane) * 4];
    }

    float o[8][4];
    #pragma unroll
    for (int nd = 0; nd < 8; nd++)
        #pragma unroll
        for (int r = 0; r < 4; r++) o[nd][r] = 0.f;
    float m0 = -1e30f, m1 = -1e30f;
    float ls[4] = {0.f, 0.f, 0.f, 0.f};           // row-sum accumulator (mma)
    const unsigned ONES2[2] = {0x3C003C00u, 0x3C003C00u};  // half2(1,1) x2

    const int bh = b * HKVc + hkv;
    const unsigned* Kt = Kf + (size_t)bh * 32 * 2048;
    const unsigned* Vt = Vf + (size_t)bh * 32 * 2048;

    auto stage = [&](int buf, int kt) {
        const unsigned* ks = Kt + (size_t)kt * 2048;
        const unsigned* vs = Vt + (size_t)kt * 2048;
        #pragma unroll
        for (int t2 = 0; t2 < 2; t2++) {
            int pos = tid + t2 * 256;
            cp_async16(sb + (buf * 2048 + pos * 4) * 4, ks + pos * 4);
            cp_async16(sb + (6144 + buf * 2048 + pos * 4) * 4, vs + pos * 4);
        }
        cp_commit();
    };

    const int ntiles = 2 * qt + 2;
    stage(0, 0);
    stage(1, 1);
    int buf = 0;

    for (int kt = 0; kt < ntiles; kt++) {
        if (kt + 1 < ntiles) cp_wait1(); else cp_wait0();
        __syncthreads();
        if (kt + 2 < ntiles) {
            int nb = buf + 2; if (nb >= 3) nb -= 3;
            stage(nb, kt + 2);
        }

        float s[8][4];
        #pragma unroll
        for (int nt = 0; nt < 8; nt++)
            #pragma unroll
            for (int r = 0; r < 4; r++) s[nt][r] = 0.f;

        #pragma unroll
        for (int kc = 0; kc < 4; kc++) {
            #pragma unroll
            for (int nt = 0; nt < 8; nt++) {
                unsigned bf[2];
                *(uint2*)bf = *(uint2*)&smu[buf * 2048 + ((kc * 8 + nt) * 32 + lane) * 2];
                mma_f16(s[nt], qa[kc], bf);
            }
        }

        // ---- causal mask only (Q pre-scaled; no elementwise scaling needed)
        if (kt * 64 + 63 > rmin) {
            int r0 = rmin + g, r1 = r0 + 8;
            #pragma unroll
            for (int nt = 0; nt < 8; nt++) {
                int c0 = kt * 64 + nt * 8 + 2 * t, c1 = c0 + 1;
                if (c0 > r0) s[nt][0] = -1e30f;
                if (c1 > r0) s[nt][1] = -1e30f;
                if (c0 > r1) s[nt][2] = -1e30f;
                if (c1 > r1) s[nt][3] = -1e30f;
            }
        }

        // ---- online softmax (base 2), packed f16 exponentials
        float mt0 = -1e30f, mt1 = -1e30f;
        #pragma unroll
        for (int nt = 0; nt < 8; nt++) {
            mt0 = fmaxf(mt0, fmaxf(s[nt][0], s[nt][1]));
            mt1 = fmaxf(mt1, fmaxf(s[nt][2], s[nt][3]));
        }
        mt0 = fmaxf(mt0, __shfl_xor_sync(0xffffffffu, mt0, 1));
        mt0 = fmaxf(mt0, __shfl_xor_sync(0xffffffffu, mt0, 2));
        mt1 = fmaxf(mt1, __shfl_xor_sync(0xffffffffu, mt1, 1));
        mt1 = fmaxf(mt1, __shfl_xor_sync(0xffffffffu, mt1, 2));
        float mn0 = fmaxf(m0, mt0), mn1 = fmaxf(m1, mt1);
        float cr0 = exp2f(m0 - mn0), cr1 = exp2f(m1 - mn1);
        m0 = mn0; m1 = mn1;

        unsigned pa[4][4];
        #pragma unroll
        for (int nt = 0; nt < 8; nt++) {
            __half2 d0 = __floats2half2_rn(s[nt][0] - mn0, s[nt][1] - mn0);
            __half2 d1 = __floats2half2_rn(s[nt][2] - mn1, s[nt][3] - mn1);
            unsigned p0, p1;
            asm("ex2.approx.f16x2 %0, %1;" : "=r"(p0) : "r"(*(unsigned*)&d0));
            asm("ex2.approx.f16x2 %0, %1;" : "=r"(p1) : "r"(*(unsigned*)&d1));
            pa[nt >> 1][(nt & 1) ? 2 : 0] = p0;
            pa[nt >> 1][(nt & 1) ? 3 : 1] = p1;
        }

        // ---- rescale accumulators
        ls[0] *= cr0; ls[1] *= cr0; ls[2] *= cr1; ls[3] *= cr1;
        #pragma unroll
        for (int nd = 0; nd < 8; nd++) {
            o[nd][0] *= cr0; o[nd][1] *= cr0;
            o[nd][2] *= cr1; o[nd][3] *= cr1;
        }

        // ---- row sums via ones-mma (every lane gets the full row sum)
        #pragma unroll
        for (int kc = 0; kc < 4; kc++)
            mma_f16(ls, pa[kc], ONES2);

        // ---- O += P V
        #pragma unroll
        for (int kc = 0; kc < 4; kc++) {
            #pragma unroll
            for (int nd = 0; nd < 8; nd++) {
                unsigned bf[2];
                *(uint2*)bf = *(uint2*)&smu[6144 + buf * 2048 + ((kc * 8 + nd) * 32 + lane) * 2];
                mma_f16(o[nd], pa[kc], bf);
            }
        }
        if (++buf == 3) buf = 0;
    }

    float inv0 = 1.f / ls[0], inv1 = 1.f / ls[2];
    const int KC16 = Dc >> 4;
    const int mt = ((b * Sc + qbase) >> 4) + w;
    #pragma unroll
    for (int c = 0; c < 4; c++) {
        uint4 wv;
        wv.x = h2u(o[2*c][0] * inv0,   o[2*c][1] * inv0);
        wv.y = h2u(o[2*c][2] * inv1,   o[2*c][3] * inv1);
        wv.z = h2u(o[2*c+1][0] * inv0, o[2*c+1][1] * inv0);
        wv.w = h2u(o[2*c+1][2] * inv1, o[2*c+1][3] * inv1);
        *(uint4*)&AOf[((size_t)(mt * KC16 + h * 4 + c) * 32 + lane) * 4] = wv;
    }
}

// ---------------------------------------------------------------------------
// Launch
// ---------------------------------------------------------------------------
extern "C" void kernel_launch(void* const* d_in, const int* in_sizes, int n_in,
                              void* d_out, int out_size)
{
    const float* q  = (const float*)d_in[0];
    const float* k  = (const float*)d_in[1];
    const float* v  = (const float*)d_in[2];
    const float* Wq = (const float*)d_in[4];
    const float* bq = (const float*)d_in[5];
    const float* Wk = (const float*)d_in[6];
    const float* bk = (const float*)d_in[7];
    const float* Wv = (const float*)d_in[8];
    const float* bv = (const float*)d_in[9];
    const float* Wo = (const float*)d_in[10];
    const float* bo = (const float*)d_in[11];
    float* out = (float*)d_out;

    unsigned *qfh, *kfh, *vfh, *qafh, *aofh, *Wqfh, *Wkfh, *Wvfh, *Wofh, *Kfrh, *Vfrh;
    cudaGetSymbolAddress((void**)&qfh,  g_qfh);
    cudaGetSymbolAddress((void**)&kfh,  g_kfh);
    cudaGetSymbolAddress((void**)&vfh,  g_vfh);
    cudaGetSymbolAddress((void**)&qafh, g_qafh);
    cudaGetSymbolAddress((void**)&aofh, g_aofh);
    cudaGetSymbolAddress((void**)&Wqfh, g_Wqfh);
    cudaGetSymbolAddress((void**)&Wkfh, g_Wkfh);
    cudaGetSymbolAddress((void**)&Wvfh, g_Wvfh);
    cudaGetSymbolAddress((void**)&Wofh, g_Wofh);
    cudaGetSymbolAddress((void**)&Kfrh, g_Kfrh);
    cudaGetSymbolAddress((void**)&Vfrh, g_Vfrh);

    const int M = Bc * Sc;
    const int SMEM = 49152;

    // 1. fragmentize inputs + weights (one launch)
    frag_inputs<<<3712, 256>>>(q, k, v, Wq, Wk, Wv, Wo,
                               qfh, kfh, vfh, Wqfh, Wkfh, Wvfh, Wofh);

    // 2. FUSED Q/K/V projections (Q->scaled A-frags, K->Kfr, V->Vfr)
    gemm_qkv<<<384, 256, SMEM>>>(qfh, kfh, vfh, Wqfh, Wkfh, Wvfh,
                                 bq, bk, bv, qafh, Kfrh, Vfrh);

    // 3. attention
    {
        dim3 grid(Sc / 128, Hc, Bc);
        attn_f16<<<grid, 256, SMEM>>>(qafh, Kfrh, Vfrh, aofh);
    }
    // 4. output projection
    {
        dim3 grid(Dc / 128, M / 128);
        gemm_o<<<grid, 256, SMEM>>>(aofh, Wofh, bo, out);
    }
}

// round 17
// speedup vs baseline: 9.5592x; 1.0270x over previous
#include <cuda_runtime.h>
#include <cuda_fp16.h>
#include <cstdint>

// Problem constants
constexpr int Bc   = 2;
constexpr int Sc   = 2048;
constexpr int Dc   = 1024;
constexpr int Hc   = 16;
constexpr int HKVc = 4;
constexpr int DKc  = 64;         // D / H
constexpr int KVD  = HKVc * DKc; // 256

// Scratch (device globals, allocation-free)
__device__ unsigned g_qfh [(Bc*Sc/16) * (Dc/16) * 32 * 4];   // input A-fragments
__device__ unsigned g_kfh [(Bc*Sc/16) * (Dc/16) * 32 * 4];
__device__ unsigned g_vfh [(Bc*Sc/16) * (Dc/16) * 32 * 4];
__device__ unsigned g_qafh[(Bc*Sc/16) * (Dc/16) * 32 * 4];   // projected Q (pre-scaled), A-fragments
__device__ unsigned g_aofh[(Bc*Sc/16) * (Dc/16) * 32 * 4];   // attn out, A-fragments
__device__ unsigned g_Wqfh[(Dc/8)  * (Dc/16) * 32 * 2];
__device__ unsigned g_Wkfh[(KVD/8) * (Dc/16) * 32 * 2];
__device__ unsigned g_Wvfh[(KVD/8) * (Dc/16) * 32 * 2];
__device__ unsigned g_Wofh[(Dc/8)  * (Dc/16) * 32 * 2];
// attention K/V B-fragments: [b*HKV][kt(32)][fc(32)][lane(32)][2]
__device__ unsigned g_Kfrh[Bc * HKVc * 32 * 2048];
__device__ unsigned g_Vfrh[Bc * HKVc * 32 * 2048];

// ---------------------------------------------------------------------------
// helpers
// ---------------------------------------------------------------------------
__device__ __forceinline__ unsigned h2u(float a, float b) {
    __half2 h = __floats2half2_rn(a, b);
    return *(unsigned*)&h;
}
__device__ __forceinline__ unsigned hh2u(__half a, __half b) {
    __half2 h = __halves2half2(a, b);
    return *(unsigned*)&h;
}

__device__ __forceinline__ void mma_f16(float* d, const unsigned* a, const unsigned* b) {
    asm volatile(
        "mma.sync.aligned.m16n8k16.row.col.f32.f16.f16.f32 "
        "{%0,%1,%2,%3}, {%4,%5,%6,%7}, {%8,%9}, {%0,%1,%2,%3};\n"
        : "+f"(d[0]), "+f"(d[1]), "+f"(d[2]), "+f"(d[3])
        : "r"(a[0]), "r"(a[1]), "r"(a[2]), "r"(a[3]), "r"(b[0]), "r"(b[1]));
}

__device__ __forceinline__ void cp_async16(uint32_t smem_addr, const void* gptr) {
    asm volatile("cp.async.cg.shared.global [%0], [%1], 16;" :: "r"(smem_addr), "l"(gptr));
}
__device__ __forceinline__ void cp_commit() { asm volatile("cp.async.commit_group;"); }
__device__ __forceinline__ void cp_wait0()  { asm volatile("cp.async.wait_group 0;"); }
__device__ __forceinline__ void cp_wait1()  { asm volatile("cp.async.wait_group 1;"); }

// ---------------------------------------------------------------------------
// MERGED input fragmentize: blocks [0,3072) = q/k/v A-fragments (1024 each);
// blocks [3072,3712) = weight B-fragments (Wq 256 | Wk 64 | Wv 64 | Wo 256).
// pad = 68 so float4 smem stores stay 16B-aligned.
// ---------------------------------------------------------------------------
__global__ __launch_bounds__(256) void frag_inputs(
    const float* __restrict__ q, const float* __restrict__ k,
    const float* __restrict__ v,
    const float* __restrict__ Wq, const float* __restrict__ Wk,
    const float* __restrict__ Wv, const float* __restrict__ Wo,
    unsigned* __restrict__ qf, unsigned* __restrict__ kf,
    unsigned* __restrict__ vf,
    unsigned* __restrict__ Wqf, unsigned* __restrict__ Wkf,
    unsigned* __restrict__ Wvf, unsigned* __restrict__ Wof)
{
    __shared__ float tile[64][68];
    const int tid = threadIdx.x;
    int bt = blockIdx.x;

    if (bt < 3072) {
        const float* A; unsigned* out;
        int sel = bt >> 10; bt &= 1023;
        if (sel == 0)      { A = q; out = qf; }
        else if (sel == 1) { A = k; out = kf; }
        else               { A = v; out = vf; }

        const int KT = Dc / 64, KC = Dc / 16;
        const int bm64 = (bt / KT) * 64, bk64 = (bt % KT) * 64;

        #pragma unroll
        for (int i = 0; i < 4; i++) {
            int f = tid + i * 256;
            int row = f >> 4, col4 = (f & 15) * 4;
            *(float4*)&tile[row][col4] = *(const float4*)&A[(size_t)(bm64 + row) * Dc + bk64 + col4];
        }
        __syncthreads();

        #pragma unroll
        for (int i = 0; i < 2; i++) {
            int s = tid + i * 256;
            int blk = s >> 5, lane = s & 31;
            int mtl = blk >> 2, kcl = blk & 3;
            int g = lane >> 2, t = lane & 3;
            int r0 = mtl * 16 + g, c0 = kcl * 16 + 2 * t;
            uint4 o;
            o.x = h2u(tile[r0][c0],         tile[r0][c0 + 1]);
            o.y = h2u(tile[r0 + 8][c0],     tile[r0 + 8][c0 + 1]);
            o.z = h2u(tile[r0][c0 + 8],     tile[r0][c0 + 9]);
            o.w = h2u(tile[r0 + 8][c0 + 8], tile[r0 + 8][c0 + 9]);
            int mt = bm64 / 16 + mtl, kc = bk64 / 16 + kcl;
            *(uint4*)&out[((size_t)(mt * KC + kc) * 32 + lane) * 4] = o;
        }
    } else {
        bt -= 3072;
        const float* B; unsigned* out; int N;
        if (bt < 256)      { B = Wq; out = Wqf; N = 1024; }
        else if (bt < 320) { B = Wk; out = Wkf; N = 256;  bt -= 256; }
        else if (bt < 384) { B = Wv; out = Wvf; N = 256;  bt -= 320; }
        else               { B = Wo; out = Wof; N = 1024; bt -= 384; }

        const int KC = Dc / 16, NT = N / 64;
        const int bk64 = (bt / NT) * 64, bn64 = (bt % NT) * 64;

        #pragma unroll
        for (int i = 0; i < 4; i++) {
            int f = tid + i * 256;
            int row = f >> 4, col4 = (f & 15) * 4;   // row = k, col = n
            *(float4*)&tile[row][col4] = *(const float4*)&B[(size_t)(bk64 + row) * N + bn64 + col4];
        }
        __syncthreads();

        #pragma unroll
        for (int i = 0; i < 4; i++) {
            int s = tid + i * 256;
            int blk = s >> 5, lane = s & 31;
            int ntl = blk >> 2, kcl = blk & 3;
            int g = lane >> 2, t = lane & 3;
            int n = ntl * 8 + g, k0 = kcl * 16 + 2 * t;
            uint2 o;
            o.x = h2u(tile[k0][n],     tile[k0 + 1][n]);
            o.y = h2u(tile[k0 + 8][n], tile[k0 + 9][n]);
            int nt = bn64 / 8 + ntl, kc = bk64 / 16 + kcl;
            *(uint2*)&out[((size_t)(nt * KC + kc) * 32 + lane) * 2] = o;
        }
    }
}

// ---------------------------------------------------------------------------
// Shared fp16 GEMM mainloop, 3-STAGE cp.async pipeline.
// BM=BN=128, BK=32, 256 thr, warp tile 64x32, m16n8k16. 48KB smem.
// ---------------------------------------------------------------------------
__device__ __forceinline__ void mainloop_f16(
    const unsigned* __restrict__ Af, const unsigned* __restrict__ Bf,
    int K, int bm, int bn, unsigned* smu, float c[4][4][4])
{
    const int tid  = threadIdx.x;
    const int lane = tid & 31;
    const int warp = tid >> 5;
    const int wm   = warp >> 2;
    const int wn   = warp & 3;
    const int KC   = K >> 4;
    const uint32_t sb = (uint32_t)__cvta_generic_to_shared(smu);

    #pragma unroll
    for (int mi = 0; mi < 4; mi++)
        #pragma unroll
        for (int ni = 0; ni < 4; ni++)
            #pragma unroll
            for (int r = 0; r < 4; r++) c[mi][ni][r] = 0.f;

    auto stage = [&](int buf, int k0) {
        #pragma unroll
        for (int t2 = 0; t2 < 2; t2++) {
            int idx = tid + t2 * 256;
            int blkA = idx >> 5, ln = idx & 31;
            int mt = (bm >> 4) + (blkA >> 1);
            int kc = (k0 >> 4) + (blkA & 1);
            cp_async16(sb + (buf * 2048 + blkA * 128 + ln * 4) * 4,
                       Af + ((size_t)(mt * KC + kc) * 32 + ln) * 4);
        }
        #pragma unroll
        for (int t2 = 0; t2 < 2; t2++) {
            int idx = tid + t2 * 256;
            int blkB = idx >> 4, lp = idx & 15;
            int nt = (bn >> 3) + (blkB >> 1);
            int kc = (k0 >> 4) + (blkB & 1);
            cp_async16(sb + (6144 + buf * 2048 + blkB * 64 + lp * 4) * 4,
                       Bf + ((size_t)(nt * KC + kc) * 32 + lp * 2) * 2);
        }
        cp_commit();
    };

    const int nit = K >> 5;
    stage(0, 0);
    stage(1, 32);
    int buf = 0;
    for (int it = 0; it < nit; it++) {
        if (it + 1 < nit) cp_wait1(); else cp_wait0();
        __syncthreads();
        if (it + 2 < nit) {
            int nb = buf + 2; if (nb >= 3) nb -= 3;
            stage(nb, (it + 2) << 5);
        }

        #pragma unroll
        for (int kc = 0; kc < 2; kc++) {
            unsigned a[4][4], b[4][2];
            #pragma unroll
            for (int mi = 0; mi < 4; mi++)
                *(uint4*)a[mi] = *(uint4*)&smu[buf * 2048 + (((wm * 4 + mi) * 2 + kc) * 32 + lane) * 4];
            #pragma unroll
            for (int ni = 0; ni < 4; ni++)
                *(uint2*)b[ni] = *(uint2*)&smu[6144 + buf * 2048 + (((wn * 4 + ni) * 2 + kc) * 32 + lane) * 2];
            #pragma unroll
            for (int mi = 0; mi < 4; mi++)
                #pragma unroll
                for (int ni = 0; ni < 4; ni++)
                    mma_f16(c[mi][ni], a[mi], b[ni]);
        }
        if (++buf == 3) buf = 0;
    }
    __syncthreads();
}

// ---------------------------------------------------------------------------
// FUSED Q/K/V projection, one launch, 384 blocks.
// ---------------------------------------------------------------------------
__global__ __launch_bounds__(256) void gemm_qkv(
    const unsigned* __restrict__ qf, const unsigned* __restrict__ kf,
    const unsigned* __restrict__ vf,
    const unsigned* __restrict__ Wqf, const unsigned* __restrict__ Wkf,
    const unsigned* __restrict__ Wvf,
    const float* __restrict__ bqv, const float* __restrict__ bkv,
    const float* __restrict__ bvv,
    unsigned* __restrict__ Qaf, unsigned* __restrict__ Kfr,
    unsigned* __restrict__ Vfr)
{
    extern __shared__ unsigned smu[];
    const int bt = blockIdx.x;
    const unsigned *Af, *Bf;
    const float* bias;
    int bm, bn, mode;
    if (bt < 256) {
        Af = qf; Bf = Wqf; bias = bqv; mode = 0;
        bm = (bt >> 3) * 128; bn = (bt & 7) * 128;
    } else if (bt < 320) {
        int u = bt - 256;
        Af = kf; Bf = Wkf; bias = bkv; mode = 1;
        bm = (u >> 1) * 128; bn = (u & 1) * 128;
    } else {
        int u = bt - 320;
        Af = vf; Bf = Wvf; bias = bvv; mode = 2;
        bm = (u >> 1) * 128; bn = (u & 1) * 128;
    }

    float c[4][4][4];
    mainloop_f16(Af, Bf, Dc, bm, bn, smu, c);

    const int tid  = threadIdx.x;
    const int lane = tid & 31, warp = tid >> 5;
    const int wm = warp >> 2, wn = warp & 3;
    const int g = lane >> 2, t = lane & 3;

    if (mode == 0) {
        // ---- Q: fragment-major fp16 A-operand, PRE-SCALED by 0.125*log2(e)
        const float SC = 0.18033688011112042f;
        const int KC16 = Dc >> 4;
        #pragma unroll
        for (int mi = 0; mi < 4; mi++) {
            int mt = (bm + wm * 64 + mi * 16) >> 4;
            #pragma unroll
            for (int kc2 = 0; kc2 < 2; kc2++) {
                int colb = bn + wn * 32 + kc2 * 16;
                float b0 = bias[colb + 2*t], b1 = bias[colb + 2*t + 1];
                float b2 = bias[colb + 8 + 2*t], b3 = bias[colb + 9 + 2*t];
                uint4 o;
                o.x = h2u((c[mi][2*kc2][0] + b0) * SC,   (c[mi][2*kc2][1] + b1) * SC);
                o.y = h2u((c[mi][2*kc2][2] + b0) * SC,   (c[mi][2*kc2][3] + b1) * SC);
                o.z = h2u((c[mi][2*kc2+1][0] + b2) * SC, (c[mi][2*kc2+1][1] + b3) * SC);
                o.w = h2u((c[mi][2*kc2+1][2] + b2) * SC, (c[mi][2*kc2+1][3] + b3) * SC);
                int kcg = (colb >> 4);
                *(uint4*)&Qaf[((size_t)(mt * KC16 + kcg) * 32 + lane) * 4] = o;
            }
        }
    } else if (mode == 1) {
        // ---- K: attention B-fragments directly
        #pragma unroll
        for (int mi = 0; mi < 4; mi++) {
            int r0 = bm + wm * 64 + mi * 16 + g;
            int b  = r0 >> 11;
            int s  = r0 & 2047;
            int kt = s >> 6;
            int nt0 = ((s & 63) >> 3);
            #pragma unroll
            for (int kc2 = 0; kc2 < 2; kc2++) {
                int colb = bn + wn * 32 + kc2 * 16;
                int hkv = colb >> 6;
                int kc  = (colb & 63) >> 4;
                float b0 = bias[colb + 2*t], b1 = bias[colb + 2*t + 1];
                float b2 = bias[colb + 8 + 2*t], b3 = bias[colb + 9 + 2*t];
                size_t base = ((size_t)((b * HKVc + hkv) * 32 + kt) * 32);
                uint2 o1, o2;
                o1.x = h2u(c[mi][2*kc2][0] + b0,   c[mi][2*kc2][1] + b1);
                o1.y = h2u(c[mi][2*kc2+1][0] + b2, c[mi][2*kc2+1][1] + b3);
                o2.x = h2u(c[mi][2*kc2][2] + b0,   c[mi][2*kc2][3] + b1);
                o2.y = h2u(c[mi][2*kc2+1][2] + b2, c[mi][2*kc2+1][3] + b3);
                *(uint2*)&Kfr[((base + kc * 8 + nt0)     * 32 + lane) * 2] = o1;
                *(uint2*)&Kfr[((base + kc * 8 + nt0 + 1) * 32 + lane) * 2] = o2;
            }
        }
    } else {
        // ---- V: stage fp16 tile [128 key][132 dk pad], emit B-fragments
        __half* smh = (__half*)smu;
        #pragma unroll
        for (int mi = 0; mi < 4; mi++) {
            int r0 = wm * 64 + mi * 16 + g;
            #pragma unroll
            for (int ni = 0; ni < 4; ni++) {
                int col = wn * 32 + ni * 8 + t * 2;
                float b0 = bias[bn + col], b1 = bias[bn + col + 1];
                *(unsigned*)&smh[r0 * 132 + col]       = h2u(c[mi][ni][0] + b0, c[mi][ni][1] + b1);
                *(unsigned*)&smh[(r0 + 8) * 132 + col] = h2u(c[mi][ni][2] + b0, c[mi][ni][3] + b1);
            }
        }
        __syncthreads();

        const int bglob = bm >> 11;
        const int kt0   = (bm & 2047) >> 6;
        const int hkv0  = bn >> 6;
        #pragma unroll
        for (int i = 0; i < 16; i++) {
            int si = tid + i * 256;
            int ln = si & 31, fc = (si >> 5) & 31, sub = si >> 10;
            int hl = sub & 1, ktl = sub >> 1;
            int kc = fc >> 3, nd = fc & 7;
            int g2 = ln >> 2, t2 = ln & 3;
            int k0 = ktl * 64 + kc * 16 + 2 * t2;
            int n  = hl * 64 + nd * 8 + g2;
            uint2 o;
            o.x = hh2u(smh[k0 * 132 + n],       smh[(k0 + 1) * 132 + n]);
            o.y = hh2u(smh[(k0 + 8) * 132 + n], smh[(k0 + 9) * 132 + n]);
            size_t dst = ((((size_t)(bglob * HKVc + hkv0 + hl) * 32 + kt0 + ktl) * 32 + fc) * 32 + ln) * 2;
            *(uint2*)&Vfr[dst] = o;
        }
    }
}

// ---------------------------------------------------------------------------
// O projection: standard float epilogue to d_out.
// ---------------------------------------------------------------------------
__global__ __launch_bounds__(256) void gemm_o(
    const unsigned* __restrict__ Af, const unsigned* __restrict__ Bf,
    const float* __restrict__ bias, float* __restrict__ C)
{
    extern __shared__ unsigned smu[];
    const int bm = blockIdx.y * 128, bn = blockIdx.x * 128;
    float c[4][4][4];
    mainloop_f16(Af, Bf, Dc, bm, bn, smu, c);

    const int lane = threadIdx.x & 31, warp = threadIdx.x >> 5;
    const int wm = warp >> 2, wn = warp & 3;
    const int g = lane >> 2, t2 = lane & 3;
    #pragma unroll
    for (int mi = 0; mi < 4; mi++) {
        int row = bm + wm * 64 + mi * 16 + g;
        #pragma unroll
        for (int ni = 0; ni < 4; ni++) {
            int col = bn + wn * 32 + ni * 8 + t2 * 2;
            float b0 = bias[col], b1 = bias[col + 1];
            *(float2*)&C[(size_t)row * Dc + col] =
                make_float2(c[mi][ni][0] + b0, c[mi][ni][1] + b1);
            *(float2*)&C[(size_t)(row + 8) * Dc + col] =
                make_float2(c[mi][ni][2] + b0, c[mi][ni][3] + b1);
        }
    }
}

// ---------------------------------------------------------------------------
// fp16 flash attention v3 (causal, GQA): 128 threads / 4 warps, each warp
// owns 32 q-rows (2 m-tiles) -> every K/V B-fragment LDS feeds 2 mma
// (smem crossbar traffic per MAC halved). 3-stage cp.async K/V pipeline.
// Q pre-scaled (base-2); softmax via ex2.approx.f16x2; row sums via ones-mma.
// Fully-masked warp tiles skip all compute.
// ---------------------------------------------------------------------------
__global__ __launch_bounds__(128) void attn_f16(
    const unsigned* __restrict__ Qf, const unsigned* __restrict__ Kf,
    const unsigned* __restrict__ Vf, unsigned* __restrict__ AOf)
{
    extern __shared__ unsigned smu[];
    const int qt  = (gridDim.x - 1) - blockIdx.x;
    const int h   = blockIdx.y;
    const int b   = blockIdx.z;
    const int hkv = h >> 2;
    const int tid = threadIdx.x;
    const int lane = tid & 31;
    const int w    = tid >> 5;          // 0..3
    const int g    = lane >> 2;
    const int t    = lane & 3;
    const int qbase = qt * 128;
    const int rmin  = qbase + w * 32;   // warp's first q row (32 rows)
    const uint32_t sb = (uint32_t)__cvta_generic_to_shared(smu);

    // ---- Q fragments for both m-tiles
    unsigned qa[2][4][4];
    {
        const int mt = (b * Sc + rmin) >> 4;
        #pragma unroll
        for (int i = 0; i < 2; i++)
            #pragma unroll
            for (int kc = 0; kc < 4; kc++)
                *(uint4*)qa[i][kc] =
                    *(const uint4*)&Qf[((size_t)((mt + i) * 64 + h * 4 + kc) * 32 + lane) * 4];
    }

    float o[2][8][4];
    #pragma unroll
    for (int i = 0; i < 2; i++)
        #pragma unroll
        for (int nd = 0; nd < 8; nd++)
            #pragma unroll
            for (int r = 0; r < 4; r++) o[i][nd][r] = 0.f;
    float m[2][2] = {{-1e30f, -1e30f}, {-1e30f, -1e30f}};
    float ls[2][4] = {{0.f,0.f,0.f,0.f},{0.f,0.f,0.f,0.f}};
    const unsigned ONES2[2] = {0x3C003C00u, 0x3C003C00u};

    const int bh = b * HKVc + hkv;
    const unsigned* Kt = Kf + (size_t)bh * 32 * 2048;
    const unsigned* Vt = Vf + (size_t)bh * 32 * 2048;

    auto stage = [&](int buf, int kt) {
        const unsigned* ks = Kt + (size_t)kt * 2048;
        const unsigned* vs = Vt + (size_t)kt * 2048;
        #pragma unroll
        for (int t2 = 0; t2 < 4; t2++) {
            int pos = tid + t2 * 128;        // 512 uint4 positions
            cp_async16(sb + (buf * 2048 + pos * 4) * 4, ks + pos * 4);
            cp_async16(sb + (6144 + buf * 2048 + pos * 4) * 4, vs + pos * 4);
        }
        cp_commit();
    };

    const int ntiles = 2 * qt + 2;
    stage(0, 0);
    stage(1, 1);
    int buf = 0;

    for (int kt = 0; kt < ntiles; kt++) {
        if (kt + 1 < ntiles) cp_wait1(); else cp_wait0();
        __syncthreads();
        if (kt + 2 < ntiles) {
            int nb = buf + 2; if (nb >= 3) nb -= 3;
            stage(nb, kt + 2);
        }

        // fully masked for this warp's 32 rows? skip all compute
        if (kt * 64 <= rmin + 31) {
            // ---- S = Q K^T for both m-tiles (B-fragment loaded once)
            float s[2][8][4];
            #pragma unroll
            for (int i = 0; i < 2; i++)
                #pragma unroll
                for (int nt = 0; nt < 8; nt++)
                    #pragma unroll
                    for (int r = 0; r < 4; r++) s[i][nt][r] = 0.f;

            #pragma unroll
            for (int kc = 0; kc < 4; kc++) {
                #pragma unroll
                for (int nt = 0; nt < 8; nt++) {
                    unsigned bf[2];
                    *(uint2*)bf = *(uint2*)&smu[buf * 2048 + ((kc * 8 + nt) * 32 + lane) * 2];
                    mma_f16(s[0][nt], qa[0][kc], bf);
                    mma_f16(s[1][nt], qa[1][kc], bf);
                }
            }

            // ---- causal mask
            if (kt * 64 + 63 > rmin) {
                #pragma unroll
                for (int i = 0; i < 2; i++) {
                    int r0 = rmin + i * 16 + g, r1 = r0 + 8;
                    #pragma unroll
                    for (int nt = 0; nt < 8; nt++) {
                        int c0 = kt * 64 + nt * 8 + 2 * t, c1 = c0 + 1;
                        if (c0 > r0) s[i][nt][0] = -1e30f;
                        if (c1 > r0) s[i][nt][1] = -1e30f;
                        if (c0 > r1) s[i][nt][2] = -1e30f;
                        if (c1 > r1) s[i][nt][3] = -1e30f;
                    }
                }
            }

            // ---- online softmax (base 2) per m-tile
            unsigned pa[2][4][4];
            #pragma unroll
            for (int i = 0; i < 2; i++) {
                float mt0 = -1e30f, mt1 = -1e30f;
                #pragma unroll
                for (int nt = 0; nt < 8; nt++) {
                    mt0 = fmaxf(mt0, fmaxf(s[i][nt][0], s[i][nt][1]));
                    mt1 = fmaxf(mt1, fmaxf(s[i][nt][2], s[i][nt][3]));
                }
                mt0 = fmaxf(mt0, __shfl_xor_sync(0xffffffffu, mt0, 1));
                mt0 = fmaxf(mt0, __shfl_xor_sync(0xffffffffu, mt0, 2));
                mt1 = fmaxf(mt1, __shfl_xor_sync(0xffffffffu, mt1, 1));
                mt1 = fmaxf(mt1, __shfl_xor_sync(0xffffffffu, mt1, 2));
                float mn0 = fmaxf(m[i][0], mt0), mn1 = fmaxf(m[i][1], mt1);
                float cr0 = exp2f(m[i][0] - mn0), cr1 = exp2f(m[i][1] - mn1);
                m[i][0] = mn0; m[i][1] = mn1;

                #pragma unroll
                for (int nt = 0; nt < 8; nt++) {
                    __half2 d0 = __floats2half2_rn(s[i][nt][0] - mn0, s[i][nt][1] - mn0);
                    __half2 d1 = __floats2half2_rn(s[i][nt][2] - mn1, s[i][nt][3] - mn1);
                    unsigned p0, p1;
                    asm("ex2.approx.f16x2 %0, %1;" : "=r"(p0) : "r"(*(unsigned*)&d0));
                    asm("ex2.approx.f16x2 %0, %1;" : "=r"(p1) : "r"(*(unsigned*)&d1));
                    pa[i][nt >> 1][(nt & 1) ? 2 : 0] = p0;
                    pa[i][nt >> 1][(nt & 1) ? 3 : 1] = p1;
                }

                ls[i][0] *= cr0; ls[i][1] *= cr0; ls[i][2] *= cr1; ls[i][3] *= cr1;
                #pragma unroll
                for (int nd = 0; nd < 8; nd++) {
                    o[i][nd][0] *= cr0; o[i][nd][1] *= cr0;
                    o[i][nd][2] *= cr1; o[i][nd][3] *= cr1;
                }
                #pragma unroll
                for (int kc = 0; kc < 4; kc++)
                    mma_f16(ls[i], pa[i][kc], ONES2);
            }

            // ---- O += P V for both m-tiles (B-fragment loaded once)
            #pragma unroll
            for (int kc = 0; kc < 4; kc++) {
                #pragma unroll
                for (int nd = 0; nd < 8; nd++) {
                    unsigned bf[2];
                    *(uint2*)bf = *(uint2*)&smu[6144 + buf * 2048 + ((kc * 8 + nd) * 32 + lane) * 2];
                    mma_f16(o[0][nd], pa[0][kc], bf);
                    mma_f16(o[1][nd], pa[1][kc], bf);
                }
            }
        }
        if (++buf == 3) buf = 0;
    }

    // ---- epilogue: two m-tiles
    const int KC16 = Dc >> 4;
    const int mtb = (b * Sc + rmin) >> 4;
    #pragma unroll
    for (int i = 0; i < 2; i++) {
        float inv0 = 1.f / ls[i][0], inv1 = 1.f / ls[i][2];
        #pragma unroll
        for (int c = 0; c < 4; c++) {
            uint4 wv;
            wv.x = h2u(o[i][2*c][0] * inv0,   o[i][2*c][1] * inv0);
            wv.y = h2u(o[i][2*c][2] * inv1,   o[i][2*c][3] * inv1);
            wv.z = h2u(o[i][2*c+1][0] * inv0, o[i][2*c+1][1] * inv0);
            wv.w = h2u(o[i][2*c+1][2] * inv1, o[i][2*c+1][3] * inv1);
            *(uint4*)&AOf[((size_t)((mtb + i) * KC16 + h * 4 + c) * 32 + lane) * 4] = wv;
        }
    }
}

// ---------------------------------------------------------------------------
// Launch
// ---------------------------------------------------------------------------
extern "C" void kernel_launch(void* const* d_in, const int* in_sizes, int n_in,
                              void* d_out, int out_size)
{
    const float* q  = (const float*)d_in[0];
    const float* k  = (const float*)d_in[1];
    const float* v  = (const float*)d_in[2];
    const float* Wq = (const float*)d_in[4];
    const float* bq = (const float*)d_in[5];
    const float* Wk = (const float*)d_in[6];
    const float* bk = (const float*)d_in[7];
    const float* Wv = (const float*)d_in[8];
    const float* bv = (const float*)d_in[9];
    const float* Wo = (const float*)d_in[10];
    const float* bo = (const float*)d_in[11];
    float* out = (float*)d_out;

    unsigned *qfh, *kfh, *vfh, *qafh, *aofh, *Wqfh, *Wkfh, *Wvfh, *Wofh, *Kfrh, *Vfrh;
    cudaGetSymbolAddress((void**)&qfh,  g_qfh);
    cudaGetSymbolAddress((void**)&kfh,  g_kfh);
    cudaGetSymbolAddress((void**)&vfh,  g_vfh);
    cudaGetSymbolAddress((void**)&qafh, g_qafh);
    cudaGetSymbolAddress((void**)&aofh, g_aofh);
    cudaGetSymbolAddress((void**)&Wqfh, g_Wqfh);
    cudaGetSymbolAddress((void**)&Wkfh, g_Wkfh);
    cudaGetSymbolAddress((void**)&Wvfh, g_Wvfh);
    cudaGetSymbolAddress((void**)&Wofh, g_Wofh);
    cudaGetSymbolAddress((void**)&Kfrh, g_Kfrh);
    cudaGetSymbolAddress((void**)&Vfrh, g_Vfrh);

    const int M = Bc * Sc;
    const int SMEM = 49152;

    // 1. fragmentize inputs + weights (one launch)
    frag_inputs<<<3712, 256>>>(q, k, v, Wq, Wk, Wv, Wo,
                               qfh, kfh, vfh, Wqfh, Wkfh, Wvfh, Wofh);

    // 2. FUSED Q/K/V projections (Q->scaled A-frags, K->Kfr, V->Vfr)
    gemm_qkv<<<384, 256, SMEM>>>(qfh, kfh, vfh, Wqfh, Wkfh, Wvfh,
                                 bq, bk, bv, qafh, Kfrh, Vfrh);

    // 3. attention (4 warps x 32 rows each)
    {
        dim3 grid(Sc / 128, Hc, Bc);
        attn_f16<<<grid, 128, SMEM>>>(qafh, Kfrh, Vfrh, aofh);
    }
    // 4. output projection
    {
        dim3 grid(Dc / 128, M / 128);
        gemm_o<<<grid, 256, SMEM>>>(aofh, Wofh, bo, out);
    }
}